// round 5
// baseline (speedup 1.0000x reference)
#include <cuda_runtime.h>
#include <cuda_bf16.h>
#include <math.h>
#include <stdint.h>

typedef __nv_bfloat16 bf16;
#define TT 1024
#define SCALE_QK 0.07216878364870323f

// ------------------------- device scratch (no cudaMalloc) -------------------
__device__ float g_qlow [2048*1536];
__device__ float g_q    [2048*6144];
__device__ float g_kvout[2048*576];
__device__ float g_kvexp[2048*8192];
__device__ float g_mb   [2048];

__device__ bf16 g_xh[2048*4096],  g_xl[2048*4096];
__device__ bf16 g_qlh[2048*1536], g_qll[2048*1536];
__device__ bf16 g_qh[2048*6144],  g_ql[2048*6144];
__device__ bf16 g_kvh[2048*512],  g_kvl[2048*512];
__device__ bf16 g_kh[64ll*1024*192], g_kl[64ll*1024*192];
__device__ bf16 g_vh[64ll*1024*128], g_vl[64ll*1024*128];
__device__ bf16 g_ath[2048*4096], g_atl[2048*4096];
__device__ bf16 g_wqah[1536*4096], g_wqal[1536*4096];
__device__ bf16 g_wqbh[6144*1536], g_wqbl[6144*1536];
__device__ bf16 g_wkvah[576*4096], g_wkval[576*4096];
__device__ bf16 g_wkvbh[8192*512], g_wkvbl[8192*512];
__device__ bf16 g_woh[4096*4096],  g_wol[4096*4096];

// ------------------------------ PTX helpers (sm_80-safe) --------------------
__device__ __forceinline__ uint32_t smem_u32(const void* p) {
    uint32_t a;
    asm("{ .reg .u64 t; cvta.to.shared.u64 t, %1; cvt.u32.u64 %0, t; }"
        : "=r"(a) : "l"(p));
    return a;
}

#define LDSM4(r, a) asm volatile( \
    "ldmatrix.sync.aligned.m8n8.x4.shared.b16 {%0,%1,%2,%3}, [%4];" \
    : "=r"((r)[0]), "=r"((r)[1]), "=r"((r)[2]), "=r"((r)[3]) : "r"(a))

#define LDSM4T(r, a) asm volatile( \
    "ldmatrix.sync.aligned.m8n8.x4.trans.shared.b16 {%0,%1,%2,%3}, [%4];" \
    : "=r"((r)[0]), "=r"((r)[1]), "=r"((r)[2]), "=r"((r)[3]) : "r"(a))

#define MMA16816(d, a, b0, b1) asm volatile( \
    "mma.sync.aligned.m16n8k16.row.col.f32.bf16.bf16.f32 " \
    "{%0,%1,%2,%3},{%4,%5,%6,%7},{%8,%9},{%0,%1,%2,%3};" \
    : "+f"((d)[0]), "+f"((d)[1]), "+f"((d)[2]), "+f"((d)[3]) \
    : "r"((a)[0]), "r"((a)[1]), "r"((a)[2]), "r"((a)[3]), "r"(b0), "r"(b1))

#define MMA_P(d, a0, a1, a2, a3, b0, b1) asm volatile( \
    "mma.sync.aligned.m16n8k16.row.col.f32.bf16.bf16.f32 " \
    "{%0,%1,%2,%3},{%4,%5,%6,%7},{%8,%9},{%0,%1,%2,%3};" \
    : "+f"((d)[0]), "+f"((d)[1]), "+f"((d)[2]), "+f"((d)[3]) \
    : "r"(a0), "r"(a1), "r"(a2), "r"(a3), "r"(b0), "r"(b1))

__device__ __forceinline__ void cpa16(uint32_t dst, const void* src, int valid) {
    int sz = valid ? 16 : 0;
    asm volatile("cp.async.cg.shared.global [%0], [%1], 16, %2;"
                 :: "r"(dst), "l"(src), "r"(sz));
}
#define CP_COMMIT() asm volatile("cp.async.commit_group;" ::: "memory")
#define CP_WAIT(n)  asm volatile("cp.async.wait_group %0;" :: "n"(n) : "memory")

__device__ __forceinline__ uint32_t packbf(float a, float b) {
    __nv_bfloat162 t = __floats2bfloat162_rn(a, b);
    return *reinterpret_cast<uint32_t*>(&t);
}

// Load one 128x32 bf16 plane into swizzled smem (rows of 64B).
__device__ __forceinline__ void load_plane(uint32_t sb, const bf16* __restrict__ G,
                                           int row0, int ld, int k0, int tid,
                                           int nvalid) {
#pragma unroll
    for (int i = 0; i < 2; i++) {
        int idx = tid * 2 + i;
        int r = idx >> 2, c = idx & 3;
        uint32_t dst = sb + r * 64 + ((c ^ ((r >> 1) & 3)) << 4);
        int ok = r < nvalid;
        const bf16* src = G + (size_t)(row0 + (ok ? r : 0)) * ld + k0 + c * 8;
        cpa16(dst, src, ok);
    }
}

// Load one 64x32 bf16 subplane (256 threads -> 1 line each).
__device__ __forceinline__ void load_plane64(uint32_t sb, const bf16* __restrict__ G,
                                             int ld, int k0, int tid) {
    int r = tid >> 2, c = tid & 3;
    uint32_t dst = sb + r * 64 + ((c ^ ((r >> 1) & 3)) << 4);
    cpa16(dst, G + (size_t)r * ld + k0 + c * 8, 1);
}

// Load one 64x128 bf16 V plane (rows of 256B) with row-xor swizzle.
__device__ __forceinline__ void load_v(uint32_t sb, const bf16* __restrict__ G,
                                       int tid) {
#pragma unroll
    for (int i = 0; i < 4; i++) {
        int idx = i * 256 + tid;
        int r = idx >> 4, c = idx & 15;
        uint32_t dst = sb + r * 256 + ((c ^ (r & 7)) << 4);
        cpa16(dst, G + (size_t)r * 128 + c * 8, 1);
    }
}

// ---------------------------------------------------------------------------
// 3-pass split-bf16 HMMA GEMM, 3-stage cp.async pipeline.
// C[M,N] = (Ah+Al)[M,K] @ (Bh+Bl)[N,K]^T * scale (drops Al*Bl).
// ---------------------------------------------------------------------------
#define GEMM_SMEM 98304
__global__ void __launch_bounds__(256, 1) gemm3_k(
    const bf16* __restrict__ Ah_, const bf16* __restrict__ Al_,
    const bf16* __restrict__ Bh_, const bf16* __restrict__ Bl_,
    float* __restrict__ C_,
    int N, int K, int lda, int ldb, int ldc,
    long aOut, long aIn, long bOut, long bIn, long cOut, long cIn,
    int innerCnt, int flags, float scale)
{
    extern __shared__ char smem[];
    int m0 = blockIdx.y * 128, n0 = blockIdx.x * 128;
    if ((flags & 2) && n0 > m0) return;

    int z = blockIdx.z, outer = z / innerCnt, inner = z - outer * innerCnt;
    const bf16* Ah = Ah_ + outer * aOut + inner * aIn;
    const bf16* Al = Al_ + outer * aOut + inner * aIn;
    const bf16* Bh = Bh_ + outer * bOut + inner * bIn;
    const bf16* Bl = Bl_ + outer * bOut + inner * bIn;
    float*      C  = C_  + outer * cOut + inner * cIn;

    int tid = threadIdx.x, lane = tid & 31, wid = tid >> 5;
    int mw = (wid & 1) * 64, nw = (wid >> 1) * 32;
    uint32_t s0 = smem_u32(smem);
    int nvB = min(128, N - n0);

    int Keff = (flags & 1) ? min(K, m0 + 128) : K;
    int nch = Keff >> 5;

    uint32_t rowA[4]; int sA[4];
#pragma unroll
    for (int mt = 0; mt < 4; mt++) {
        int r = mw + mt * 16 + (lane & 15);
        rowA[mt] = r * 64; sA[mt] = (r >> 1) & 3;
    }
    uint32_t rowB[2]; int sB[2];
#pragma unroll
    for (int h2 = 0; h2 < 2; h2++) {
        int r = nw + h2 * 16 + (lane & 7) + ((lane >> 4) << 3);
        rowB[h2] = r * 64; sB[h2] = (r >> 1) & 3;
    }
    int aCk = (lane >> 4) & 1, bCk = (lane >> 3) & 1;

    float acc[4][4][4];
#pragma unroll
    for (int i = 0; i < 4; i++)
#pragma unroll
        for (int j = 0; j < 4; j++)
#pragma unroll
            for (int r = 0; r < 4; r++) acc[i][j][r] = 0.f;

    // prologue: stages 0,1
    {
        load_plane(s0,         Ah, m0, lda, 0, tid, 128);
        load_plane(s0 + 8192,  Al, m0, lda, 0, tid, 128);
        load_plane(s0 + 16384, Bh, n0, ldb, 0, tid, nvB);
        load_plane(s0 + 24576, Bl, n0, ldb, 0, tid, nvB);
        CP_COMMIT();
        if (nch > 1) {
            uint32_t sb = s0 + 32768;
            load_plane(sb,         Ah, m0, lda, 32, tid, 128);
            load_plane(sb + 8192,  Al, m0, lda, 32, tid, 128);
            load_plane(sb + 16384, Bh, n0, ldb, 32, tid, nvB);
            load_plane(sb + 24576, Bl, n0, ldb, 32, tid, nvB);
        }
        CP_COMMIT();
    }

    for (int c = 0; c < nch; c++) {
        CP_WAIT(1);
        __syncthreads();
        if (c + 2 < nch) {
            uint32_t sb = s0 + ((c + 2) % 3) * 32768;
            int k0 = (c + 2) * 32;
            load_plane(sb,         Ah, m0, lda, k0, tid, 128);
            load_plane(sb + 8192,  Al, m0, lda, k0, tid, 128);
            load_plane(sb + 16384, Bh, n0, ldb, k0, tid, nvB);
            load_plane(sb + 24576, Bl, n0, ldb, k0, tid, nvB);
        }
        CP_COMMIT();

        uint32_t base = s0 + (c % 3) * 32768;
        uint32_t pAh = base, pAl = base + 8192;
        uint32_t pBh = base + 16384, pBl = base + 24576;
#pragma unroll
        for (int ks = 0; ks < 2; ks++) {
            uint32_t af[4][4], bhf[2][4], blf[2][4];
            int cA = ks * 2 + aCk, cB = ks * 2 + bCk;
#pragma unroll
            for (int mt = 0; mt < 4; mt++)
                LDSM4(af[mt], pAh + rowA[mt] + (uint32_t)((cA ^ sA[mt]) << 4));
#pragma unroll
            for (int h2 = 0; h2 < 2; h2++) {
                LDSM4(bhf[h2], pBh + rowB[h2] + (uint32_t)((cB ^ sB[h2]) << 4));
                LDSM4(blf[h2], pBl + rowB[h2] + (uint32_t)((cB ^ sB[h2]) << 4));
            }
#pragma unroll
            for (int mt = 0; mt < 4; mt++)
#pragma unroll
                for (int nt = 0; nt < 4; nt++)
                    MMA16816(acc[mt][nt], af[mt],
                             bhf[nt >> 1][(nt & 1) * 2], bhf[nt >> 1][(nt & 1) * 2 + 1]);
#pragma unroll
            for (int mt = 0; mt < 4; mt++)
#pragma unroll
                for (int nt = 0; nt < 4; nt++)
                    MMA16816(acc[mt][nt], af[mt],
                             blf[nt >> 1][(nt & 1) * 2], blf[nt >> 1][(nt & 1) * 2 + 1]);
#pragma unroll
            for (int mt = 0; mt < 4; mt++)
                LDSM4(af[mt], pAl + rowA[mt] + (uint32_t)((cA ^ sA[mt]) << 4));
#pragma unroll
            for (int mt = 0; mt < 4; mt++)
#pragma unroll
                for (int nt = 0; nt < 4; nt++)
                    MMA16816(acc[mt][nt], af[mt],
                             bhf[nt >> 1][(nt & 1) * 2], bhf[nt >> 1][(nt & 1) * 2 + 1]);
        }
        __syncthreads();
    }

#pragma unroll
    for (int mt = 0; mt < 4; mt++) {
        int r0 = m0 + mw + mt * 16 + (lane >> 2);
#pragma unroll
        for (int nt = 0; nt < 4; nt++) {
            int col = n0 + nw + nt * 8 + 2 * (lane & 3);
            if (col < N) {
                float2 v0 = make_float2(acc[mt][nt][0] * scale, acc[mt][nt][1] * scale);
                float2 v1 = make_float2(acc[mt][nt][2] * scale, acc[mt][nt][3] * scale);
                *(float2*)(C + (size_t)r0 * ldc + col) = v0;
                *(float2*)(C + (size_t)(r0 + 8) * ldc + col) = v1;
            }
        }
    }
}

// ---------------------------------------------------------------------------
// Fused flash attention: per CTA one (bh, 128-query tile). 8 warps x 16 rows.
// S = 3-pass split QK^T (k=192), online softmax, 3-pass split PV (d=128).
// Emits attention output directly as hi/lo bf16 planes [2048][4096].
// ---------------------------------------------------------------------------
#define FL_SMEM 229376
__global__ void __launch_bounds__(256, 1) flash_k(
    const bf16* __restrict__ qh_, const bf16* __restrict__ ql_,
    const bf16* __restrict__ kh_, const bf16* __restrict__ kl_,
    const bf16* __restrict__ vh_, const bf16* __restrict__ vl_,
    const float* __restrict__ mb,
    bf16* __restrict__ ath, bf16* __restrict__ atl)
{
    extern __shared__ char smem[];
    int bh = blockIdx.x, b = bh >> 5, h = bh & 31;
    int qi = 7 - blockIdx.y;               // heavy tiles first
    int t0 = qi * 128;
    int tid = threadIdx.x, lane = tid & 31, wid = tid >> 5;
    int wrow = wid * 16;

    uint32_t S0 = smem_u32(smem);
    uint32_t Qh = S0, Ql = S0 + 49152;
    uint32_t Kb = S0 + 98304;              // two 49152 stages (hi @0, lo @24576)
    uint32_t Vb = S0 + 196608;             // hi @0, lo @16384

    const bf16* Qgh = qh_ + ((size_t)(b * 1024 + t0)) * 6144 + h * 192;
    const bf16* Qgl = ql_ + ((size_t)(b * 1024 + t0)) * 6144 + h * 192;
    const bf16* Kgh = kh_ + (size_t)bh * 1024 * 192;
    const bf16* Kgl = kl_ + (size_t)bh * 1024 * 192;
    const bf16* Vgh = vh_ + (size_t)bh * 1024 * 128;
    const bf16* Vgl = vl_ + (size_t)bh * 1024 * 128;
    const float* mbb = mb + b * 1024;

    // group 0: Q (12 subplanes) + K tile 0
#pragma unroll
    for (int sp = 0; sp < 6; sp++) {
        load_plane(Qh + sp * 8192, Qgh, 0, 6144, sp * 32, tid, 128);
        load_plane(Ql + sp * 8192, Qgl, 0, 6144, sp * 32, tid, 128);
    }
#pragma unroll
    for (int sp = 0; sp < 6; sp++) {
        load_plane64(Kb + sp * 4096,         Kgh, 192, sp * 32, tid);
        load_plane64(Kb + 24576 + sp * 4096, Kgl, 192, sp * 32, tid);
    }
    CP_COMMIT();

    int nst = (t0 + 128) >> 6;
    float m0 = -1e30f, m1 = -1e30f, l0 = 0.f, l1 = 0.f;
    float O[16][4];
#pragma unroll
    for (int i = 0; i < 16; i++)
#pragma unroll
        for (int j = 0; j < 4; j++) O[i][j] = 0.f;

    int rA = wrow + (lane & 15);
    int swA = (rA >> 1) & 3;
    int rB[4], swB[4];
#pragma unroll
    for (int g = 0; g < 4; g++) {
        rB[g] = g * 16 + (lane & 7) + ((lane >> 4) << 3);
        swB[g] = (rB[g] >> 1) & 3;
    }
    int aSel = (lane >> 4) & 1, bSel = (lane >> 3) & 1;
    int trow = t0 + wrow + (lane >> 2);

    for (int i = 0; i < nst; i++) {
        __syncthreads();                               // V/K stage reuse safety
        load_v(Vb,          Vgh + (size_t)i * 64 * 128, tid);
        load_v(Vb + 16384,  Vgl + (size_t)i * 64 * 128, tid);
        CP_COMMIT();
        if (i + 1 < nst) {
            uint32_t Ks = Kb + ((i + 1) & 1) * 49152;
            const bf16* gh = Kgh + (size_t)(i + 1) * 64 * 192;
            const bf16* gl = Kgl + (size_t)(i + 1) * 64 * 192;
#pragma unroll
            for (int sp = 0; sp < 6; sp++) {
                load_plane64(Ks + sp * 4096,         gh, 192, sp * 32, tid);
                load_plane64(Ks + 24576 + sp * 4096, gl, 192, sp * 32, tid);
            }
        }
        CP_COMMIT();

        CP_WAIT(2);                                    // K(i) (and Q) ready
        __syncthreads();

        // ---- phase 1: S = QK^T (3 passes) ----
        float S[8][4];
#pragma unroll
        for (int nt = 0; nt < 8; nt++)
#pragma unroll
            for (int j = 0; j < 4; j++) S[nt][j] = 0.f;

        uint32_t Ks = Kb + (i & 1) * 49152;
#pragma unroll
        for (int ks = 0; ks < 12; ks++) {
            int sp = ks >> 1;
            int cA = ((ks & 1) << 1) + aSel;
            int cB = ((ks & 1) << 1) + bSel;
            uint32_t ah[4], bhf[4][4], blf[4][4];
            LDSM4(ah, Qh + sp * 8192 + rA * 64 + (uint32_t)((cA ^ swA) << 4));
#pragma unroll
            for (int g = 0; g < 4; g++)
                LDSM4(bhf[g], Ks + sp * 4096 + rB[g] * 64 + (uint32_t)((cB ^ swB[g]) << 4));
#pragma unroll
            for (int g = 0; g < 4; g++) {
                MMA16816(S[2 * g], ah, bhf[g][0], bhf[g][1]);
                MMA16816(S[2 * g + 1], ah, bhf[g][2], bhf[g][3]);
            }
#pragma unroll
            for (int g = 0; g < 4; g++)
                LDSM4(blf[g], Ks + 24576 + sp * 4096 + rB[g] * 64 + (uint32_t)((cB ^ swB[g]) << 4));
#pragma unroll
            for (int g = 0; g < 4; g++) {
                MMA16816(S[2 * g], ah, blf[g][0], blf[g][1]);
                MMA16816(S[2 * g + 1], ah, blf[g][2], blf[g][3]);
            }
            LDSM4(ah, Ql + sp * 8192 + rA * 64 + (uint32_t)((cA ^ swA) << 4));
#pragma unroll
            for (int g = 0; g < 4; g++) {
                MMA16816(S[2 * g], ah, bhf[g][0], bhf[g][1]);
                MMA16816(S[2 * g + 1], ah, bhf[g][2], bhf[g][3]);
            }
        }

        // ---- online softmax ----
        int s0i = i * 64;
        float mx0 = -1e30f, mx1 = -1e30f;
#pragma unroll
        for (int nt = 0; nt < 8; nt++) {
            int sb0 = s0i + nt * 8 + ((lane & 3) << 1);
            float bias0 = mbb[sb0], bias1 = mbb[sb0 + 1];
            float v0 = S[nt][0] * SCALE_QK + bias0; if (sb0     > trow)     v0 = -1e30f;
            float v1 = S[nt][1] * SCALE_QK + bias1; if (sb0 + 1 > trow)     v1 = -1e30f;
            float v2 = S[nt][2] * SCALE_QK + bias0; if (sb0     > trow + 8) v2 = -1e30f;
            float v3 = S[nt][3] * SCALE_QK + bias1; if (sb0 + 1 > trow + 8) v3 = -1e30f;
            S[nt][0] = v0; S[nt][1] = v1; S[nt][2] = v2; S[nt][3] = v3;
            mx0 = fmaxf(mx0, fmaxf(v0, v1));
            mx1 = fmaxf(mx1, fmaxf(v2, v3));
        }
        mx0 = fmaxf(mx0, __shfl_xor_sync(0xffffffffu, mx0, 1));
        mx0 = fmaxf(mx0, __shfl_xor_sync(0xffffffffu, mx0, 2));
        mx1 = fmaxf(mx1, __shfl_xor_sync(0xffffffffu, mx1, 1));
        mx1 = fmaxf(mx1, __shfl_xor_sync(0xffffffffu, mx1, 2));
        float mn0 = fmaxf(m0, mx0), mn1 = fmaxf(m1, mx1);
        float cr0 = __expf(m0 - mn0), cr1 = __expf(m1 - mn1);
        float sum0 = 0.f, sum1 = 0.f;
#pragma unroll
        for (int nt = 0; nt < 8; nt++) {
            S[nt][0] = __expf(S[nt][0] - mn0);
            S[nt][1] = __expf(S[nt][1] - mn0);
            S[nt][2] = __expf(S[nt][2] - mn1);
            S[nt][3] = __expf(S[nt][3] - mn1);
            sum0 += S[nt][0] + S[nt][1];
            sum1 += S[nt][2] + S[nt][3];
        }
        sum0 += __shfl_xor_sync(0xffffffffu, sum0, 1);
        sum0 += __shfl_xor_sync(0xffffffffu, sum0, 2);
        sum1 += __shfl_xor_sync(0xffffffffu, sum1, 1);
        sum1 += __shfl_xor_sync(0xffffffffu, sum1, 2);
        l0 = l0 * cr0 + sum0;  l1 = l1 * cr1 + sum1;
        m0 = mn0;  m1 = mn1;
#pragma unroll
        for (int nd = 0; nd < 16; nd++) {
            O[nd][0] *= cr0; O[nd][1] *= cr0;
            O[nd][2] *= cr1; O[nd][3] *= cr1;
        }

        CP_WAIT(1);                                    // V(i) ready
        __syncthreads();

        // ---- phase 2: O += P @ V (3 passes) ----
        int rV = (lane & 15);
#pragma unroll
        for (int kc = 0; kc < 4; kc++) {
            uint32_t phi[4], plo[4];
#pragma unroll
            for (int j = 0; j < 2; j++) {
                int nt = 2 * kc + j;
                float p0 = S[nt][0], p1 = S[nt][1], p2 = S[nt][2], p3 = S[nt][3];
                float h0 = __bfloat162float(__float2bfloat16(p0));
                float h1 = __bfloat162float(__float2bfloat16(p1));
                float h2 = __bfloat162float(__float2bfloat16(p2));
                float h3 = __bfloat162float(__float2bfloat16(p3));
                phi[2 * j]     = packbf(p0, p1);
                phi[2 * j + 1] = packbf(p2, p3);
                plo[2 * j]     = packbf(p0 - h0, p1 - h1);
                plo[2 * j + 1] = packbf(p2 - h2, p3 - h3);
            }
            int row = kc * 16 + rV;
            int sw = row & 7;
            uint32_t rbase = (uint32_t)row * 256;
            int cgrp = (lane >> 4) << 3;
#pragma unroll
            for (int g = 0; g < 8; g++) {
                int cch = (((g << 4) + cgrp) >> 3) ^ sw;
                uint32_t v4[4];
                LDSM4T(v4, Vb + rbase + (uint32_t)(cch << 4));
                MMA_P(O[2 * g],     phi[0], phi[1], phi[2], phi[3], v4[0], v4[1]);
                MMA_P(O[2 * g + 1], phi[0], phi[1], phi[2], phi[3], v4[2], v4[3]);
                MMA_P(O[2 * g],     plo[0], plo[1], plo[2], plo[3], v4[0], v4[1]);
                MMA_P(O[2 * g + 1], plo[0], plo[1], plo[2], plo[3], v4[2], v4[3]);
                LDSM4T(v4, Vb + 16384 + rbase + (uint32_t)(cch << 4));
                MMA_P(O[2 * g],     phi[0], phi[1], phi[2], phi[3], v4[0], v4[1]);
                MMA_P(O[2 * g + 1], phi[0], phi[1], phi[2], phi[3], v4[2], v4[3]);
            }
        }
    }

    // ---- epilogue: O / l -> hi/lo bf16 planes ----
    float inv0 = 1.f / l0, inv1 = 1.f / l1;
    size_t row0 = ((size_t)(b * 1024) + trow) * 4096 + h * 128;
    size_t row1 = row0 + (size_t)8 * 4096;
    int dcol = (lane & 3) * 2;
#pragma unroll
    for (int nd = 0; nd < 16; nd++) {
        float o0 = O[nd][0] * inv0, o1 = O[nd][1] * inv0;
        float o2 = O[nd][2] * inv1, o3 = O[nd][3] * inv1;
        float h0 = __bfloat162float(__float2bfloat16(o0));
        float h1 = __bfloat162float(__float2bfloat16(o1));
        float h2 = __bfloat162float(__float2bfloat16(o2));
        float h3 = __bfloat162float(__float2bfloat16(o3));
        int c = nd * 8 + dcol;
        *(uint32_t*)(ath + row0 + c) = packbf(o0, o1);
        *(uint32_t*)(atl + row0 + c) = packbf(o0 - h0, o1 - h1);
        *(uint32_t*)(ath + row1 + c) = packbf(o2, o3);
        *(uint32_t*)(atl + row1 + c) = packbf(o2 - h2, o3 - h3);
    }
}

// ------------------------- conversion / elementwise -------------------------
__device__ __forceinline__ void split1(float v, bf16* h, bf16* l, size_t i) {
    bf16 hi = __float2bfloat16(v);
    h[i] = hi;
    l[i] = __float2bfloat16(v - __bfloat162float(hi));
}

__global__ void split_k(const float* __restrict__ x, bf16* __restrict__ h,
                        bf16* __restrict__ l, long n) {
    long i = blockIdx.x * 256ll + threadIdx.x;
    if (i < n) split1(x[i], h, l, i);
}

__global__ void wtsplit_k(const float* __restrict__ W, bf16* __restrict__ Th,
                          bf16* __restrict__ Tl, int K, int N) {
    __shared__ float t[32][33];
    int n0 = blockIdx.x * 32, k0 = blockIdx.y * 32;
    int tx = threadIdx.x, ty = threadIdx.y;
#pragma unroll
    for (int j = 0; j < 32; j += 8)
        t[ty + j][tx] = W[(size_t)(k0 + ty + j) * N + n0 + tx];
    __syncthreads();
#pragma unroll
    for (int j = 0; j < 32; j += 8)
        split1(t[tx][ty + j], Th, Tl, (size_t)(n0 + ty + j) * K + k0 + tx);
}

__global__ void rmsns_k(const float* __restrict__ x, const float* __restrict__ w,
                        bf16* __restrict__ h, bf16* __restrict__ l, int n, int lds) {
    __shared__ float red[256];
    long row = blockIdx.x;
    const float* p = x + row * lds;
    int tid = threadIdx.x;
    float ss = 0.f;
    for (int c = tid; c < n; c += 256) { float v = p[c]; ss += v * v; }
    red[tid] = ss; __syncthreads();
    for (int s = 128; s > 0; s >>= 1) {
        if (tid < s) red[tid] += red[tid + s];
        __syncthreads();
    }
    float r = rsqrtf(red[0] / (float)n + 1e-6f);
    for (int c = tid; c < n; c += 256)
        split1(p[c] * r * w[c], h, l, row * n + c);
}

__global__ void rope_q_k(float* __restrict__ q, const int* __restrict__ pos) {
    int gid = blockIdx.x * 256 + threadIdx.x;
    int i = gid & 31, row = gid >> 5;
    int h = row & 31, bt = row >> 5;
    float p = (float)pos[bt];
    float invf = powf(10000.f, -(float)i / 32.f);
    float sn, cs; sincosf(p * invf, &sn, &cs);
    float* base = q + (size_t)bt * 6144 + h * 192 + 128;
    float x1 = base[i], x2 = base[32 + i];
    base[i]      = x1 * cs - x2 * sn;
    base[32 + i] = x1 * sn + x2 * cs;
}

__global__ void rope_kpe_k(float* __restrict__ kvout, const int* __restrict__ pos) {
    int gid = blockIdx.x * 256 + threadIdx.x;
    int i = gid & 31, bt = gid >> 5;
    float p = (float)pos[bt];
    float invf = powf(10000.f, -(float)i / 32.f);
    float sn, cs; sincosf(p * invf, &sn, &cs);
    float* base = kvout + (size_t)bt * 576 + 512;
    float x1 = base[i], x2 = base[32 + i];
    base[i]      = x1 * cs - x2 * sn;
    base[32 + i] = x1 * sn + x2 * cs;
}

__global__ void kgather_k(const float* __restrict__ kvexp,
                          const float* __restrict__ kvout,
                          bf16* __restrict__ kh, bf16* __restrict__ kl) {
    long gid = blockIdx.x * 256ll + threadIdx.x;   // 64*1024*192
    int k = (int)(gid % 192);
    long r = gid / 192;
    int s = (int)(r & 1023), bh = (int)(r >> 10);
    int b = bh >> 5, h = bh & 31;
    float v = (k < 128)
        ? kvexp[((size_t)b * 1024 + s) * 8192 + h * 256 + k]
        : kvout[((size_t)b * 1024 + s) * 576 + 512 + (k - 128)];
    split1(v, kh, kl, gid);
}

// V gather in natural [bh][s][128] layout (coalesced both sides)
__global__ void vgather_k(const float* __restrict__ kvexp,
                          bf16* __restrict__ vh, bf16* __restrict__ vl) {
    long gid = blockIdx.x * 256ll + threadIdx.x;   // 64*1024*128
    int d = (int)(gid & 127);
    long r = gid >> 7;
    int s = (int)(r & 1023), bh = (int)(r >> 10);
    int b = bh >> 5, h = bh & 31;
    float v = kvexp[((size_t)b * 1024 + s) * 8192 + h * 256 + 128 + d];
    split1(v, vh, vl, gid);
}

__global__ void maskbias_k(const int* __restrict__ amask, float* __restrict__ mb) {
    int i = blockIdx.x * 256 + threadIdx.x;
    if (i < 2048) mb[i] = amask[i] ? 0.f : -1e30f;
}

// ---------------------------------------------------------------------------
extern "C" void kernel_launch(void* const* d_in, const int* in_sizes, int n_in,
                              void* d_out, int out_size)
{
    const float* x        = (const float*)d_in[0];
    const float* wq_a     = (const float*)d_in[1];
    const float* q_norm_w = (const float*)d_in[2];
    const float* wq_b     = (const float*)d_in[3];
    const float* wkv_a    = (const float*)d_in[4];
    const float* kv_norm_w= (const float*)d_in[5];
    const float* wkv_b    = (const float*)d_in[6];
    const float* wo       = (const float*)d_in[7];
    const int*   amask    = (const int*)d_in[8];
    const int*   pos      = (const int*)d_in[9];
    float*       out      = (float*)d_out;

    cudaFuncSetAttribute(gemm3_k, cudaFuncAttributeMaxDynamicSharedMemorySize,
                         GEMM_SMEM);
    cudaFuncSetAttribute(flash_k, cudaFuncAttributeMaxDynamicSharedMemorySize,
                         FL_SMEM);

    float *qlow, *qf, *kvout, *kvexp, *mb;
    bf16 *xh,*xl,*qlh,*qll,*qh,*ql,*kvh,*kvl,*kh,*kl,*vh,*vl,*ath,*atl;
    bf16 *wqah,*wqal,*wqbh,*wqbl,*wkvah,*wkval,*wkvbh,*wkvbl,*woh,*wol;
    cudaGetSymbolAddress((void**)&qlow, g_qlow);
    cudaGetSymbolAddress((void**)&qf,   g_q);
    cudaGetSymbolAddress((void**)&kvout,g_kvout);
    cudaGetSymbolAddress((void**)&kvexp,g_kvexp);
    cudaGetSymbolAddress((void**)&mb,   g_mb);
    cudaGetSymbolAddress((void**)&xh, g_xh);   cudaGetSymbolAddress((void**)&xl, g_xl);
    cudaGetSymbolAddress((void**)&qlh,g_qlh);  cudaGetSymbolAddress((void**)&qll,g_qll);
    cudaGetSymbolAddress((void**)&qh, g_qh);   cudaGetSymbolAddress((void**)&ql, g_ql);
    cudaGetSymbolAddress((void**)&kvh,g_kvh);  cudaGetSymbolAddress((void**)&kvl,g_kvl);
    cudaGetSymbolAddress((void**)&kh, g_kh);   cudaGetSymbolAddress((void**)&kl, g_kl);
    cudaGetSymbolAddress((void**)&vh, g_vh);   cudaGetSymbolAddress((void**)&vl, g_vl);
    cudaGetSymbolAddress((void**)&ath,g_ath);  cudaGetSymbolAddress((void**)&atl,g_atl);
    cudaGetSymbolAddress((void**)&wqah,g_wqah); cudaGetSymbolAddress((void**)&wqal,g_wqal);
    cudaGetSymbolAddress((void**)&wqbh,g_wqbh); cudaGetSymbolAddress((void**)&wqbl,g_wqbl);
    cudaGetSymbolAddress((void**)&wkvah,g_wkvah); cudaGetSymbolAddress((void**)&wkval,g_wkval);
    cudaGetSymbolAddress((void**)&wkvbh,g_wkvbh); cudaGetSymbolAddress((void**)&wkvbl,g_wkvbl);
    cudaGetSymbolAddress((void**)&woh,g_woh);   cudaGetSymbolAddress((void**)&wol,g_wol);

    dim3 tb(32, 8);
    wtsplit_k<<<dim3(48, 128), tb>>>(wq_a, wqah, wqal, 4096, 1536);
    wtsplit_k<<<dim3(192, 48), tb>>>(wq_b, wqbh, wqbl, 1536, 6144);
    wtsplit_k<<<dim3(18, 128), tb>>>(wkv_a, wkvah, wkval, 4096, 576);
    wtsplit_k<<<dim3(256, 16), tb>>>(wkv_b, wkvbh, wkvbl, 512, 8192);
    wtsplit_k<<<dim3(128, 128), tb>>>(wo, woh, wol, 4096, 4096);
    split_k<<<32768, 256>>>(x, xh, xl, 2048ll * 4096);
    maskbias_k<<<8, 256>>>(amask, mb);

    // 1. qlow = x @ wq_a
    gemm3_k<<<dim3(12, 16, 1), 256, GEMM_SMEM>>>(xh, xl, wqah, wqal, qlow,
        1536, 4096, 4096, 4096, 1536, 0,0,0,0,0,0, 1, 0, 1.f);
    // 2. rmsnorm -> hi/lo
    rmsns_k<<<2048, 256>>>(qlow, q_norm_w, qlh, qll, 1536, 1536);
    // 3. q = qlow @ wq_b
    gemm3_k<<<dim3(48, 16, 1), 256, GEMM_SMEM>>>(qlh, qll, wqbh, wqbl, qf,
        6144, 1536, 1536, 1536, 6144, 0,0,0,0,0,0, 1, 0, 1.f);
    // 4. kvout = x @ wkv_a
    gemm3_k<<<dim3(5, 16, 1), 256, GEMM_SMEM>>>(xh, xl, wkvah, wkval, kvout,
        576, 4096, 4096, 4096, 576, 0,0,0,0,0,0, 1, 0, 1.f);
    // 5. rmsnorm kv -> hi/lo; rope
    rmsns_k<<<2048, 256>>>(kvout, kv_norm_w, kvh, kvl, 512, 576);
    rope_q_k<<<8192, 256>>>(qf, pos);
    rope_kpe_k<<<256, 256>>>(kvout, pos);
    split_k<<<49152, 256>>>(qf, qh, ql, 2048ll * 6144);
    // 7. kvexp = kv @ wkv_b
    gemm3_k<<<dim3(64, 16, 1), 256, GEMM_SMEM>>>(kvh, kvl, wkvbh, wkvbl, kvexp,
        8192, 512, 512, 512, 8192, 0,0,0,0,0,0, 1, 0, 1.f);
    // 8. per-head K/V gather (hi/lo planes)
    kgather_k<<<49152, 256>>>(kvexp, kvout, kh, kl);
    vgather_k<<<32768, 256>>>(kvexp, vh, vl);
    // 9. fused attention -> ath/atl
    flash_k<<<dim3(64, 8), 256, FL_SMEM>>>(qh, ql, kh, kl, vh, vl, mb, ath, atl);
    // 10. out = attn @ wo
    gemm3_k<<<dim3(32, 16, 1), 256, GEMM_SMEM>>>(ath, atl, woh, wol, out,
        4096, 4096, 4096, 4096, 4096, 0,0,0,0,0,0, 1, 0, 1.f);
}

// round 6
// speedup vs baseline: 1.1402x; 1.1402x over previous
#include <cuda_runtime.h>
#include <cuda_bf16.h>
#include <math.h>
#include <stdint.h>

typedef __nv_bfloat16 bf16;
#define TT 1024
#define SCALE_QK 0.07216878364870323f

// ------------------------- device scratch (no cudaMalloc) -------------------
__device__ float g_qkv  [2048*2112];     // [:,0:1536]=qlow, [:,1536:2048]=kv, [:,2048:2112]=k_pe
__device__ float g_q    [2048*6144];
__device__ float g_kvexp[2048*8192];
__device__ float g_mb   [2048];

__device__ bf16 g_xh[2048*4096],  g_xl[2048*4096];
__device__ bf16 g_qlh[2048*1536], g_qll[2048*1536];
__device__ bf16 g_qh[2048*6144],  g_ql[2048*6144];
__device__ bf16 g_kvh[2048*512],  g_kvl[2048*512];
__device__ bf16 g_kh[64ll*1024*192], g_kl[64ll*1024*192];
__device__ bf16 g_vh[64ll*1024*128], g_vl[64ll*1024*128];
__device__ bf16 g_ath[2048*4096], g_atl[2048*4096];
__device__ bf16 g_wabh[2112*4096], g_wabl[2112*4096];   // [wq_a ; wkv_a] transposed
__device__ bf16 g_wqbh[6144*1536], g_wqbl[6144*1536];
__device__ bf16 g_wkvbh[8192*512], g_wkvbl[8192*512];
__device__ bf16 g_woh[4096*4096],  g_wol[4096*4096];

// ------------------------------ PTX helpers (sm_80-safe) --------------------
__device__ __forceinline__ uint32_t smem_u32(const void* p) {
    uint32_t a;
    asm("{ .reg .u64 t; cvta.to.shared.u64 t, %1; cvt.u32.u64 %0, t; }"
        : "=r"(a) : "l"(p));
    return a;
}

#define LDSM4(r, a) asm volatile( \
    "ldmatrix.sync.aligned.m8n8.x4.shared.b16 {%0,%1,%2,%3}, [%4];" \
    : "=r"((r)[0]), "=r"((r)[1]), "=r"((r)[2]), "=r"((r)[3]) : "r"(a))

#define LDSM4T(r, a) asm volatile( \
    "ldmatrix.sync.aligned.m8n8.x4.trans.shared.b16 {%0,%1,%2,%3}, [%4];" \
    : "=r"((r)[0]), "=r"((r)[1]), "=r"((r)[2]), "=r"((r)[3]) : "r"(a))

#define MMA16816(d, a, b0, b1) asm volatile( \
    "mma.sync.aligned.m16n8k16.row.col.f32.bf16.bf16.f32 " \
    "{%0,%1,%2,%3},{%4,%5,%6,%7},{%8,%9},{%0,%1,%2,%3};" \
    : "+f"((d)[0]), "+f"((d)[1]), "+f"((d)[2]), "+f"((d)[3]) \
    : "r"((a)[0]), "r"((a)[1]), "r"((a)[2]), "r"((a)[3]), "r"(b0), "r"(b1))

#define MMA_P(d, a0, a1, a2, a3, b0, b1) asm volatile( \
    "mma.sync.aligned.m16n8k16.row.col.f32.bf16.bf16.f32 " \
    "{%0,%1,%2,%3},{%4,%5,%6,%7},{%8,%9},{%0,%1,%2,%3};" \
    : "+f"((d)[0]), "+f"((d)[1]), "+f"((d)[2]), "+f"((d)[3]) \
    : "r"(a0), "r"(a1), "r"(a2), "r"(a3), "r"(b0), "r"(b1))

__device__ __forceinline__ void cpa16(uint32_t dst, const void* src, int valid) {
    int sz = valid ? 16 : 0;
    asm volatile("cp.async.cg.shared.global [%0], [%1], 16, %2;"
                 :: "r"(dst), "l"(src), "r"(sz));
}
#define CP_COMMIT() asm volatile("cp.async.commit_group;" ::: "memory")
#define CP_WAIT(n)  asm volatile("cp.async.wait_group %0;" :: "n"(n) : "memory")

__device__ __forceinline__ uint32_t packbf(float a, float b) {
    __nv_bfloat162 t = __floats2bfloat162_rn(a, b);
    return *reinterpret_cast<uint32_t*>(&t);
}

// Load one 128x32 bf16 plane into swizzled smem (rows of 64B).
__device__ __forceinline__ void load_plane(uint32_t sb, const bf16* __restrict__ G,
                                           int row0, int ld, int k0, int tid,
                                           int nvalid) {
#pragma unroll
    for (int i = 0; i < 2; i++) {
        int idx = tid * 2 + i;
        int r = idx >> 2, c = idx & 3;
        uint32_t dst = sb + r * 64 + ((c ^ ((r >> 1) & 3)) << 4);
        int ok = r < nvalid;
        const bf16* src = G + (size_t)(row0 + (ok ? r : 0)) * ld + k0 + c * 8;
        cpa16(dst, src, ok);
    }
}

// Load one 64x32 bf16 subplane (256 threads -> 1 line each).
__device__ __forceinline__ void load_plane64(uint32_t sb, const bf16* __restrict__ G,
                                             int ld, int k0, int tid) {
    int r = tid >> 2, c = tid & 3;
    uint32_t dst = sb + r * 64 + ((c ^ ((r >> 1) & 3)) << 4);
    cpa16(dst, G + (size_t)r * ld + k0 + c * 8, 1);
}

// Load one 64x128 bf16 V plane (rows of 256B) with row-xor swizzle.
__device__ __forceinline__ void load_v(uint32_t sb, const bf16* __restrict__ G,
                                       int tid) {
#pragma unroll
    for (int i = 0; i < 4; i++) {
        int idx = i * 256 + tid;
        int r = idx >> 4, c = idx & 15;
        uint32_t dst = sb + r * 256 + ((c ^ (r & 7)) << 4);
        cpa16(dst, G + (size_t)r * 128 + c * 8, 1);
    }
}

// ---------------------------------------------------------------------------
// 3-pass split-bf16 HMMA GEMM, 3-stage cp.async pipeline, 2 CTAs/SM.
// C[M,N] = (Ah+Al)[M,K] @ (Bh+Bl)[N,K]^T * scale (drops Al*Bl).
// ---------------------------------------------------------------------------
#define GEMM_SMEM 98304
__global__ void __launch_bounds__(256, 2) gemm3_k(
    const bf16* __restrict__ Ah_, const bf16* __restrict__ Al_,
    const bf16* __restrict__ Bh_, const bf16* __restrict__ Bl_,
    float* __restrict__ C_,
    int N, int K, int lda, int ldb, int ldc,
    long aOut, long aIn, long bOut, long bIn, long cOut, long cIn,
    int innerCnt, int flags, float scale)
{
    extern __shared__ char smem[];
    int m0 = blockIdx.y * 128, n0 = blockIdx.x * 128;
    if ((flags & 2) && n0 > m0) return;

    int z = blockIdx.z, outer = z / innerCnt, inner = z - outer * innerCnt;
    const bf16* Ah = Ah_ + outer * aOut + inner * aIn;
    const bf16* Al = Al_ + outer * aOut + inner * aIn;
    const bf16* Bh = Bh_ + outer * bOut + inner * bIn;
    const bf16* Bl = Bl_ + outer * bOut + inner * bIn;
    float*      C  = C_  + outer * cOut + inner * cIn;

    int tid = threadIdx.x, lane = tid & 31, wid = tid >> 5;
    int mw = (wid & 1) * 64, nw = (wid >> 1) * 32;
    uint32_t s0 = smem_u32(smem);
    int nvB = min(128, N - n0);

    int Keff = (flags & 1) ? min(K, m0 + 128) : K;
    int nch = Keff >> 5;

    uint32_t rowA[4]; int sA[4];
#pragma unroll
    for (int mt = 0; mt < 4; mt++) {
        int r = mw + mt * 16 + (lane & 15);
        rowA[mt] = r * 64; sA[mt] = (r >> 1) & 3;
    }
    uint32_t rowB[2]; int sB[2];
#pragma unroll
    for (int h2 = 0; h2 < 2; h2++) {
        int r = nw + h2 * 16 + (lane & 7) + ((lane >> 4) << 3);
        rowB[h2] = r * 64; sB[h2] = (r >> 1) & 3;
    }
    int aCk = (lane >> 4) & 1, bCk = (lane >> 3) & 1;

    float acc[4][4][4];
#pragma unroll
    for (int i = 0; i < 4; i++)
#pragma unroll
        for (int j = 0; j < 4; j++)
#pragma unroll
            for (int r = 0; r < 4; r++) acc[i][j][r] = 0.f;

    // prologue: stages 0,1
    {
        load_plane(s0,         Ah, m0, lda, 0, tid, 128);
        load_plane(s0 + 8192,  Al, m0, lda, 0, tid, 128);
        load_plane(s0 + 16384, Bh, n0, ldb, 0, tid, nvB);
        load_plane(s0 + 24576, Bl, n0, ldb, 0, tid, nvB);
        CP_COMMIT();
        if (nch > 1) {
            uint32_t sb = s0 + 32768;
            load_plane(sb,         Ah, m0, lda, 32, tid, 128);
            load_plane(sb + 8192,  Al, m0, lda, 32, tid, 128);
            load_plane(sb + 16384, Bh, n0, ldb, 32, tid, nvB);
            load_plane(sb + 24576, Bl, n0, ldb, 32, tid, nvB);
        }
        CP_COMMIT();
    }

    for (int c = 0; c < nch; c++) {
        CP_WAIT(1);
        __syncthreads();
        if (c + 2 < nch) {
            uint32_t sb = s0 + ((c + 2) % 3) * 32768;
            int k0 = (c + 2) * 32;
            load_plane(sb,         Ah, m0, lda, k0, tid, 128);
            load_plane(sb + 8192,  Al, m0, lda, k0, tid, 128);
            load_plane(sb + 16384, Bh, n0, ldb, k0, tid, nvB);
            load_plane(sb + 24576, Bl, n0, ldb, k0, tid, nvB);
        }
        CP_COMMIT();

        uint32_t base = s0 + (c % 3) * 32768;
        uint32_t pAh = base, pAl = base + 8192;
        uint32_t pBh = base + 16384, pBl = base + 24576;
#pragma unroll
        for (int ks = 0; ks < 2; ks++) {
            uint32_t af[4][4], bhf[2][4], blf[2][4];
            int cA = ks * 2 + aCk, cB = ks * 2 + bCk;
#pragma unroll
            for (int mt = 0; mt < 4; mt++)
                LDSM4(af[mt], pAh + rowA[mt] + (uint32_t)((cA ^ sA[mt]) << 4));
#pragma unroll
            for (int h2 = 0; h2 < 2; h2++) {
                LDSM4(bhf[h2], pBh + rowB[h2] + (uint32_t)((cB ^ sB[h2]) << 4));
                LDSM4(blf[h2], pBl + rowB[h2] + (uint32_t)((cB ^ sB[h2]) << 4));
            }
#pragma unroll
            for (int mt = 0; mt < 4; mt++)
#pragma unroll
                for (int nt = 0; nt < 4; nt++)
                    MMA16816(acc[mt][nt], af[mt],
                             bhf[nt >> 1][(nt & 1) * 2], bhf[nt >> 1][(nt & 1) * 2 + 1]);
#pragma unroll
            for (int mt = 0; mt < 4; mt++)
#pragma unroll
                for (int nt = 0; nt < 4; nt++)
                    MMA16816(acc[mt][nt], af[mt],
                             blf[nt >> 1][(nt & 1) * 2], blf[nt >> 1][(nt & 1) * 2 + 1]);
#pragma unroll
            for (int mt = 0; mt < 4; mt++)
                LDSM4(af[mt], pAl + rowA[mt] + (uint32_t)((cA ^ sA[mt]) << 4));
#pragma unroll
            for (int mt = 0; mt < 4; mt++)
#pragma unroll
                for (int nt = 0; nt < 4; nt++)
                    MMA16816(acc[mt][nt], af[mt],
                             bhf[nt >> 1][(nt & 1) * 2], bhf[nt >> 1][(nt & 1) * 2 + 1]);
        }
        __syncthreads();
    }

#pragma unroll
    for (int mt = 0; mt < 4; mt++) {
        int r0 = m0 + mw + mt * 16 + (lane >> 2);
#pragma unroll
        for (int nt = 0; nt < 4; nt++) {
            int col = n0 + nw + nt * 8 + 2 * (lane & 3);
            if (col < N) {
                float2 v0 = make_float2(acc[mt][nt][0] * scale, acc[mt][nt][1] * scale);
                float2 v1 = make_float2(acc[mt][nt][2] * scale, acc[mt][nt][3] * scale);
                *(float2*)(C + (size_t)r0 * ldc + col) = v0;
                *(float2*)(C + (size_t)(r0 + 8) * ldc + col) = v1;
            }
        }
    }
}

// ---------------------------------------------------------------------------
// Fused flash attention: per CTA one (bh, 128-query tile). 8 warps x 16 rows.
// ---------------------------------------------------------------------------
#define FL_SMEM 229376
__global__ void __launch_bounds__(256, 1) flash_k(
    const bf16* __restrict__ qh_, const bf16* __restrict__ ql_,
    const bf16* __restrict__ kh_, const bf16* __restrict__ kl_,
    const bf16* __restrict__ vh_, const bf16* __restrict__ vl_,
    const float* __restrict__ mb,
    bf16* __restrict__ ath, bf16* __restrict__ atl)
{
    extern __shared__ char smem[];
    int bh = blockIdx.x, b = bh >> 5, h = bh & 31;
    int qi = 7 - blockIdx.y;               // heavy tiles first
    int t0 = qi * 128;
    int tid = threadIdx.x, lane = tid & 31, wid = tid >> 5;
    int wrow = wid * 16;

    uint32_t S0 = smem_u32(smem);
    uint32_t Qh = S0, Ql = S0 + 49152;
    uint32_t Kb = S0 + 98304;              // two 49152 stages (hi @0, lo @24576)
    uint32_t Vb = S0 + 196608;             // hi @0, lo @16384

    const bf16* Qgh = qh_ + ((size_t)(b * 1024 + t0)) * 6144 + h * 192;
    const bf16* Qgl = ql_ + ((size_t)(b * 1024 + t0)) * 6144 + h * 192;
    const bf16* Kgh = kh_ + (size_t)bh * 1024 * 192;
    const bf16* Kgl = kl_ + (size_t)bh * 1024 * 192;
    const bf16* Vgh = vh_ + (size_t)bh * 1024 * 128;
    const bf16* Vgl = vl_ + (size_t)bh * 1024 * 128;
    const float* mbb = mb + b * 1024;

#pragma unroll
    for (int sp = 0; sp < 6; sp++) {
        load_plane(Qh + sp * 8192, Qgh, 0, 6144, sp * 32, tid, 128);
        load_plane(Ql + sp * 8192, Qgl, 0, 6144, sp * 32, tid, 128);
    }
#pragma unroll
    for (int sp = 0; sp < 6; sp++) {
        load_plane64(Kb + sp * 4096,         Kgh, 192, sp * 32, tid);
        load_plane64(Kb + 24576 + sp * 4096, Kgl, 192, sp * 32, tid);
    }
    CP_COMMIT();

    int nst = (t0 + 128) >> 6;
    float m0 = -1e30f, m1 = -1e30f, l0 = 0.f, l1 = 0.f;
    float O[16][4];
#pragma unroll
    for (int i = 0; i < 16; i++)
#pragma unroll
        for (int j = 0; j < 4; j++) O[i][j] = 0.f;

    int rA = wrow + (lane & 15);
    int swA = (rA >> 1) & 3;
    int rB[4], swB[4];
#pragma unroll
    for (int g = 0; g < 4; g++) {
        rB[g] = g * 16 + (lane & 7) + ((lane >> 4) << 3);
        swB[g] = (rB[g] >> 1) & 3;
    }
    int aSel = (lane >> 4) & 1, bSel = (lane >> 3) & 1;
    int trow = t0 + wrow + (lane >> 2);

    for (int i = 0; i < nst; i++) {
        __syncthreads();
        load_v(Vb,          Vgh + (size_t)i * 64 * 128, tid);
        load_v(Vb + 16384,  Vgl + (size_t)i * 64 * 128, tid);
        CP_COMMIT();
        if (i + 1 < nst) {
            uint32_t Ks = Kb + ((i + 1) & 1) * 49152;
            const bf16* gh = Kgh + (size_t)(i + 1) * 64 * 192;
            const bf16* gl = Kgl + (size_t)(i + 1) * 64 * 192;
#pragma unroll
            for (int sp = 0; sp < 6; sp++) {
                load_plane64(Ks + sp * 4096,         gh, 192, sp * 32, tid);
                load_plane64(Ks + 24576 + sp * 4096, gl, 192, sp * 32, tid);
            }
        }
        CP_COMMIT();

        CP_WAIT(2);
        __syncthreads();

        // ---- S = QK^T (3 passes) ----
        float S[8][4];
#pragma unroll
        for (int nt = 0; nt < 8; nt++)
#pragma unroll
            for (int j = 0; j < 4; j++) S[nt][j] = 0.f;

        uint32_t Ks = Kb + (i & 1) * 49152;
#pragma unroll
        for (int ks = 0; ks < 12; ks++) {
            int sp = ks >> 1;
            int cA = ((ks & 1) << 1) + aSel;
            int cB = ((ks & 1) << 1) + bSel;
            uint32_t ah[4], bhf[4][4], blf[4][4];
            LDSM4(ah, Qh + sp * 8192 + rA * 64 + (uint32_t)((cA ^ swA) << 4));
#pragma unroll
            for (int g = 0; g < 4; g++)
                LDSM4(bhf[g], Ks + sp * 4096 + rB[g] * 64 + (uint32_t)((cB ^ swB[g]) << 4));
#pragma unroll
            for (int g = 0; g < 4; g++) {
                MMA16816(S[2 * g], ah, bhf[g][0], bhf[g][1]);
                MMA16816(S[2 * g + 1], ah, bhf[g][2], bhf[g][3]);
            }
#pragma unroll
            for (int g = 0; g < 4; g++)
                LDSM4(blf[g], Ks + 24576 + sp * 4096 + rB[g] * 64 + (uint32_t)((cB ^ swB[g]) << 4));
#pragma unroll
            for (int g = 0; g < 4; g++) {
                MMA16816(S[2 * g], ah, blf[g][0], blf[g][1]);
                MMA16816(S[2 * g + 1], ah, blf[g][2], blf[g][3]);
            }
            LDSM4(ah, Ql + sp * 8192 + rA * 64 + (uint32_t)((cA ^ swA) << 4));
#pragma unroll
            for (int g = 0; g < 4; g++) {
                MMA16816(S[2 * g], ah, bhf[g][0], bhf[g][1]);
                MMA16816(S[2 * g + 1], ah, bhf[g][2], bhf[g][3]);
            }
        }

        // ---- online softmax ----
        int s0i = i * 64;
        float mx0 = -1e30f, mx1 = -1e30f;
#pragma unroll
        for (int nt = 0; nt < 8; nt++) {
            int sb0 = s0i + nt * 8 + ((lane & 3) << 1);
            float bias0 = mbb[sb0], bias1 = mbb[sb0 + 1];
            float v0 = S[nt][0] * SCALE_QK + bias0; if (sb0     > trow)     v0 = -1e30f;
            float v1 = S[nt][1] * SCALE_QK + bias1; if (sb0 + 1 > trow)     v1 = -1e30f;
            float v2 = S[nt][2] * SCALE_QK + bias0; if (sb0     > trow + 8) v2 = -1e30f;
            float v3 = S[nt][3] * SCALE_QK + bias1; if (sb0 + 1 > trow + 8) v3 = -1e30f;
            S[nt][0] = v0; S[nt][1] = v1; S[nt][2] = v2; S[nt][3] = v3;
            mx0 = fmaxf(mx0, fmaxf(v0, v1));
            mx1 = fmaxf(mx1, fmaxf(v2, v3));
        }
        mx0 = fmaxf(mx0, __shfl_xor_sync(0xffffffffu, mx0, 1));
        mx0 = fmaxf(mx0, __shfl_xor_sync(0xffffffffu, mx0, 2));
        mx1 = fmaxf(mx1, __shfl_xor_sync(0xffffffffu, mx1, 1));
        mx1 = fmaxf(mx1, __shfl_xor_sync(0xffffffffu, mx1, 2));
        float mn0 = fmaxf(m0, mx0), mn1 = fmaxf(m1, mx1);
        float cr0 = __expf(m0 - mn0), cr1 = __expf(m1 - mn1);
        float sum0 = 0.f, sum1 = 0.f;
#pragma unroll
        for (int nt = 0; nt < 8; nt++) {
            S[nt][0] = __expf(S[nt][0] - mn0);
            S[nt][1] = __expf(S[nt][1] - mn0);
            S[nt][2] = __expf(S[nt][2] - mn1);
            S[nt][3] = __expf(S[nt][3] - mn1);
            sum0 += S[nt][0] + S[nt][1];
            sum1 += S[nt][2] + S[nt][3];
        }
        sum0 += __shfl_xor_sync(0xffffffffu, sum0, 1);
        sum0 += __shfl_xor_sync(0xffffffffu, sum0, 2);
        sum1 += __shfl_xor_sync(0xffffffffu, sum1, 1);
        sum1 += __shfl_xor_sync(0xffffffffu, sum1, 2);
        l0 = l0 * cr0 + sum0;  l1 = l1 * cr1 + sum1;
        m0 = mn0;  m1 = mn1;
#pragma unroll
        for (int nd = 0; nd < 16; nd++) {
            O[nd][0] *= cr0; O[nd][1] *= cr0;
            O[nd][2] *= cr1; O[nd][3] *= cr1;
        }

        CP_WAIT(1);
        __syncthreads();

        // ---- O += P @ V (3 passes) ----
        int rV = (lane & 15);
#pragma unroll
        for (int kc = 0; kc < 4; kc++) {
            uint32_t phi[4], plo[4];
#pragma unroll
            for (int j = 0; j < 2; j++) {
                int nt = 2 * kc + j;
                float p0 = S[nt][0], p1 = S[nt][1], p2 = S[nt][2], p3 = S[nt][3];
                float h0 = __bfloat162float(__float2bfloat16(p0));
                float h1 = __bfloat162float(__float2bfloat16(p1));
                float h2 = __bfloat162float(__float2bfloat16(p2));
                float h3 = __bfloat162float(__float2bfloat16(p3));
                phi[2 * j]     = packbf(p0, p1);
                phi[2 * j + 1] = packbf(p2, p3);
                plo[2 * j]     = packbf(p0 - h0, p1 - h1);
                plo[2 * j + 1] = packbf(p2 - h2, p3 - h3);
            }
            int row = kc * 16 + rV;
            int sw = row & 7;
            uint32_t rbase = (uint32_t)row * 256;
            int cgrp = (lane >> 4) << 3;
#pragma unroll
            for (int g = 0; g < 8; g++) {
                int cch = (((g << 4) + cgrp) >> 3) ^ sw;
                uint32_t v4[4];
                LDSM4T(v4, Vb + rbase + (uint32_t)(cch << 4));
                MMA_P(O[2 * g],     phi[0], phi[1], phi[2], phi[3], v4[0], v4[1]);
                MMA_P(O[2 * g + 1], phi[0], phi[1], phi[2], phi[3], v4[2], v4[3]);
                MMA_P(O[2 * g],     plo[0], plo[1], plo[2], plo[3], v4[0], v4[1]);
                MMA_P(O[2 * g + 1], plo[0], plo[1], plo[2], plo[3], v4[2], v4[3]);
                LDSM4T(v4, Vb + 16384 + rbase + (uint32_t)(cch << 4));
                MMA_P(O[2 * g],     phi[0], phi[1], phi[2], phi[3], v4[0], v4[1]);
                MMA_P(O[2 * g + 1], phi[0], phi[1], phi[2], phi[3], v4[2], v4[3]);
            }
        }
    }

    // ---- epilogue ----
    float inv0 = 1.f / l0, inv1 = 1.f / l1;
    size_t row0 = ((size_t)(b * 1024) + trow) * 4096 + h * 128;
    size_t row1 = row0 + (size_t)8 * 4096;
    int dcol = (lane & 3) * 2;
#pragma unroll
    for (int nd = 0; nd < 16; nd++) {
        float o0 = O[nd][0] * inv0, o1 = O[nd][1] * inv0;
        float o2 = O[nd][2] * inv1, o3 = O[nd][3] * inv1;
        float h0 = __bfloat162float(__float2bfloat16(o0));
        float h1 = __bfloat162float(__float2bfloat16(o1));
        float h2 = __bfloat162float(__float2bfloat16(o2));
        float h3 = __bfloat162float(__float2bfloat16(o3));
        int c = nd * 8 + dcol;
        *(uint32_t*)(ath + row0 + c) = packbf(o0, o1);
        *(uint32_t*)(atl + row0 + c) = packbf(o0 - h0, o1 - h1);
        *(uint32_t*)(ath + row1 + c) = packbf(o2, o3);
        *(uint32_t*)(atl + row1 + c) = packbf(o2 - h2, o3 - h3);
    }
}

// ------------------------- conversion / elementwise -------------------------
__device__ __forceinline__ void split1(float v, bf16* h, bf16* l, size_t i) {
    bf16 hi = __float2bfloat16(v);
    h[i] = hi;
    l[i] = __float2bfloat16(v - __bfloat162float(hi));
}

__global__ void split_k(const float* __restrict__ x, bf16* __restrict__ h,
                        bf16* __restrict__ l, long n) {
    long i = blockIdx.x * 256ll + threadIdx.x;
    if (i < n) split1(x[i], h, l, i);
}

__global__ void wtsplit_k(const float* __restrict__ W, bf16* __restrict__ Th,
                          bf16* __restrict__ Tl, int K, int N) {
    __shared__ float t[32][33];
    int n0 = blockIdx.x * 32, k0 = blockIdx.y * 32;
    int tx = threadIdx.x, ty = threadIdx.y;
#pragma unroll
    for (int j = 0; j < 32; j += 8)
        t[ty + j][tx] = W[(size_t)(k0 + ty + j) * N + n0 + tx];
    __syncthreads();
#pragma unroll
    for (int j = 0; j < 32; j += 8)
        split1(t[tx][ty + j], Th, Tl, (size_t)(n0 + ty + j) * K + k0 + tx);
}

__global__ void rmsns_k(const float* __restrict__ x, const float* __restrict__ w,
                        bf16* __restrict__ h, bf16* __restrict__ l, int n, int lds) {
    __shared__ float red[256];
    long row = blockIdx.x;
    const float* p = x + row * lds;
    int tid = threadIdx.x;
    float ss = 0.f;
    for (int c = tid; c < n; c += 256) { float v = p[c]; ss += v * v; }
    red[tid] = ss; __syncthreads();
    for (int s = 128; s > 0; s >>= 1) {
        if (tid < s) red[tid] += red[tid + s];
        __syncthreads();
    }
    float r = rsqrtf(red[0] / (float)n + 1e-6f);
    for (int c = tid; c < n; c += 256)
        split1(p[c] * r * w[c], h, l, row * n + c);
}

// fused rope + split for q: one warp per (token, head)
__global__ void rope_split_q_k(const float* __restrict__ qf,
                               const int* __restrict__ pos,
                               bf16* __restrict__ qh, bf16* __restrict__ ql) {
    int w = blockIdx.x * 8 + (threadIdx.x >> 5);   // 8192 blocks * 8 warps
    int lane = threadIdx.x & 31;
    int bt = w >> 5, h = w & 31;
    const float* base = qf + (size_t)bt * 6144 + h * 192;
    size_t ob = (size_t)bt * 6144 + h * 192;
#pragma unroll
    for (int j = 0; j < 4; j++)
        split1(base[lane + j * 32], qh, ql, ob + lane + j * 32);
    float p = (float)pos[bt];
    float invf = powf(10000.f, -(float)lane / 32.f);
    float sn, cs; sincosf(p * invf, &sn, &cs);
    float x1 = base[128 + lane], x2 = base[160 + lane];
    split1(x1 * cs - x2 * sn, qh, ql, ob + 128 + lane);
    split1(x1 * sn + x2 * cs, qh, ql, ob + 160 + lane);
}

// rope on shared k_pe: qkv cols [2048,2112)
__global__ void rope_kpe_k(float* __restrict__ qkv, const int* __restrict__ pos) {
    int gid = blockIdx.x * 256 + threadIdx.x;      // B*T*32
    int i = gid & 31, bt = gid >> 5;
    float p = (float)pos[bt];
    float invf = powf(10000.f, -(float)i / 32.f);
    float sn, cs; sincosf(p * invf, &sn, &cs);
    float* base = qkv + (size_t)bt * 2112 + 2048;
    float x1 = base[i], x2 = base[32 + i];
    base[i]      = x1 * cs - x2 * sn;
    base[32 + i] = x1 * sn + x2 * cs;
}

// K gather: [bh][s][192] from kvexp nope cols + roped shared pe (qkv cols 2048+)
__global__ void kgather_k(const float* __restrict__ kvexp,
                          const float* __restrict__ qkv,
                          bf16* __restrict__ kh, bf16* __restrict__ kl) {
    long gid = blockIdx.x * 256ll + threadIdx.x;   // 64*1024*192
    int k = (int)(gid % 192);
    long r = gid / 192;
    int s = (int)(r & 1023), bh = (int)(r >> 10);
    int b = bh >> 5, h = bh & 31;
    float v = (k < 128)
        ? kvexp[((size_t)b * 1024 + s) * 8192 + h * 256 + k]
        : qkv[((size_t)b * 1024 + s) * 2112 + 2048 + (k - 128)];
    split1(v, kh, kl, gid);
}

__global__ void vgather_k(const float* __restrict__ kvexp,
                          bf16* __restrict__ vh, bf16* __restrict__ vl) {
    long gid = blockIdx.x * 256ll + threadIdx.x;   // 64*1024*128
    int d = (int)(gid & 127);
    long r = gid >> 7;
    int s = (int)(r & 1023), bh = (int)(r >> 10);
    int b = bh >> 5, h = bh & 31;
    float v = kvexp[((size_t)b * 1024 + s) * 8192 + h * 256 + 128 + d];
    split1(v, vh, vl, gid);
}

__global__ void maskbias_k(const int* __restrict__ amask, float* __restrict__ mb) {
    int i = blockIdx.x * 256 + threadIdx.x;
    if (i < 2048) mb[i] = amask[i] ? 0.f : -1e30f;
}

// ---------------------------------------------------------------------------
extern "C" void kernel_launch(void* const* d_in, const int* in_sizes, int n_in,
                              void* d_out, int out_size)
{
    const float* x        = (const float*)d_in[0];
    const float* wq_a     = (const float*)d_in[1];
    const float* q_norm_w = (const float*)d_in[2];
    const float* wq_b     = (const float*)d_in[3];
    const float* wkv_a    = (const float*)d_in[4];
    const float* kv_norm_w= (const float*)d_in[5];
    const float* wkv_b    = (const float*)d_in[6];
    const float* wo       = (const float*)d_in[7];
    const int*   amask    = (const int*)d_in[8];
    const int*   pos      = (const int*)d_in[9];
    float*       out      = (float*)d_out;

    cudaFuncSetAttribute(gemm3_k, cudaFuncAttributeMaxDynamicSharedMemorySize,
                         GEMM_SMEM);
    cudaFuncSetAttribute(flash_k, cudaFuncAttributeMaxDynamicSharedMemorySize,
                         FL_SMEM);

    float *qkv, *qf, *kvexp, *mb;
    bf16 *xh,*xl,*qlh,*qll,*qh,*ql,*kvh,*kvl,*kh,*kl,*vh,*vl,*ath,*atl;
    bf16 *wabh,*wabl,*wqbh,*wqbl,*wkvbh,*wkvbl,*woh,*wol;
    cudaGetSymbolAddress((void**)&qkv,  g_qkv);
    cudaGetSymbolAddress((void**)&qf,   g_q);
    cudaGetSymbolAddress((void**)&kvexp,g_kvexp);
    cudaGetSymbolAddress((void**)&mb,   g_mb);
    cudaGetSymbolAddress((void**)&xh, g_xh);   cudaGetSymbolAddress((void**)&xl, g_xl);
    cudaGetSymbolAddress((void**)&qlh,g_qlh);  cudaGetSymbolAddress((void**)&qll,g_qll);
    cudaGetSymbolAddress((void**)&qh, g_qh);   cudaGetSymbolAddress((void**)&ql, g_ql);
    cudaGetSymbolAddress((void**)&kvh,g_kvh);  cudaGetSymbolAddress((void**)&kvl,g_kvl);
    cudaGetSymbolAddress((void**)&kh, g_kh);   cudaGetSymbolAddress((void**)&kl, g_kl);
    cudaGetSymbolAddress((void**)&vh, g_vh);   cudaGetSymbolAddress((void**)&vl, g_vl);
    cudaGetSymbolAddress((void**)&ath,g_ath);  cudaGetSymbolAddress((void**)&atl,g_atl);
    cudaGetSymbolAddress((void**)&wabh,g_wabh); cudaGetSymbolAddress((void**)&wabl,g_wabl);
    cudaGetSymbolAddress((void**)&wqbh,g_wqbh); cudaGetSymbolAddress((void**)&wqbl,g_wqbl);
    cudaGetSymbolAddress((void**)&wkvbh,g_wkvbh); cudaGetSymbolAddress((void**)&wkvbl,g_wkvbl);
    cudaGetSymbolAddress((void**)&woh,g_woh);   cudaGetSymbolAddress((void**)&wol,g_wol);

    dim3 tb(32, 8);
    // weight transpose+split: wq_a -> rows [0,1536), wkv_a -> rows [1536,2112)
    wtsplit_k<<<dim3(48, 128), tb>>>(wq_a, wabh, wabl, 4096, 1536);
    wtsplit_k<<<dim3(18, 128), tb>>>(wkv_a, wabh + (size_t)1536 * 4096,
                                     wabl + (size_t)1536 * 4096, 4096, 576);
    wtsplit_k<<<dim3(192, 48), tb>>>(wq_b, wqbh, wqbl, 1536, 6144);
    wtsplit_k<<<dim3(256, 16), tb>>>(wkv_b, wkvbh, wkvbl, 512, 8192);
    wtsplit_k<<<dim3(128, 128), tb>>>(wo, woh, wol, 4096, 4096);
    split_k<<<32768, 256>>>(x, xh, xl, 2048ll * 4096);
    maskbias_k<<<8, 256>>>(amask, mb);

    // 1. merged down-proj: qkv = x @ [wq_a | wkv_a]   [2048, 2112]
    gemm3_k<<<dim3(17, 16, 1), 256, GEMM_SMEM>>>(xh, xl, wabh, wabl, qkv,
        2112, 4096, 4096, 4096, 2112, 0,0,0,0,0,0, 1, 0, 1.f);
    // 2. rmsnorms -> hi/lo
    rmsns_k<<<2048, 256>>>(qkv, q_norm_w, qlh, qll, 1536, 2112);
    rmsns_k<<<2048, 256>>>(qkv + 1536, kv_norm_w, kvh, kvl, 512, 2112);
    rope_kpe_k<<<256, 256>>>(qkv, pos);
    // 3. q = qlow @ wq_b
    gemm3_k<<<dim3(48, 16, 1), 256, GEMM_SMEM>>>(qlh, qll, wqbh, wqbl, qf,
        6144, 1536, 1536, 1536, 6144, 0,0,0,0,0,0, 1, 0, 1.f);
    rope_split_q_k<<<8192, 256>>>(qf, pos, qh, ql);
    // 4. kvexp = kv @ wkv_b
    gemm3_k<<<dim3(64, 16, 1), 256, GEMM_SMEM>>>(kvh, kvl, wkvbh, wkvbl, kvexp,
        8192, 512, 512, 512, 8192, 0,0,0,0,0,0, 1, 0, 1.f);
    // 5. per-head K/V gather (hi/lo planes)
    kgather_k<<<49152, 256>>>(kvexp, qkv, kh, kl);
    vgather_k<<<32768, 256>>>(kvexp, vh, vl);
    // 6. fused attention -> ath/atl
    flash_k<<<dim3(64, 8), 256, FL_SMEM>>>(qh, ql, kh, kl, vh, vl, mb, ath, atl);
    // 7. out = attn @ wo
    gemm3_k<<<dim3(32, 16, 1), 256, GEMM_SMEM>>>(ath, atl, woh, wol, out,
        4096, 4096, 4096, 4096, 4096, 0,0,0,0,0,0, 1, 0, 1.f);
}

// round 8
// speedup vs baseline: 1.6183x; 1.4193x over previous
#include <cuda_runtime.h>
#include <cuda_fp16.h>
#include <math.h>
#include <stdint.h>

typedef __half h16;
#define TT 1024
#define SCALE_QK 0.07216878364870323f

// ------------------------- device scratch (no cudaMalloc) -------------------
__device__ float g_qkv  [2048*2112];   // qlow | kv | k_pe
__device__ float g_q    [2048*6144];
__device__ float g_kvexp[2048*8192];
__device__ float g_mb   [2048];

__device__ h16 g_xh[2048*4096],  g_xl[2048*4096];
__device__ h16 g_qlh[2048*1536], g_qll[2048*1536];
__device__ h16 g_qh[2048*6144],  g_ql[2048*6144];
__device__ h16 g_kvh[2048*512],  g_kvl[2048*512];
__device__ h16 g_kh[64ll*1024*192], g_kl[64ll*1024*192];
__device__ h16 g_vh[64ll*1024*128], g_vl[64ll*1024*128];
__device__ h16 g_ath[2048*4096], g_atl[2048*4096];
__device__ h16 g_wab[2112*4096];          // [wq_a ; wkv_a] transposed, single plane
__device__ h16 g_wqb[6144*1536];
__device__ h16 g_wkvb[8192*512];
__device__ h16 g_wo[4096*4096];

// ------------------------------ PTX helpers (sm_80-safe) --------------------
__device__ __forceinline__ uint32_t smem_u32(const void* p) {
    uint32_t a;
    asm("{ .reg .u64 t; cvta.to.shared.u64 t, %1; cvt.u32.u64 %0, t; }"
        : "=r"(a) : "l"(p));
    return a;
}

#define LDSM4(r, a) asm volatile( \
    "ldmatrix.sync.aligned.m8n8.x4.shared.b16 {%0,%1,%2,%3}, [%4];" \
    : "=r"((r)[0]), "=r"((r)[1]), "=r"((r)[2]), "=r"((r)[3]) : "r"(a))

#define LDSM4T(r, a) asm volatile( \
    "ldmatrix.sync.aligned.m8n8.x4.trans.shared.b16 {%0,%1,%2,%3}, [%4];" \
    : "=r"((r)[0]), "=r"((r)[1]), "=r"((r)[2]), "=r"((r)[3]) : "r"(a))

#define MMAH(d, a, b0, b1) asm volatile( \
    "mma.sync.aligned.m16n8k16.row.col.f32.f16.f16.f32 " \
    "{%0,%1,%2,%3},{%4,%5,%6,%7},{%8,%9},{%0,%1,%2,%3};" \
    : "+f"((d)[0]), "+f"((d)[1]), "+f"((d)[2]), "+f"((d)[3]) \
    : "r"((a)[0]), "r"((a)[1]), "r"((a)[2]), "r"((a)[3]), "r"(b0), "r"(b1))

#define MMAH_P(d, a0, a1, a2, a3, b0, b1) asm volatile( \
    "mma.sync.aligned.m16n8k16.row.col.f32.f16.f16.f32 " \
    "{%0,%1,%2,%3},{%4,%5,%6,%7},{%8,%9},{%0,%1,%2,%3};" \
    : "+f"((d)[0]), "+f"((d)[1]), "+f"((d)[2]), "+f"((d)[3]) \
    : "r"(a0), "r"(a1), "r"(a2), "r"(a3), "r"(b0), "r"(b1))

__device__ __forceinline__ void cpa16(uint32_t dst, const void* src, int valid) {
    int sz = valid ? 16 : 0;
    asm volatile("cp.async.cg.shared.global [%0], [%1], 16, %2;"
                 :: "r"(dst), "l"(src), "r"(sz));
}
#define CP_COMMIT() asm volatile("cp.async.commit_group;" ::: "memory")
#define CP_WAIT(n)  asm volatile("cp.async.wait_group %0;" :: "n"(n) : "memory")

__device__ __forceinline__ uint32_t packh(float a, float b) {
    __half2 t = __floats2half2_rn(a, b);
    return *reinterpret_cast<uint32_t*>(&t);
}

// Load one 128x32 h16 plane into swizzled smem (rows of 64B).
__device__ __forceinline__ void load_plane(uint32_t sb, const h16* __restrict__ G,
                                           int row0, int ld, int k0, int tid,
                                           int nvalid) {
#pragma unroll
    for (int i = 0; i < 2; i++) {
        int idx = tid * 2 + i;
        int r = idx >> 2, c = idx & 3;
        uint32_t dst = sb + r * 64 + ((c ^ ((r >> 1) & 3)) << 4);
        int ok = r < nvalid;
        const h16* src = G + (size_t)(row0 + (ok ? r : 0)) * ld + k0 + c * 8;
        cpa16(dst, src, ok);
    }
}

// Load one 64x32 h16 subplane (256 threads -> 1 line each).
__device__ __forceinline__ void load_plane64(uint32_t sb, const h16* __restrict__ G,
                                             int ld, int k0, int tid) {
    int r = tid >> 2, c = tid & 3;
    uint32_t dst = sb + r * 64 + ((c ^ ((r >> 1) & 3)) << 4);
    cpa16(dst, G + (size_t)r * ld + k0 + c * 8, 1);
}

// Load one 64x128 h16 V plane (rows of 256B) with row-xor swizzle.
__device__ __forceinline__ void load_v(uint32_t sb, const h16* __restrict__ G,
                                       int tid) {
#pragma unroll
    for (int i = 0; i < 4; i++) {
        int idx = i * 256 + tid;
        int r = idx >> 4, c = idx & 15;
        uint32_t dst = sb + r * 256 + ((c ^ (r & 7)) << 4);
        cpa16(dst, G + (size_t)r * 128 + c * 8, 1);
    }
}

// ---------------------------------------------------------------------------
// 2-pass split-fp16 HMMA GEMM body: C[128 rows @m0, 128 cols @n0]
//   = (Ah+Al)[M,K] @ B[N,K]^T   (A split fp16, B single fp16)
// 3-stage cp.async pipeline, 24KB/stage.
// ---------------------------------------------------------------------------
#define GEMM2_SMEM 73728
__device__ __forceinline__ void gemm2_body(
    const h16* __restrict__ Ah, const h16* __restrict__ Al,
    const h16* __restrict__ B, float* __restrict__ C,
    int N, int K, int lda, int ldb, int ldc, int m0, int n0, char* smem)
{
    int tid = threadIdx.x, lane = tid & 31, wid = tid >> 5;
    int mw = (wid & 1) * 64, nw = (wid >> 1) * 32;
    uint32_t s0 = smem_u32(smem);
    int nvB = min(128, N - n0);
    int nch = K >> 5;

    uint32_t rowA[4]; int sA[4];
#pragma unroll
    for (int mt = 0; mt < 4; mt++) {
        int r = mw + mt * 16 + (lane & 15);
        rowA[mt] = r * 64; sA[mt] = (r >> 1) & 3;
    }
    uint32_t rowB[2]; int sB[2];
#pragma unroll
    for (int h2 = 0; h2 < 2; h2++) {
        int r = nw + h2 * 16 + (lane & 7) + ((lane >> 4) << 3);
        rowB[h2] = r * 64; sB[h2] = (r >> 1) & 3;
    }
    int aCk = (lane >> 4) & 1, bCk = (lane >> 3) & 1;

    float acc[4][4][4];
#pragma unroll
    for (int i = 0; i < 4; i++)
#pragma unroll
        for (int j = 0; j < 4; j++)
#pragma unroll
            for (int r = 0; r < 4; r++) acc[i][j][r] = 0.f;

    // prologue: stages 0,1
    load_plane(s0,         Ah, m0, lda, 0, tid, 128);
    load_plane(s0 + 8192,  Al, m0, lda, 0, tid, 128);
    load_plane(s0 + 16384, B,  n0, ldb, 0, tid, nvB);
    CP_COMMIT();
    if (nch > 1) {
        uint32_t sb = s0 + 24576;
        load_plane(sb,         Ah, m0, lda, 32, tid, 128);
        load_plane(sb + 8192,  Al, m0, lda, 32, tid, 128);
        load_plane(sb + 16384, B,  n0, ldb, 32, tid, nvB);
    }
    CP_COMMIT();

    for (int c = 0; c < nch; c++) {
        CP_WAIT(1);
        __syncthreads();
        if (c + 2 < nch) {
            uint32_t sb = s0 + ((c + 2) % 3) * 24576;
            int k0 = (c + 2) * 32;
            load_plane(sb,         Ah, m0, lda, k0, tid, 128);
            load_plane(sb + 8192,  Al, m0, lda, k0, tid, 128);
            load_plane(sb + 16384, B,  n0, ldb, k0, tid, nvB);
        }
        CP_COMMIT();

        uint32_t base = s0 + (c % 3) * 24576;
        uint32_t pAh = base, pAl = base + 8192, pB = base + 16384;
#pragma unroll
        for (int ks = 0; ks < 2; ks++) {
            uint32_t af[4][4], bf[2][4];
            int cA = ks * 2 + aCk, cB = ks * 2 + bCk;
#pragma unroll
            for (int mt = 0; mt < 4; mt++)
                LDSM4(af[mt], pAh + rowA[mt] + (uint32_t)((cA ^ sA[mt]) << 4));
#pragma unroll
            for (int h2 = 0; h2 < 2; h2++)
                LDSM4(bf[h2], pB + rowB[h2] + (uint32_t)((cB ^ sB[h2]) << 4));
#pragma unroll
            for (int mt = 0; mt < 4; mt++)
#pragma unroll
                for (int nt = 0; nt < 4; nt++)
                    MMAH(acc[mt][nt], af[mt],
                         bf[nt >> 1][(nt & 1) * 2], bf[nt >> 1][(nt & 1) * 2 + 1]);
#pragma unroll
            for (int mt = 0; mt < 4; mt++)
                LDSM4(af[mt], pAl + rowA[mt] + (uint32_t)((cA ^ sA[mt]) << 4));
#pragma unroll
            for (int mt = 0; mt < 4; mt++)
#pragma unroll
                for (int nt = 0; nt < 4; nt++)
                    MMAH(acc[mt][nt], af[mt],
                         bf[nt >> 1][(nt & 1) * 2], bf[nt >> 1][(nt & 1) * 2 + 1]);
        }
    }

#pragma unroll
    for (int mt = 0; mt < 4; mt++) {
        int r0 = m0 + mw + mt * 16 + (lane >> 2);
#pragma unroll
        for (int nt = 0; nt < 4; nt++) {
            int col = n0 + nw + nt * 8 + 2 * (lane & 3);
            if (col < N) {
                float2 v0 = make_float2(acc[mt][nt][0], acc[mt][nt][1]);
                float2 v1 = make_float2(acc[mt][nt][2], acc[mt][nt][3]);
                *(float2*)(C + (size_t)r0 * ldc + col) = v0;
                *(float2*)(C + (size_t)(r0 + 8) * ldc + col) = v1;
            }
        }
    }
}

__global__ void __launch_bounds__(256, 2) gemm2_k(
    const h16* __restrict__ Ah, const h16* __restrict__ Al,
    const h16* __restrict__ B, float* __restrict__ C,
    int N, int K, int lda, int ldb, int ldc)
{
    extern __shared__ char smem[];
    gemm2_body(Ah, Al, B, C, N, K, lda, ldb, ldc,
               blockIdx.y * 128, blockIdx.x * 128, smem);
}

__global__ void __launch_bounds__(256, 2) gemm2_dual_k(
    const h16* __restrict__ A0h, const h16* __restrict__ A0l,
    const h16* __restrict__ B0, float* __restrict__ C0,
    int N0, int K0, int lda0, int ldb0, int ldc0,
    const h16* __restrict__ A1h, const h16* __restrict__ A1l,
    const h16* __restrict__ B1, float* __restrict__ C1,
    int N1, int K1, int lda1, int ldb1, int ldc1, int nx0)
{
    extern __shared__ char smem[];
    if ((int)blockIdx.x < nx0)
        gemm2_body(A0h, A0l, B0, C0, N0, K0, lda0, ldb0, ldc0,
                   blockIdx.y * 128, blockIdx.x * 128, smem);
    else
        gemm2_body(A1h, A1l, B1, C1, N1, K1, lda1, ldb1, ldc1,
                   blockIdx.y * 128, (blockIdx.x - nx0) * 128, smem);
}

// ---------------------------------------------------------------------------
// Fused flash attention (fp16): per CTA one (bh, 128-query tile).
// QK^T 3-pass (Q hi/lo, K hi/lo, drop ll); online softmax;
// PV 2-pass (P single, V hi/lo). Emits hi/lo fp16 output planes.
// ---------------------------------------------------------------------------
#define FL_SMEM 229376
__global__ void __launch_bounds__(256, 1) flash_k(
    const h16* __restrict__ qh_, const h16* __restrict__ ql_,
    const h16* __restrict__ kh_, const h16* __restrict__ kl_,
    const h16* __restrict__ vh_, const h16* __restrict__ vl_,
    const float* __restrict__ mb,
    h16* __restrict__ ath, h16* __restrict__ atl)
{
    extern __shared__ char smem[];
    int bh = blockIdx.x, b = bh >> 5, h = bh & 31;
    int qi = 7 - blockIdx.y;
    int t0 = qi * 128;
    int tid = threadIdx.x, lane = tid & 31, wid = tid >> 5;
    int wrow = wid * 16;

    uint32_t S0 = smem_u32(smem);
    uint32_t Qh = S0, Ql = S0 + 49152;
    uint32_t Kb = S0 + 98304;
    uint32_t Vb = S0 + 196608;

    const h16* Qgh = qh_ + ((size_t)(b * 1024 + t0)) * 6144 + h * 192;
    const h16* Qgl = ql_ + ((size_t)(b * 1024 + t0)) * 6144 + h * 192;
    const h16* Kgh = kh_ + (size_t)bh * 1024 * 192;
    const h16* Kgl = kl_ + (size_t)bh * 1024 * 192;
    const h16* Vgh = vh_ + (size_t)bh * 1024 * 128;
    const h16* Vgl = vl_ + (size_t)bh * 1024 * 128;
    const float* mbb = mb + b * 1024;

#pragma unroll
    for (int sp = 0; sp < 6; sp++) {
        load_plane(Qh + sp * 8192, Qgh, 0, 6144, sp * 32, tid, 128);
        load_plane(Ql + sp * 8192, Qgl, 0, 6144, sp * 32, tid, 128);
    }
#pragma unroll
    for (int sp = 0; sp < 6; sp++) {
        load_plane64(Kb + sp * 4096,         Kgh, 192, sp * 32, tid);
        load_plane64(Kb + 24576 + sp * 4096, Kgl, 192, sp * 32, tid);
    }
    CP_COMMIT();

    int nst = (t0 + 128) >> 6;
    float m0 = -1e30f, m1 = -1e30f, l0 = 0.f, l1 = 0.f;
    float O[16][4];
#pragma unroll
    for (int i = 0; i < 16; i++)
#pragma unroll
        for (int j = 0; j < 4; j++) O[i][j] = 0.f;

    int rA = wrow + (lane & 15);
    int swA = (rA >> 1) & 3;
    int rB[4], swB[4];
#pragma unroll
    for (int g = 0; g < 4; g++) {
        rB[g] = g * 16 + (lane & 7) + ((lane >> 4) << 3);
        swB[g] = (rB[g] >> 1) & 3;
    }
    int aSel = (lane >> 4) & 1, bSel = (lane >> 3) & 1;
    int trow = t0 + wrow + (lane >> 2);

    for (int i = 0; i < nst; i++) {
        __syncthreads();
        load_v(Vb,          Vgh + (size_t)i * 64 * 128, tid);
        load_v(Vb + 16384,  Vgl + (size_t)i * 64 * 128, tid);
        CP_COMMIT();
        if (i + 1 < nst) {
            uint32_t Ks = Kb + ((i + 1) & 1) * 49152;
            const h16* gh = Kgh + (size_t)(i + 1) * 64 * 192;
            const h16* gl = Kgl + (size_t)(i + 1) * 64 * 192;
#pragma unroll
            for (int sp = 0; sp < 6; sp++) {
                load_plane64(Ks + sp * 4096,         gh, 192, sp * 32, tid);
                load_plane64(Ks + 24576 + sp * 4096, gl, 192, sp * 32, tid);
            }
        }
        CP_COMMIT();

        CP_WAIT(2);
        __syncthreads();

        // ---- S = QK^T (3 passes: QhKh, QhKl, QlKh) ----
        float S[8][4];
#pragma unroll
        for (int nt = 0; nt < 8; nt++)
#pragma unroll
            for (int j = 0; j < 4; j++) S[nt][j] = 0.f;

        uint32_t Ks = Kb + (i & 1) * 49152;
#pragma unroll
        for (int ks = 0; ks < 12; ks++) {
            int sp = ks >> 1;
            int cA = ((ks & 1) << 1) + aSel;
            int cB = ((ks & 1) << 1) + bSel;
            uint32_t ah[4], bhf[4][4], blf[4][4];
            LDSM4(ah, Qh + sp * 8192 + rA * 64 + (uint32_t)((cA ^ swA) << 4));
#pragma unroll
            for (int g = 0; g < 4; g++)
                LDSM4(bhf[g], Ks + sp * 4096 + rB[g] * 64 + (uint32_t)((cB ^ swB[g]) << 4));
#pragma unroll
            for (int g = 0; g < 4; g++) {
                MMAH(S[2 * g], ah, bhf[g][0], bhf[g][1]);
                MMAH(S[2 * g + 1], ah, bhf[g][2], bhf[g][3]);
            }
#pragma unroll
            for (int g = 0; g < 4; g++)
                LDSM4(blf[g], Ks + 24576 + sp * 4096 + rB[g] * 64 + (uint32_t)((cB ^ swB[g]) << 4));
#pragma unroll
            for (int g = 0; g < 4; g++) {
                MMAH(S[2 * g], ah, blf[g][0], blf[g][1]);
                MMAH(S[2 * g + 1], ah, blf[g][2], blf[g][3]);
            }
            LDSM4(ah, Ql + sp * 8192 + rA * 64 + (uint32_t)((cA ^ swA) << 4));
#pragma unroll
            for (int g = 0; g < 4; g++) {
                MMAH(S[2 * g], ah, bhf[g][0], bhf[g][1]);
                MMAH(S[2 * g + 1], ah, bhf[g][2], bhf[g][3]);
            }
        }

        // ---- online softmax ----
        int s0i = i * 64;
        float mx0 = -1e30f, mx1 = -1e30f;
#pragma unroll
        for (int nt = 0; nt < 8; nt++) {
            int sb0 = s0i + nt * 8 + ((lane & 3) << 1);
            float bias0 = mbb[sb0], bias1 = mbb[sb0 + 1];
            float v0 = S[nt][0] * SCALE_QK + bias0; if (sb0     > trow)     v0 = -1e30f;
            float v1 = S[nt][1] * SCALE_QK + bias1; if (sb0 + 1 > trow)     v1 = -1e30f;
            float v2 = S[nt][2] * SCALE_QK + bias0; if (sb0     > trow + 8) v2 = -1e30f;
            float v3 = S[nt][3] * SCALE_QK + bias1; if (sb0 + 1 > trow + 8) v3 = -1e30f;
            S[nt][0] = v0; S[nt][1] = v1; S[nt][2] = v2; S[nt][3] = v3;
            mx0 = fmaxf(mx0, fmaxf(v0, v1));
            mx1 = fmaxf(mx1, fmaxf(v2, v3));
        }
        mx0 = fmaxf(mx0, __shfl_xor_sync(0xffffffffu, mx0, 1));
        mx0 = fmaxf(mx0, __shfl_xor_sync(0xffffffffu, mx0, 2));
        mx1 = fmaxf(mx1, __shfl_xor_sync(0xffffffffu, mx1, 1));
        mx1 = fmaxf(mx1, __shfl_xor_sync(0xffffffffu, mx1, 2));
        float mn0 = fmaxf(m0, mx0), mn1 = fmaxf(m1, mx1);
        float cr0 = __expf(m0 - mn0), cr1 = __expf(m1 - mn1);
        float sum0 = 0.f, sum1 = 0.f;
#pragma unroll
        for (int nt = 0; nt < 8; nt++) {
            S[nt][0] = __expf(S[nt][0] - mn0);
            S[nt][1] = __expf(S[nt][1] - mn0);
            S[nt][2] = __expf(S[nt][2] - mn1);
            S[nt][3] = __expf(S[nt][3] - mn1);
            sum0 += S[nt][0] + S[nt][1];
            sum1 += S[nt][2] + S[nt][3];
        }
        sum0 += __shfl_xor_sync(0xffffffffu, sum0, 1);
        sum0 += __shfl_xor_sync(0xffffffffu, sum0, 2);
        sum1 += __shfl_xor_sync(0xffffffffu, sum1, 1);
        sum1 += __shfl_xor_sync(0xffffffffu, sum1, 2);
        l0 = l0 * cr0 + sum0;  l1 = l1 * cr1 + sum1;
        m0 = mn0;  m1 = mn1;
#pragma unroll
        for (int nd = 0; nd < 16; nd++) {
            O[nd][0] *= cr0; O[nd][1] *= cr0;
            O[nd][2] *= cr1; O[nd][3] *= cr1;
        }

        CP_WAIT(1);
        __syncthreads();

        // ---- O += P @ V (2 passes: P·Vh + P·Vl) ----
        int rV = (lane & 15);
#pragma unroll
        for (int kc = 0; kc < 4; kc++) {
            uint32_t phi[4];
#pragma unroll
            for (int j = 0; j < 2; j++) {
                int nt = 2 * kc + j;
                phi[2 * j]     = packh(S[nt][0], S[nt][1]);
                phi[2 * j + 1] = packh(S[nt][2], S[nt][3]);
            }
            int row = kc * 16 + rV;
            int sw = row & 7;
            uint32_t rbase = (uint32_t)row * 256;
            int cgrp = (lane >> 4) << 3;
#pragma unroll
            for (int g = 0; g < 8; g++) {
                int cch = (((g << 4) + cgrp) >> 3) ^ sw;
                uint32_t v4[4];
                LDSM4T(v4, Vb + rbase + (uint32_t)(cch << 4));
                MMAH_P(O[2 * g],     phi[0], phi[1], phi[2], phi[3], v4[0], v4[1]);
                MMAH_P(O[2 * g + 1], phi[0], phi[1], phi[2], phi[3], v4[2], v4[3]);
                LDSM4T(v4, Vb + 16384 + rbase + (uint32_t)(cch << 4));
                MMAH_P(O[2 * g],     phi[0], phi[1], phi[2], phi[3], v4[0], v4[1]);
                MMAH_P(O[2 * g + 1], phi[0], phi[1], phi[2], phi[3], v4[2], v4[3]);
            }
        }
    }

    // ---- epilogue: O / l -> hi/lo fp16 planes ----
    float inv0 = 1.f / l0, inv1 = 1.f / l1;
    size_t row0 = ((size_t)(b * 1024) + trow) * 4096 + h * 128;
    size_t row1 = row0 + (size_t)8 * 4096;
    int dcol = (lane & 3) * 2;
#pragma unroll
    for (int nd = 0; nd < 16; nd++) {
        float o0 = O[nd][0] * inv0, o1 = O[nd][1] * inv0;
        float o2 = O[nd][2] * inv1, o3 = O[nd][3] * inv1;
        float h0 = __half2float(__float2half_rn(o0));
        float h1 = __half2float(__float2half_rn(o1));
        float h2 = __half2float(__float2half_rn(o2));
        float h3 = __half2float(__float2half_rn(o3));
        int c = nd * 8 + dcol;
        *(uint32_t*)(ath + row0 + c) = packh(o0, o1);
        *(uint32_t*)(atl + row0 + c) = packh(o0 - h0, o1 - h1);
        *(uint32_t*)(ath + row1 + c) = packh(o2, o3);
        *(uint32_t*)(atl + row1 + c) = packh(o2 - h2, o3 - h3);
    }
}

// ------------------------- conversion / elementwise -------------------------
__device__ __forceinline__ void split1h(float v, h16* h, h16* l, size_t i) {
    h16 hi = __float2half_rn(v);
    h[i] = hi;
    l[i] = __float2half_rn(v - __half2float(hi));
}

__global__ void split_k(const float* __restrict__ x, h16* __restrict__ h,
                        h16* __restrict__ l, long n) {
    long i = blockIdx.x * 256ll + threadIdx.x;
    if (i < n) split1h(x[i], h, l, i);
}

// Merged weight transpose+convert (single fp16 plane) for all 5 weights.
__global__ void wtconv_k(const float* __restrict__ wq_a,
                         const float* __restrict__ wkv_a,
                         const float* __restrict__ wq_b,
                         const float* __restrict__ wkv_b,
                         const float* __restrict__ wo,
                         h16* __restrict__ wab, h16* __restrict__ wqb,
                         h16* __restrict__ wkvb, h16* __restrict__ wot)
{
    __shared__ float t[32][33];
    int bx = blockIdx.x;
    const float* W; h16* T; int K, N, nx, tIdx, rowOff;
    if (bx < 6144)       { W = wq_a;  T = wab;  K = 4096; N = 1536; nx = 48;  tIdx = bx;         rowOff = 0; }
    else if (bx < 8448)  { W = wkv_a; T = wab;  K = 4096; N = 576;  nx = 18;  tIdx = bx - 6144;  rowOff = 1536; }
    else if (bx < 17664) { W = wq_b;  T = wqb;  K = 1536; N = 6144; nx = 192; tIdx = bx - 8448;  rowOff = 0; }
    else if (bx < 21760) { W = wkv_b; T = wkvb; K = 512;  N = 8192; nx = 256; tIdx = bx - 17664; rowOff = 0; }
    else                 { W = wo;    T = wot;  K = 4096; N = 4096; nx = 128; tIdx = bx - 21760; rowOff = 0; }
    int n0 = (tIdx % nx) * 32, k0 = (tIdx / nx) * 32;
    int tx = threadIdx.x, ty = threadIdx.y;
#pragma unroll
    for (int j = 0; j < 32; j += 8)
        t[ty + j][tx] = W[(size_t)(k0 + ty + j) * N + n0 + tx];
    __syncthreads();
#pragma unroll
    for (int j = 0; j < 32; j += 8)
        T[(size_t)(rowOff + n0 + ty + j) * K + k0 + tx] =
            __float2half_rn(t[tx][ty + j]);
}

// Merged rmsnorm (q rows then kv rows) -> hi/lo fp16 planes.
__global__ void rmsns2_k(const float* __restrict__ qkv,
                         const float* __restrict__ qw,
                         const float* __restrict__ kvw,
                         h16* __restrict__ qlh, h16* __restrict__ qll,
                         h16* __restrict__ kvh, h16* __restrict__ kvl)
{
    __shared__ float red[256];
    int rb = blockIdx.x;
    int isq = rb < 2048;
    long row = isq ? rb : rb - 2048;
    int n = isq ? 1536 : 512;
    const float* p = qkv + row * 2112 + (isq ? 0 : 1536);
    const float* w = isq ? qw : kvw;
    h16* oh = (isq ? qlh : kvh) + row * n;
    h16* ol = (isq ? qll : kvl) + row * n;
    int tid = threadIdx.x;
    float ss = 0.f;
    for (int c = tid; c < n; c += 256) { float v = p[c]; ss += v * v; }
    red[tid] = ss; __syncthreads();
    for (int s = 128; s > 0; s >>= 1) {
        if (tid < s) red[tid] += red[tid + s];
        __syncthreads();
    }
    float r = rsqrtf(red[0] / (float)n + 1e-6f);
    for (int c = tid; c < n; c += 256) {
        float v = p[c] * r * w[c];
        h16 hi = __float2half_rn(v);
        oh[c] = hi;
        ol[c] = __float2half_rn(v - __half2float(hi));
    }
}

// fused rope + split for q: one warp per (token, head)
__global__ void rope_split_q_k(const float* __restrict__ qf,
                               const int* __restrict__ pos,
                               h16* __restrict__ qh, h16* __restrict__ ql) {
    int w = blockIdx.x * 8 + (threadIdx.x >> 5);
    int lane = threadIdx.x & 31;
    int bt = w >> 5, h = w & 31;
    const float* base = qf + (size_t)bt * 6144 + h * 192;
    size_t ob = (size_t)bt * 6144 + h * 192;
#pragma unroll
    for (int j = 0; j < 4; j++)
        split1h(base[lane + j * 32], qh, ql, ob + lane + j * 32);
    float p = (float)pos[bt];
    float invf = powf(10000.f, -(float)lane / 32.f);
    float sn, cs; sincosf(p * invf, &sn, &cs);
    float x1 = base[128 + lane], x2 = base[160 + lane];
    split1h(x1 * cs - x2 * sn, qh, ql, ob + 128 + lane);
    split1h(x1 * sn + x2 * cs, qh, ql, ob + 160 + lane);
}

// rope on shared k_pe: qkv cols [2048,2112)
__global__ void rope_kpe_k(float* __restrict__ qkv, const int* __restrict__ pos) {
    int gid = blockIdx.x * 256 + threadIdx.x;
    int i = gid & 31, bt = gid >> 5;
    float p = (float)pos[bt];
    float invf = powf(10000.f, -(float)i / 32.f);
    float sn, cs; sincosf(p * invf, &sn, &cs);
    float* base = qkv + (size_t)bt * 2112 + 2048;
    float x1 = base[i], x2 = base[32 + i];
    base[i]      = x1 * cs - x2 * sn;
    base[32 + i] = x1 * sn + x2 * cs;
}

// Merged K+V gather -> hi/lo fp16 planes.
__global__ void kvgather_k(const float* __restrict__ kvexp,
                           const float* __restrict__ qkv,
                           h16* __restrict__ kh, h16* __restrict__ kl,
                           h16* __restrict__ vh, h16* __restrict__ vl) {
    long gid = blockIdx.x * 256ll + threadIdx.x;   // 64*1024*(192+128)
    const long NK = 64ll * 1024 * 192;
    if (gid < NK) {
        int k = (int)(gid % 192);
        long r = gid / 192;
        int s = (int)(r & 1023), bh = (int)(r >> 10);
        int b = bh >> 5, h = bh & 31;
        float v = (k < 128)
            ? kvexp[((size_t)b * 1024 + s) * 8192 + h * 256 + k]
            : qkv[((size_t)b * 1024 + s) * 2112 + 2048 + (k - 128)];
        split1h(v, kh, kl, gid);
    } else {
        long g2 = gid - NK;
        int d = (int)(g2 & 127);
        long r = g2 >> 7;
        int s = (int)(r & 1023), bh = (int)(r >> 10);
        int b = bh >> 5, h = bh & 31;
        float v = kvexp[((size_t)b * 1024 + s) * 8192 + h * 256 + 128 + d];
        split1h(v, vh, vl, g2);
    }
}

__global__ void maskbias_k(const int* __restrict__ amask, float* __restrict__ mb) {
    int i = blockIdx.x * 256 + threadIdx.x;
    if (i < 2048) mb[i] = amask[i] ? 0.f : -1e30f;
}

// ---------------------------------------------------------------------------
extern "C" void kernel_launch(void* const* d_in, const int* in_sizes, int n_in,
                              void* d_out, int out_size)
{
    const float* x        = (const float*)d_in[0];
    const float* wq_a     = (const float*)d_in[1];
    const float* q_norm_w = (const float*)d_in[2];
    const float* wq_b     = (const float*)d_in[3];
    const float* wkv_a    = (const float*)d_in[4];
    const float* kv_norm_w= (const float*)d_in[5];
    const float* wkv_b    = (const float*)d_in[6];
    const float* wo       = (const float*)d_in[7];
    const int*   amask    = (const int*)d_in[8];
    const int*   pos      = (const int*)d_in[9];
    float*       out      = (float*)d_out;

    cudaFuncSetAttribute(gemm2_k, cudaFuncAttributeMaxDynamicSharedMemorySize,
                         GEMM2_SMEM);
    cudaFuncSetAttribute(gemm2_dual_k, cudaFuncAttributeMaxDynamicSharedMemorySize,
                         GEMM2_SMEM);
    cudaFuncSetAttribute(flash_k, cudaFuncAttributeMaxDynamicSharedMemorySize,
                         FL_SMEM);

    float *qkv, *qf, *kvexp, *mb;
    h16 *xh,*xl,*qlh,*qll,*qh,*ql,*kvh,*kvl,*kh,*kl,*vh,*vl,*ath,*atl;
    h16 *wab,*wqb,*wkvb,*wot;
    cudaGetSymbolAddress((void**)&qkv,  g_qkv);
    cudaGetSymbolAddress((void**)&qf,   g_q);
    cudaGetSymbolAddress((void**)&kvexp,g_kvexp);
    cudaGetSymbolAddress((void**)&mb,   g_mb);
    cudaGetSymbolAddress((void**)&xh, g_xh);   cudaGetSymbolAddress((void**)&xl, g_xl);
    cudaGetSymbolAddress((void**)&qlh,g_qlh);  cudaGetSymbolAddress((void**)&qll,g_qll);
    cudaGetSymbolAddress((void**)&qh, g_qh);   cudaGetSymbolAddress((void**)&ql, g_ql);
    cudaGetSymbolAddress((void**)&kvh,g_kvh);  cudaGetSymbolAddress((void**)&kvl,g_kvl);
    cudaGetSymbolAddress((void**)&kh, g_kh);   cudaGetSymbolAddress((void**)&kl, g_kl);
    cudaGetSymbolAddress((void**)&vh, g_vh);   cudaGetSymbolAddress((void**)&vl, g_vl);
    cudaGetSymbolAddress((void**)&ath,g_ath);  cudaGetSymbolAddress((void**)&atl,g_atl);
    cudaGetSymbolAddress((void**)&wab,g_wab);  cudaGetSymbolAddress((void**)&wqb,g_wqb);
    cudaGetSymbolAddress((void**)&wkvb,g_wkvb); cudaGetSymbolAddress((void**)&wot,g_wo);

    // prologue conversions
    wtconv_k<<<38144, dim3(32, 8)>>>(wq_a, wkv_a, wq_b, wkv_b, wo,
                                     wab, wqb, wkvb, wot);
    split_k<<<32768, 256>>>(x, xh, xl, 2048ll * 4096);
    maskbias_k<<<8, 256>>>(amask, mb);

    // 1. merged down-proj: qkv = x @ [wq_a | wkv_a]   [2048, 2112]
    gemm2_k<<<dim3(17, 16), 256, GEMM2_SMEM>>>(xh, xl, wab, qkv,
        2112, 4096, 4096, 4096, 2112);
    // 2. rmsnorms -> hi/lo; rope k_pe
    rmsns2_k<<<4096, 256>>>(qkv, q_norm_w, kv_norm_w, qlh, qll, kvh, kvl);
    rope_kpe_k<<<256, 256>>>(qkv, pos);
    // 3. dual up-proj: q = qlow @ wq_b ; kvexp = kv @ wkv_b
    gemm2_dual_k<<<dim3(112, 16), 256, GEMM2_SMEM>>>(
        qlh, qll, wqb, qf,    6144, 1536, 1536, 1536, 6144,
        kvh, kvl, wkvb, kvexp, 8192, 512, 512, 512, 8192, 48);
    rope_split_q_k<<<8192, 256>>>(qf, pos, qh, ql);
    // 4. merged K/V gather
    kvgather_k<<<81920, 256>>>(kvexp, qkv, kh, kl, vh, vl);
    // 5. fused attention -> ath/atl
    flash_k<<<dim3(64, 8), 256, FL_SMEM>>>(qh, ql, kh, kl, vh, vl, mb, ath, atl);
    // 6. out = attn @ wo
    gemm2_k<<<dim3(32, 16), 256, GEMM2_SMEM>>>(ath, atl, wot, out,
        4096, 4096, 4096, 4096, 4096);
}

// round 9
// speedup vs baseline: 1.6630x; 1.0276x over previous
#include <cuda_runtime.h>
#include <cuda_fp16.h>
#include <math.h>
#include <stdint.h>

typedef __half h16;
#define TT 1024
#define SCALE_QK 0.07216878364870323f

// ------------------------- device scratch (no cudaMalloc) -------------------
__device__ float g_qkv  [2048*2112];   // qlow | kv | k_pe(fp32, pre-rope)
__device__ float g_mb   [2048];

__device__ h16 g_xh[2048*4096],  g_xl[2048*4096];
__device__ h16 g_qlh[2048*1536], g_qll[2048*1536];
__device__ h16 g_qh[2048*6144],  g_ql[2048*6144];
__device__ h16 g_kvh[2048*512],  g_kvl[2048*512];
__device__ h16 g_kvexph[2048ll*8192], g_kvexpl[2048ll*8192];
__device__ h16 g_kpeh[2048*64],  g_kpel[2048*64];
__device__ h16 g_ath[2048*4096], g_atl[2048*4096];
__device__ h16 g_wab[2112*4096];
__device__ h16 g_wqb[6144*1536];
__device__ h16 g_wkvb[8192*512];
__device__ h16 g_wo[4096*4096];

// ------------------------------ PTX helpers (sm_80-safe) --------------------
__device__ __forceinline__ uint32_t smem_u32(const void* p) {
    uint32_t a;
    asm("{ .reg .u64 t; cvta.to.shared.u64 t, %1; cvt.u32.u64 %0, t; }"
        : "=r"(a) : "l"(p));
    return a;
}

#define LDSM4(r, a) asm volatile( \
    "ldmatrix.sync.aligned.m8n8.x4.shared.b16 {%0,%1,%2,%3}, [%4];" \
    : "=r"((r)[0]), "=r"((r)[1]), "=r"((r)[2]), "=r"((r)[3]) : "r"(a))

#define LDSM4T(r, a) asm volatile( \
    "ldmatrix.sync.aligned.m8n8.x4.trans.shared.b16 {%0,%1,%2,%3}, [%4];" \
    : "=r"((r)[0]), "=r"((r)[1]), "=r"((r)[2]), "=r"((r)[3]) : "r"(a))

#define MMAH(d, a, b0, b1) asm volatile( \
    "mma.sync.aligned.m16n8k16.row.col.f32.f16.f16.f32 " \
    "{%0,%1,%2,%3},{%4,%5,%6,%7},{%8,%9},{%0,%1,%2,%3};" \
    : "+f"((d)[0]), "+f"((d)[1]), "+f"((d)[2]), "+f"((d)[3]) \
    : "r"((a)[0]), "r"((a)[1]), "r"((a)[2]), "r"((a)[3]), "r"(b0), "r"(b1))

#define MMAH_P(d, a0, a1, a2, a3, b0, b1) asm volatile( \
    "mma.sync.aligned.m16n8k16.row.col.f32.f16.f16.f32 " \
    "{%0,%1,%2,%3},{%4,%5,%6,%7},{%8,%9},{%0,%1,%2,%3};" \
    : "+f"((d)[0]), "+f"((d)[1]), "+f"((d)[2]), "+f"((d)[3]) \
    : "r"(a0), "r"(a1), "r"(a2), "r"(a3), "r"(b0), "r"(b1))

__device__ __forceinline__ void cpa16(uint32_t dst, const void* src, int valid) {
    int sz = valid ? 16 : 0;
    asm volatile("cp.async.cg.shared.global [%0], [%1], 16, %2;"
                 :: "r"(dst), "l"(src), "r"(sz));
}
#define CP_COMMIT() asm volatile("cp.async.commit_group;" ::: "memory")
#define CP_WAIT(n)  asm volatile("cp.async.wait_group %0;" :: "n"(n) : "memory")

__device__ __forceinline__ uint32_t packh(float a, float b) {
    __half2 t = __floats2half2_rn(a, b);
    return *reinterpret_cast<uint32_t*>(&t);
}

// Load one 128x32 h16 plane into swizzled smem (rows of 64B).
__device__ __forceinline__ void load_plane(uint32_t sb, const h16* __restrict__ G,
                                           int row0, int ld, int k0, int tid,
                                           int nvalid) {
#pragma unroll
    for (int i = 0; i < 2; i++) {
        int idx = tid * 2 + i;
        int r = idx >> 2, c = idx & 3;
        uint32_t dst = sb + r * 64 + ((c ^ ((r >> 1) & 3)) << 4);
        int ok = r < nvalid;
        const h16* src = G + (size_t)(row0 + (ok ? r : 0)) * ld + k0 + c * 8;
        cpa16(dst, src, ok);
    }
}

// Load one 64x32 h16 subplane (256 threads -> 1 line each). G pre-offset.
__device__ __forceinline__ void load_plane64(uint32_t sb, const h16* __restrict__ G,
                                             int ld, int tid) {
    int r = tid >> 2, c = tid & 3;
    uint32_t dst = sb + r * 64 + ((c ^ ((r >> 1) & 3)) << 4);
    cpa16(dst, G + (size_t)r * ld + c * 8, 1);
}

// Load one 64x128 h16 V plane (rows of 256B) with row-xor swizzle; row stride ld.
__device__ __forceinline__ void load_v(uint32_t sb, const h16* __restrict__ G,
                                       int ld, int tid) {
#pragma unroll
    for (int i = 0; i < 4; i++) {
        int idx = i * 256 + tid;
        int r = idx >> 4, c = idx & 15;
        uint32_t dst = sb + r * 256 + ((c ^ (r & 7)) << 4);
        cpa16(dst, G + (size_t)r * ld + c * 8, 1);
    }
}

// ---------------------------------------------------------------------------
// 2-pass split-fp16 HMMA GEMM body. H16OUT=0: fp32 C; H16OUT=1: hi/lo planes.
// ---------------------------------------------------------------------------
#define GEMM2_SMEM 73728
template<int H16OUT>
__device__ __forceinline__ void gemm2_body(
    const h16* __restrict__ Ah, const h16* __restrict__ Al,
    const h16* __restrict__ B, float* __restrict__ C,
    h16* __restrict__ Ch, h16* __restrict__ Cl,
    int N, int K, int lda, int ldb, int ldc, int m0, int n0, char* smem)
{
    int tid = threadIdx.x, lane = tid & 31, wid = tid >> 5;
    int mw = (wid & 1) * 64, nw = (wid >> 1) * 32;
    uint32_t s0 = smem_u32(smem);
    int nvB = min(128, N - n0);
    int nch = K >> 5;

    uint32_t rowA[4]; int sA[4];
#pragma unroll
    for (int mt = 0; mt < 4; mt++) {
        int r = mw + mt * 16 + (lane & 15);
        rowA[mt] = r * 64; sA[mt] = (r >> 1) & 3;
    }
    uint32_t rowB[2]; int sB[2];
#pragma unroll
    for (int h2 = 0; h2 < 2; h2++) {
        int r = nw + h2 * 16 + (lane & 7) + ((lane >> 4) << 3);
        rowB[h2] = r * 64; sB[h2] = (r >> 1) & 3;
    }
    int aCk = (lane >> 4) & 1, bCk = (lane >> 3) & 1;

    float acc[4][4][4];
#pragma unroll
    for (int i = 0; i < 4; i++)
#pragma unroll
        for (int j = 0; j < 4; j++)
#pragma unroll
            for (int r = 0; r < 4; r++) acc[i][j][r] = 0.f;

    load_plane(s0,         Ah, m0, lda, 0, tid, 128);
    load_plane(s0 + 8192,  Al, m0, lda, 0, tid, 128);
    load_plane(s0 + 16384, B,  n0, ldb, 0, tid, nvB);
    CP_COMMIT();
    if (nch > 1) {
        uint32_t sb = s0 + 24576;
        load_plane(sb,         Ah, m0, lda, 32, tid, 128);
        load_plane(sb + 8192,  Al, m0, lda, 32, tid, 128);
        load_plane(sb + 16384, B,  n0, ldb, 32, tid, nvB);
    }
    CP_COMMIT();

    for (int c = 0; c < nch; c++) {
        CP_WAIT(1);
        __syncthreads();
        if (c + 2 < nch) {
            uint32_t sb = s0 + ((c + 2) % 3) * 24576;
            int k0 = (c + 2) * 32;
            load_plane(sb,         Ah, m0, lda, k0, tid, 128);
            load_plane(sb + 8192,  Al, m0, lda, k0, tid, 128);
            load_plane(sb + 16384, B,  n0, ldb, k0, tid, nvB);
        }
        CP_COMMIT();

        uint32_t base = s0 + (c % 3) * 24576;
        uint32_t pAh = base, pAl = base + 8192, pB = base + 16384;
#pragma unroll
        for (int ks = 0; ks < 2; ks++) {
            uint32_t af[4][4], bf[2][4];
            int cA = ks * 2 + aCk, cB = ks * 2 + bCk;
#pragma unroll
            for (int mt = 0; mt < 4; mt++)
                LDSM4(af[mt], pAh + rowA[mt] + (uint32_t)((cA ^ sA[mt]) << 4));
#pragma unroll
            for (int h2 = 0; h2 < 2; h2++)
                LDSM4(bf[h2], pB + rowB[h2] + (uint32_t)((cB ^ sB[h2]) << 4));
#pragma unroll
            for (int mt = 0; mt < 4; mt++)
#pragma unroll
                for (int nt = 0; nt < 4; nt++)
                    MMAH(acc[mt][nt], af[mt],
                         bf[nt >> 1][(nt & 1) * 2], bf[nt >> 1][(nt & 1) * 2 + 1]);
#pragma unroll
            for (int mt = 0; mt < 4; mt++)
                LDSM4(af[mt], pAl + rowA[mt] + (uint32_t)((cA ^ sA[mt]) << 4));
#pragma unroll
            for (int mt = 0; mt < 4; mt++)
#pragma unroll
                for (int nt = 0; nt < 4; nt++)
                    MMAH(acc[mt][nt], af[mt],
                         bf[nt >> 1][(nt & 1) * 2], bf[nt >> 1][(nt & 1) * 2 + 1]);
        }
    }

#pragma unroll
    for (int mt = 0; mt < 4; mt++) {
        int r0 = m0 + mw + mt * 16 + (lane >> 2);
#pragma unroll
        for (int nt = 0; nt < 4; nt++) {
            int col = n0 + nw + nt * 8 + 2 * (lane & 3);
            if (col < N) {
                if (H16OUT == 0) {
                    float2 v0 = make_float2(acc[mt][nt][0], acc[mt][nt][1]);
                    float2 v1 = make_float2(acc[mt][nt][2], acc[mt][nt][3]);
                    *(float2*)(C + (size_t)r0 * ldc + col) = v0;
                    *(float2*)(C + (size_t)(r0 + 8) * ldc + col) = v1;
                } else {
                    float a0 = acc[mt][nt][0], a1 = acc[mt][nt][1];
                    float a2 = acc[mt][nt][2], a3 = acc[mt][nt][3];
                    float h0 = __half2float(__float2half_rn(a0));
                    float h1 = __half2float(__float2half_rn(a1));
                    float h2f = __half2float(__float2half_rn(a2));
                    float h3 = __half2float(__float2half_rn(a3));
                    *(uint32_t*)(Ch + (size_t)r0 * ldc + col) = packh(a0, a1);
                    *(uint32_t*)(Cl + (size_t)r0 * ldc + col) = packh(a0 - h0, a1 - h1);
                    *(uint32_t*)(Ch + (size_t)(r0 + 8) * ldc + col) = packh(a2, a3);
                    *(uint32_t*)(Cl + (size_t)(r0 + 8) * ldc + col) = packh(a2 - h2f, a3 - h3);
                }
            }
        }
    }
}

__global__ void __launch_bounds__(256, 2) gemm2_k(
    const h16* __restrict__ Ah, const h16* __restrict__ Al,
    const h16* __restrict__ B, float* __restrict__ C,
    int N, int K, int lda, int ldb, int ldc)
{
    extern __shared__ char smem[];
    gemm2_body<0>(Ah, Al, B, C, nullptr, nullptr, N, K, lda, ldb, ldc,
                  blockIdx.y * 128, blockIdx.x * 128, smem);
}

__global__ void __launch_bounds__(256, 2) gemm2h_dual_k(
    const h16* __restrict__ A0h, const h16* __restrict__ A0l,
    const h16* __restrict__ B0, h16* __restrict__ C0h, h16* __restrict__ C0l,
    int N0, int K0, int lda0, int ldb0, int ldc0,
    const h16* __restrict__ A1h, const h16* __restrict__ A1l,
    const h16* __restrict__ B1, h16* __restrict__ C1h, h16* __restrict__ C1l,
    int N1, int K1, int lda1, int ldb1, int ldc1, int nx0)
{
    extern __shared__ char smem[];
    if ((int)blockIdx.x < nx0)
        gemm2_body<1>(A0h, A0l, B0, nullptr, C0h, C0l, N0, K0, lda0, ldb0, ldc0,
                      blockIdx.y * 128, blockIdx.x * 128, smem);
    else
        gemm2_body<1>(A1h, A1l, B1, nullptr, C1h, C1l, N1, K1, lda1, ldb1, ldc1,
                      blockIdx.y * 128, (blockIdx.x - nx0) * 128, smem);
}

// ---------------------------------------------------------------------------
// Fused flash attention (fp16). K/V loaded strided from kvexp hi/lo planes
// + small roped k_pe planes. Emits hi/lo fp16 output planes.
// ---------------------------------------------------------------------------
#define FL_SMEM 229376
__global__ void __launch_bounds__(256, 1) flash_k(
    const h16* __restrict__ qh_, const h16* __restrict__ ql_,
    const h16* __restrict__ kvh_, const h16* __restrict__ kvl_,
    const h16* __restrict__ kpeh_, const h16* __restrict__ kpel_,
    const float* __restrict__ mb,
    h16* __restrict__ ath, h16* __restrict__ atl)
{
    extern __shared__ char smem[];
    int bh = blockIdx.x, b = bh >> 5, h = bh & 31;
    int qi = 7 - blockIdx.y;
    int t0 = qi * 128;
    int tid = threadIdx.x, lane = tid & 31, wid = tid >> 5;
    int wrow = wid * 16;

    uint32_t S0 = smem_u32(smem);
    uint32_t Qh = S0, Ql = S0 + 49152;
    uint32_t Kb = S0 + 98304;
    uint32_t Vb = S0 + 196608;

    const h16* Qgh = qh_ + ((size_t)(b * 1024 + t0)) * 6144 + h * 192;
    const h16* Qgl = ql_ + ((size_t)(b * 1024 + t0)) * 6144 + h * 192;
    const h16* KNh = kvh_ + (size_t)b * 1024 * 8192 + h * 256;
    const h16* KNl = kvl_ + (size_t)b * 1024 * 8192 + h * 256;
    const h16* KPh = kpeh_ + (size_t)b * 1024 * 64;
    const h16* KPl = kpel_ + (size_t)b * 1024 * 64;
    const h16* Vgh = KNh + 128;
    const h16* Vgl = KNl + 128;
    const float* mbb = mb + b * 1024;

#pragma unroll
    for (int sp = 0; sp < 6; sp++) {
        load_plane(Qh + sp * 8192, Qgh, 0, 6144, sp * 32, tid, 128);
        load_plane(Ql + sp * 8192, Qgl, 0, 6144, sp * 32, tid, 128);
    }
#pragma unroll
    for (int sp = 0; sp < 4; sp++) {
        load_plane64(Kb + sp * 4096,         KNh + sp * 32, 8192, tid);
        load_plane64(Kb + 24576 + sp * 4096, KNl + sp * 32, 8192, tid);
    }
#pragma unroll
    for (int sp = 4; sp < 6; sp++) {
        load_plane64(Kb + sp * 4096,         KPh + (sp - 4) * 32, 64, tid);
        load_plane64(Kb + 24576 + sp * 4096, KPl + (sp - 4) * 32, 64, tid);
    }
    CP_COMMIT();

    int nst = (t0 + 128) >> 6;
    float m0 = -1e30f, m1 = -1e30f, l0 = 0.f, l1 = 0.f;
    float O[16][4];
#pragma unroll
    for (int i = 0; i < 16; i++)
#pragma unroll
        for (int j = 0; j < 4; j++) O[i][j] = 0.f;

    int rA = wrow + (lane & 15);
    int swA = (rA >> 1) & 3;
    int rB[4], swB[4];
#pragma unroll
    for (int g = 0; g < 4; g++) {
        rB[g] = g * 16 + (lane & 7) + ((lane >> 4) << 3);
        swB[g] = (rB[g] >> 1) & 3;
    }
    int aSel = (lane >> 4) & 1, bSel = (lane >> 3) & 1;
    int trow = t0 + wrow + (lane >> 2);

    for (int i = 0; i < nst; i++) {
        __syncthreads();
        load_v(Vb,         Vgh + (size_t)i * 64 * 8192, 8192, tid);
        load_v(Vb + 16384, Vgl + (size_t)i * 64 * 8192, 8192, tid);
        CP_COMMIT();
        if (i + 1 < nst) {
            uint32_t Ks = Kb + ((i + 1) & 1) * 49152;
            size_t roff = (size_t)(i + 1) * 64;
#pragma unroll
            for (int sp = 0; sp < 4; sp++) {
                load_plane64(Ks + sp * 4096,         KNh + roff * 8192 + sp * 32, 8192, tid);
                load_plane64(Ks + 24576 + sp * 4096, KNl + roff * 8192 + sp * 32, 8192, tid);
            }
#pragma unroll
            for (int sp = 4; sp < 6; sp++) {
                load_plane64(Ks + sp * 4096,         KPh + roff * 64 + (sp - 4) * 32, 64, tid);
                load_plane64(Ks + 24576 + sp * 4096, KPl + roff * 64 + (sp - 4) * 32, 64, tid);
            }
        }
        CP_COMMIT();

        CP_WAIT(2);
        __syncthreads();

        // ---- S = QK^T (3 passes: QhKh, QhKl, QlKh) ----
        float S[8][4];
#pragma unroll
        for (int nt = 0; nt < 8; nt++)
#pragma unroll
            for (int j = 0; j < 4; j++) S[nt][j] = 0.f;

        uint32_t Ks = Kb + (i & 1) * 49152;
#pragma unroll
        for (int ks = 0; ks < 12; ks++) {
            int sp = ks >> 1;
            int cA = ((ks & 1) << 1) + aSel;
            int cB = ((ks & 1) << 1) + bSel;
            uint32_t ah[4], bhf[4][4], blf[4][4];
            LDSM4(ah, Qh + sp * 8192 + rA * 64 + (uint32_t)((cA ^ swA) << 4));
#pragma unroll
            for (int g = 0; g < 4; g++)
                LDSM4(bhf[g], Ks + sp * 4096 + rB[g] * 64 + (uint32_t)((cB ^ swB[g]) << 4));
#pragma unroll
            for (int g = 0; g < 4; g++) {
                MMAH(S[2 * g], ah, bhf[g][0], bhf[g][1]);
                MMAH(S[2 * g + 1], ah, bhf[g][2], bhf[g][3]);
            }
#pragma unroll
            for (int g = 0; g < 4; g++)
                LDSM4(blf[g], Ks + 24576 + sp * 4096 + rB[g] * 64 + (uint32_t)((cB ^ swB[g]) << 4));
#pragma unroll
            for (int g = 0; g < 4; g++) {
                MMAH(S[2 * g], ah, blf[g][0], blf[g][1]);
                MMAH(S[2 * g + 1], ah, blf[g][2], blf[g][3]);
            }
            LDSM4(ah, Ql + sp * 8192 + rA * 64 + (uint32_t)((cA ^ swA) << 4));
#pragma unroll
            for (int g = 0; g < 4; g++) {
                MMAH(S[2 * g], ah, bhf[g][0], bhf[g][1]);
                MMAH(S[2 * g + 1], ah, bhf[g][2], bhf[g][3]);
            }
        }

        // ---- online softmax ----
        int s0i = i * 64;
        float mx0 = -1e30f, mx1 = -1e30f;
#pragma unroll
        for (int nt = 0; nt < 8; nt++) {
            int sb0 = s0i + nt * 8 + ((lane & 3) << 1);
            float bias0 = mbb[sb0], bias1 = mbb[sb0 + 1];
            float v0 = S[nt][0] * SCALE_QK + bias0; if (sb0     > trow)     v0 = -1e30f;
            float v1 = S[nt][1] * SCALE_QK + bias1; if (sb0 + 1 > trow)     v1 = -1e30f;
            float v2 = S[nt][2] * SCALE_QK + bias0; if (sb0     > trow + 8) v2 = -1e30f;
            float v3 = S[nt][3] * SCALE_QK + bias1; if (sb0 + 1 > trow + 8) v3 = -1e30f;
            S[nt][0] = v0; S[nt][1] = v1; S[nt][2] = v2; S[nt][3] = v3;
            mx0 = fmaxf(mx0, fmaxf(v0, v1));
            mx1 = fmaxf(mx1, fmaxf(v2, v3));
        }
        mx0 = fmaxf(mx0, __shfl_xor_sync(0xffffffffu, mx0, 1));
        mx0 = fmaxf(mx0, __shfl_xor_sync(0xffffffffu, mx0, 2));
        mx1 = fmaxf(mx1, __shfl_xor_sync(0xffffffffu, mx1, 1));
        mx1 = fmaxf(mx1, __shfl_xor_sync(0xffffffffu, mx1, 2));
        float mn0 = fmaxf(m0, mx0), mn1 = fmaxf(m1, mx1);
        float cr0 = __expf(m0 - mn0), cr1 = __expf(m1 - mn1);
        float sum0 = 0.f, sum1 = 0.f;
#pragma unroll
        for (int nt = 0; nt < 8; nt++) {
            S[nt][0] = __expf(S[nt][0] - mn0);
            S[nt][1] = __expf(S[nt][1] - mn0);
            S[nt][2] = __expf(S[nt][2] - mn1);
            S[nt][3] = __expf(S[nt][3] - mn1);
            sum0 += S[nt][0] + S[nt][1];
            sum1 += S[nt][2] + S[nt][3];
        }
        sum0 += __shfl_xor_sync(0xffffffffu, sum0, 1);
        sum0 += __shfl_xor_sync(0xffffffffu, sum0, 2);
        sum1 += __shfl_xor_sync(0xffffffffu, sum1, 1);
        sum1 += __shfl_xor_sync(0xffffffffu, sum1, 2);
        l0 = l0 * cr0 + sum0;  l1 = l1 * cr1 + sum1;
        m0 = mn0;  m1 = mn1;
#pragma unroll
        for (int nd = 0; nd < 16; nd++) {
            O[nd][0] *= cr0; O[nd][1] *= cr0;
            O[nd][2] *= cr1; O[nd][3] *= cr1;
        }

        CP_WAIT(1);
        __syncthreads();

        // ---- O += P @ V (2 passes: P·Vh + P·Vl) ----
        int rV = (lane & 15);
#pragma unroll
        for (int kc = 0; kc < 4; kc++) {
            uint32_t phi[4];
#pragma unroll
            for (int j = 0; j < 2; j++) {
                int nt = 2 * kc + j;
                phi[2 * j]     = packh(S[nt][0], S[nt][1]);
                phi[2 * j + 1] = packh(S[nt][2], S[nt][3]);
            }
            int row = kc * 16 + rV;
            int sw = row & 7;
            uint32_t rbase = (uint32_t)row * 256;
            int cgrp = (lane >> 4) << 3;
#pragma unroll
            for (int g = 0; g < 8; g++) {
                int cch = (((g << 4) + cgrp) >> 3) ^ sw;
                uint32_t v4[4];
                LDSM4T(v4, Vb + rbase + (uint32_t)(cch << 4));
                MMAH_P(O[2 * g],     phi[0], phi[1], phi[2], phi[3], v4[0], v4[1]);
                MMAH_P(O[2 * g + 1], phi[0], phi[1], phi[2], phi[3], v4[2], v4[3]);
                LDSM4T(v4, Vb + 16384 + rbase + (uint32_t)(cch << 4));
                MMAH_P(O[2 * g],     phi[0], phi[1], phi[2], phi[3], v4[0], v4[1]);
                MMAH_P(O[2 * g + 1], phi[0], phi[1], phi[2], phi[3], v4[2], v4[3]);
            }
        }
    }

    // ---- epilogue: O / l -> hi/lo fp16 planes ----
    float inv0 = 1.f / l0, inv1 = 1.f / l1;
    size_t row0 = ((size_t)(b * 1024) + trow) * 4096 + h * 128;
    size_t row1 = row0 + (size_t)8 * 4096;
    int dcol = (lane & 3) * 2;
#pragma unroll
    for (int nd = 0; nd < 16; nd++) {
        float o0 = O[nd][0] * inv0, o1 = O[nd][1] * inv0;
        float o2 = O[nd][2] * inv1, o3 = O[nd][3] * inv1;
        float h0 = __half2float(__float2half_rn(o0));
        float h1 = __half2float(__float2half_rn(o1));
        float h2f = __half2float(__float2half_rn(o2));
        float h3 = __half2float(__float2half_rn(o3));
        int c = nd * 8 + dcol;
        *(uint32_t*)(ath + row0 + c) = packh(o0, o1);
        *(uint32_t*)(atl + row0 + c) = packh(o0 - h0, o1 - h1);
        *(uint32_t*)(ath + row1 + c) = packh(o2, o3);
        *(uint32_t*)(atl + row1 + c) = packh(o2 - h2f, o3 - h3);
    }
}

// ------------------------- conversion / elementwise -------------------------
__device__ __forceinline__ void split1h(float v, h16* h, h16* l, size_t i) {
    h16 hi = __float2half_rn(v);
    h[i] = hi;
    l[i] = __float2half_rn(v - __half2float(hi));
}

__global__ void split_k(const float* __restrict__ x, h16* __restrict__ h,
                        h16* __restrict__ l, long n) {
    long i = blockIdx.x * 256ll + threadIdx.x;
    if (i < n) split1h(x[i], h, l, i);
}

// Merged weight transpose+convert (single fp16 plane) for all 5 weights.
__global__ void wtconv_k(const float* __restrict__ wq_a,
                         const float* __restrict__ wkv_a,
                         const float* __restrict__ wq_b,
                         const float* __restrict__ wkv_b,
                         const float* __restrict__ wo,
                         h16* __restrict__ wab, h16* __restrict__ wqb,
                         h16* __restrict__ wkvb, h16* __restrict__ wot)
{
    __shared__ float t[32][33];
    int bx = blockIdx.x;
    const float* W; h16* T; int K, N, nx, tIdx, rowOff;
    if (bx < 6144)       { W = wq_a;  T = wab;  K = 4096; N = 1536; nx = 48;  tIdx = bx;         rowOff = 0; }
    else if (bx < 8448)  { W = wkv_a; T = wab;  K = 4096; N = 576;  nx = 18;  tIdx = bx - 6144;  rowOff = 1536; }
    else if (bx < 17664) { W = wq_b;  T = wqb;  K = 1536; N = 6144; nx = 192; tIdx = bx - 8448;  rowOff = 0; }
    else if (bx < 21760) { W = wkv_b; T = wkvb; K = 512;  N = 8192; nx = 256; tIdx = bx - 17664; rowOff = 0; }
    else                 { W = wo;    T = wot;  K = 4096; N = 4096; nx = 128; tIdx = bx - 21760; rowOff = 0; }
    int n0 = (tIdx % nx) * 32, k0 = (tIdx / nx) * 32;
    int tx = threadIdx.x, ty = threadIdx.y;
#pragma unroll
    for (int j = 0; j < 32; j += 8)
        t[ty + j][tx] = W[(size_t)(k0 + ty + j) * N + n0 + tx];
    __syncthreads();
#pragma unroll
    for (int j = 0; j < 32; j += 8)
        T[(size_t)(rowOff + n0 + ty + j) * K + k0 + tx] =
            __float2half_rn(t[tx][ty + j]);
}

// Merged rmsnorm (q rows then kv rows) -> hi/lo fp16 planes.
__global__ void rmsns2_k(const float* __restrict__ qkv,
                         const float* __restrict__ qw,
                         const float* __restrict__ kvw,
                         h16* __restrict__ qlh, h16* __restrict__ qll,
                         h16* __restrict__ kvh, h16* __restrict__ kvl)
{
    __shared__ float red[256];
    int rb = blockIdx.x;
    int isq = rb < 2048;
    long row = isq ? rb : rb - 2048;
    int n = isq ? 1536 : 512;
    const float* p = qkv + row * 2112 + (isq ? 0 : 1536);
    const float* w = isq ? qw : kvw;
    h16* oh = (isq ? qlh : kvh) + row * n;
    h16* ol = (isq ? qll : kvl) + row * n;
    int tid = threadIdx.x;
    float ss = 0.f;
    for (int c = tid; c < n; c += 256) { float v = p[c]; ss += v * v; }
    red[tid] = ss; __syncthreads();
    for (int s = 128; s > 0; s >>= 1) {
        if (tid < s) red[tid] += red[tid + s];
        __syncthreads();
    }
    float r = rsqrtf(red[0] / (float)n + 1e-6f);
    for (int c = tid; c < n; c += 256) {
        float v = p[c] * r * w[c];
        h16 hi = __float2half_rn(v);
        oh[c] = hi;
        ol[c] = __float2half_rn(v - __half2float(hi));
    }
}

// Rope patch on q planes (pe cols) in place: one warp per (token, head).
__global__ void rope_qpe_k(h16* __restrict__ qh, h16* __restrict__ ql,
                           const int* __restrict__ pos) {
    int w = blockIdx.x * 8 + (threadIdx.x >> 5);
    int lane = threadIdx.x & 31;
    int bt = w >> 5, h = w & 31;
    size_t ob = (size_t)bt * 6144 + h * 192;
    float p = (float)pos[bt];
    float invf = powf(10000.f, -(float)lane / 32.f);
    float sn, cs; sincosf(p * invf, &sn, &cs);
    float x1 = __half2float(qh[ob + 128 + lane]) + __half2float(ql[ob + 128 + lane]);
    float x2 = __half2float(qh[ob + 160 + lane]) + __half2float(ql[ob + 160 + lane]);
    split1h(x1 * cs - x2 * sn, qh, ql, ob + 128 + lane);
    split1h(x1 * sn + x2 * cs, qh, ql, ob + 160 + lane);
}

// rope shared k_pe (fp32 in qkv cols 2048+) -> kpeh/kpel planes [2048][64].
__global__ void rope_kpe_k(const float* __restrict__ qkv,
                           const int* __restrict__ pos,
                           h16* __restrict__ kpeh, h16* __restrict__ kpel) {
    int w = blockIdx.x * 8 + (threadIdx.x >> 5);   // 256 blocks * 8 warps = 2048
    int lane = threadIdx.x & 31;
    const float* base = qkv + (size_t)w * 2112 + 2048;
    float p = (float)pos[w];
    float invf = powf(10000.f, -(float)lane / 32.f);
    float sn, cs; sincosf(p * invf, &sn, &cs);
    float x1 = base[lane], x2 = base[32 + lane];
    size_t ob = (size_t)w * 64;
    split1h(x1 * cs - x2 * sn, kpeh, kpel, ob + lane);
    split1h(x1 * sn + x2 * cs, kpeh, kpel, ob + 32 + lane);
}

__global__ void maskbias_k(const int* __restrict__ amask, float* __restrict__ mb) {
    int i = blockIdx.x * 256 + threadIdx.x;
    if (i < 2048) mb[i] = amask[i] ? 0.f : -1e30f;
}

// ---------------------------------------------------------------------------
extern "C" void kernel_launch(void* const* d_in, const int* in_sizes, int n_in,
                              void* d_out, int out_size)
{
    const float* x        = (const float*)d_in[0];
    const float* wq_a     = (const float*)d_in[1];
    const float* q_norm_w = (const float*)d_in[2];
    const float* wq_b     = (const float*)d_in[3];
    const float* wkv_a    = (const float*)d_in[4];
    const float* kv_norm_w= (const float*)d_in[5];
    const float* wkv_b    = (const float*)d_in[6];
    const float* wo       = (const float*)d_in[7];
    const int*   amask    = (const int*)d_in[8];
    const int*   pos      = (const int*)d_in[9];
    float*       out      = (float*)d_out;

    cudaFuncSetAttribute(gemm2_k, cudaFuncAttributeMaxDynamicSharedMemorySize,
                         GEMM2_SMEM);
    cudaFuncSetAttribute(gemm2h_dual_k, cudaFuncAttributeMaxDynamicSharedMemorySize,
                         GEMM2_SMEM);
    cudaFuncSetAttribute(flash_k, cudaFuncAttributeMaxDynamicSharedMemorySize,
                         FL_SMEM);

    float *qkv, *mb;
    h16 *xh,*xl,*qlh,*qll,*qh,*ql,*kvh,*kvl,*kvexph,*kvexpl,*kpeh,*kpel,*ath,*atl;
    h16 *wab,*wqb,*wkvb,*wot;
    cudaGetSymbolAddress((void**)&qkv,  g_qkv);
    cudaGetSymbolAddress((void**)&mb,   g_mb);
    cudaGetSymbolAddress((void**)&xh, g_xh);   cudaGetSymbolAddress((void**)&xl, g_xl);
    cudaGetSymbolAddress((void**)&qlh,g_qlh);  cudaGetSymbolAddress((void**)&qll,g_qll);
    cudaGetSymbolAddress((void**)&qh, g_qh);   cudaGetSymbolAddress((void**)&ql, g_ql);
    cudaGetSymbolAddress((void**)&kvh,g_kvh);  cudaGetSymbolAddress((void**)&kvl,g_kvl);
    cudaGetSymbolAddress((void**)&kvexph,g_kvexph);
    cudaGetSymbolAddress((void**)&kvexpl,g_kvexpl);
    cudaGetSymbolAddress((void**)&kpeh,g_kpeh); cudaGetSymbolAddress((void**)&kpel,g_kpel);
    cudaGetSymbolAddress((void**)&ath,g_ath);  cudaGetSymbolAddress((void**)&atl,g_atl);
    cudaGetSymbolAddress((void**)&wab,g_wab);  cudaGetSymbolAddress((void**)&wqb,g_wqb);
    cudaGetSymbolAddress((void**)&wkvb,g_wkvb); cudaGetSymbolAddress((void**)&wot,g_wo);

    // prologue conversions
    wtconv_k<<<38144, dim3(32, 8)>>>(wq_a, wkv_a, wq_b, wkv_b, wo,
                                     wab, wqb, wkvb, wot);
    split_k<<<32768, 256>>>(x, xh, xl, 2048ll * 4096);
    maskbias_k<<<8, 256>>>(amask, mb);

    // 1. merged down-proj: qkv = x @ [wq_a | wkv_a]   [2048, 2112] fp32
    gemm2_k<<<dim3(17, 16), 256, GEMM2_SMEM>>>(xh, xl, wab, qkv,
        2112, 4096, 4096, 4096, 2112);
    // 2. rmsnorms -> hi/lo planes; rope k_pe -> planes
    rmsns2_k<<<4096, 256>>>(qkv, q_norm_w, kv_norm_w, qlh, qll, kvh, kvl);
    rope_kpe_k<<<256, 256>>>(qkv, pos, kpeh, kpel);
    // 3. dual up-proj writing hi/lo planes directly
    gemm2h_dual_k<<<dim3(112, 16), 256, GEMM2_SMEM>>>(
        qlh, qll, wqb, qh, ql,          6144, 1536, 1536, 1536, 6144,
        kvh, kvl, wkvb, kvexph, kvexpl, 8192, 512, 512, 512, 8192, 48);
    // 4. rope patch on q pe columns
    rope_qpe_k<<<8192, 256>>>(qh, ql, pos);
    // 5. fused attention (strided K/V from kvexp planes) -> ath/atl
    flash_k<<<dim3(64, 8), 256, FL_SMEM>>>(qh, ql, kvexph, kvexpl,
                                           kpeh, kpel, mb, ath, atl);
    // 6. out = attn @ wo
    gemm2_k<<<dim3(32, 16), 256, GEMM2_SMEM>>>(ath, atl, wot, out,
        4096, 4096, 4096, 4096, 4096);
}

// round 10
// speedup vs baseline: 1.7130x; 1.0301x over previous
#include <cuda_runtime.h>
#include <cuda_fp16.h>
#include <math.h>
#include <stdint.h>

typedef __half h16;
#define TT 1024
#define SCALE_QK 0.07216878364870323f

// ------------------------- device scratch (no cudaMalloc) -------------------
__device__ float g_qkv  [2048*2112];   // qlow | kv | k_pe(fp32, pre-rope)
__device__ float g_mb   [2048];

__device__ h16 g_xh[2048*4096],  g_xl[2048*4096];
__device__ h16 g_qlh[2048*1536], g_qll[2048*1536];
__device__ h16 g_qh[2048*6144],  g_ql[2048*6144];
__device__ h16 g_kvh[2048*512],  g_kvl[2048*512];
__device__ h16 g_kvexph[2048ll*8192], g_kvexpl[2048ll*8192];
__device__ h16 g_kpeh[2048*64],  g_kpel[2048*64];
__device__ h16 g_ath[2048*4096], g_atl[2048*4096];
__device__ h16 g_wab[2112*4096];
__device__ h16 g_wqb[6144*1536];
__device__ h16 g_wkvb[8192*512];
__device__ h16 g_wo[4096*4096];

// ------------------------------ PTX helpers (sm_80-safe) --------------------
__device__ __forceinline__ uint32_t smem_u32(const void* p) {
    uint32_t a;
    asm("{ .reg .u64 t; cvta.to.shared.u64 t, %1; cvt.u32.u64 %0, t; }"
        : "=r"(a) : "l"(p));
    return a;
}

#define LDSM4(r, a) asm volatile( \
    "ldmatrix.sync.aligned.m8n8.x4.shared.b16 {%0,%1,%2,%3}, [%4];" \
    : "=r"((r)[0]), "=r"((r)[1]), "=r"((r)[2]), "=r"((r)[3]) : "r"(a))

#define LDSM4T(r, a) asm volatile( \
    "ldmatrix.sync.aligned.m8n8.x4.trans.shared.b16 {%0,%1,%2,%3}, [%4];" \
    : "=r"((r)[0]), "=r"((r)[1]), "=r"((r)[2]), "=r"((r)[3]) : "r"(a))

#define MMAH(d, a, b0, b1) asm volatile( \
    "mma.sync.aligned.m16n8k16.row.col.f32.f16.f16.f32 " \
    "{%0,%1,%2,%3},{%4,%5,%6,%7},{%8,%9},{%0,%1,%2,%3};" \
    : "+f"((d)[0]), "+f"((d)[1]), "+f"((d)[2]), "+f"((d)[3]) \
    : "r"((a)[0]), "r"((a)[1]), "r"((a)[2]), "r"((a)[3]), "r"(b0), "r"(b1))

#define MMAH_P(d, a0, a1, a2, a3, b0, b1) asm volatile( \
    "mma.sync.aligned.m16n8k16.row.col.f32.f16.f16.f32 " \
    "{%0,%1,%2,%3},{%4,%5,%6,%7},{%8,%9},{%0,%1,%2,%3};" \
    : "+f"((d)[0]), "+f"((d)[1]), "+f"((d)[2]), "+f"((d)[3]) \
    : "r"(a0), "r"(a1), "r"(a2), "r"(a3), "r"(b0), "r"(b1))

__device__ __forceinline__ void cpa16(uint32_t dst, const void* src, int valid) {
    int sz = valid ? 16 : 0;
    asm volatile("cp.async.cg.shared.global [%0], [%1], 16, %2;"
                 :: "r"(dst), "l"(src), "r"(sz));
}
#define CP_COMMIT() asm volatile("cp.async.commit_group;" ::: "memory")
#define CP_WAIT(n)  asm volatile("cp.async.wait_group %0;" :: "n"(n) : "memory")

__device__ __forceinline__ uint32_t packh(float a, float b) {
    __half2 t = __floats2half2_rn(a, b);
    return *reinterpret_cast<uint32_t*>(&t);
}

// Load one 128x32 h16 plane into swizzled smem (rows of 64B).
__device__ __forceinline__ void load_plane(uint32_t sb, const h16* __restrict__ G,
                                           int row0, int ld, int k0, int tid,
                                           int nvalid) {
#pragma unroll
    for (int i = 0; i < 2; i++) {
        int idx = tid * 2 + i;
        int r = idx >> 2, c = idx & 3;
        uint32_t dst = sb + r * 64 + ((c ^ ((r >> 1) & 3)) << 4);
        int ok = r < nvalid;
        const h16* src = G + (size_t)(row0 + (ok ? r : 0)) * ld + k0 + c * 8;
        cpa16(dst, src, ok);
    }
}

// Load one 64x32 h16 subplane (256 threads -> 1 line each). G pre-offset.
__device__ __forceinline__ void load_plane64(uint32_t sb, const h16* __restrict__ G,
                                             int ld, int tid) {
    int r = tid >> 2, c = tid & 3;
    uint32_t dst = sb + r * 64 + ((c ^ ((r >> 1) & 3)) << 4);
    cpa16(dst, G + (size_t)r * ld + c * 8, 1);
}

// Load one 64x128 h16 V plane (rows of 256B) with row-xor swizzle; row stride ld.
__device__ __forceinline__ void load_v(uint32_t sb, const h16* __restrict__ G,
                                       int ld, int tid) {
#pragma unroll
    for (int i = 0; i < 4; i++) {
        int idx = i * 256 + tid;
        int r = idx >> 4, c = idx & 15;
        uint32_t dst = sb + r * 256 + ((c ^ (r & 7)) << 4);
        cpa16(dst, G + (size_t)r * ld + c * 8, 1);
    }
}

// ---------------------------------------------------------------------------
// 2-pass split-fp16 HMMA GEMM body, 4-stage cp.async pipeline.
// H16OUT=0: fp32 C; H16OUT=1: hi/lo fp16 planes.
// ---------------------------------------------------------------------------
#define GEMM2_SMEM 98304
template<int H16OUT>
__device__ __forceinline__ void gemm2_body(
    const h16* __restrict__ Ah, const h16* __restrict__ Al,
    const h16* __restrict__ B, float* __restrict__ C,
    h16* __restrict__ Ch, h16* __restrict__ Cl,
    int N, int K, int lda, int ldb, int ldc, int m0, int n0, char* smem)
{
    int tid = threadIdx.x, lane = tid & 31, wid = tid >> 5;
    int mw = (wid & 1) * 64, nw = (wid >> 1) * 32;
    uint32_t s0 = smem_u32(smem);
    int nvB = min(128, N - n0);
    int nch = K >> 5;

    uint32_t rowA[4]; int sA[4];
#pragma unroll
    for (int mt = 0; mt < 4; mt++) {
        int r = mw + mt * 16 + (lane & 15);
        rowA[mt] = r * 64; sA[mt] = (r >> 1) & 3;
    }
    uint32_t rowB[2]; int sB[2];
#pragma unroll
    for (int h2 = 0; h2 < 2; h2++) {
        int r = nw + h2 * 16 + (lane & 7) + ((lane >> 4) << 3);
        rowB[h2] = r * 64; sB[h2] = (r >> 1) & 3;
    }
    int aCk = (lane >> 4) & 1, bCk = (lane >> 3) & 1;

    float acc[4][4][4];
#pragma unroll
    for (int i = 0; i < 4; i++)
#pragma unroll
        for (int j = 0; j < 4; j++)
#pragma unroll
            for (int r = 0; r < 4; r++) acc[i][j][r] = 0.f;

    // prologue: stages 0..2
#pragma unroll
    for (int pc = 0; pc < 3; pc++) {
        if (pc < nch) {
            uint32_t sb = s0 + pc * 24576;
            load_plane(sb,         Ah, m0, lda, pc * 32, tid, 128);
            load_plane(sb + 8192,  Al, m0, lda, pc * 32, tid, 128);
            load_plane(sb + 16384, B,  n0, ldb, pc * 32, tid, nvB);
        }
        CP_COMMIT();
    }

    for (int c = 0; c < nch; c++) {
        CP_WAIT(2);
        __syncthreads();
        if (c + 3 < nch) {
            uint32_t sb = s0 + ((c + 3) & 3) * 24576;
            int k0 = (c + 3) * 32;
            load_plane(sb,         Ah, m0, lda, k0, tid, 128);
            load_plane(sb + 8192,  Al, m0, lda, k0, tid, 128);
            load_plane(sb + 16384, B,  n0, ldb, k0, tid, nvB);
        }
        CP_COMMIT();

        uint32_t base = s0 + (c & 3) * 24576;
        uint32_t pAh = base, pAl = base + 8192, pB = base + 16384;
#pragma unroll
        for (int ks = 0; ks < 2; ks++) {
            uint32_t af[4][4], bf[2][4];
            int cA = ks * 2 + aCk, cB = ks * 2 + bCk;
#pragma unroll
            for (int mt = 0; mt < 4; mt++)
                LDSM4(af[mt], pAh + rowA[mt] + (uint32_t)((cA ^ sA[mt]) << 4));
#pragma unroll
            for (int h2 = 0; h2 < 2; h2++)
                LDSM4(bf[h2], pB + rowB[h2] + (uint32_t)((cB ^ sB[h2]) << 4));
#pragma unroll
            for (int mt = 0; mt < 4; mt++)
#pragma unroll
                for (int nt = 0; nt < 4; nt++)
                    MMAH(acc[mt][nt], af[mt],
                         bf[nt >> 1][(nt & 1) * 2], bf[nt >> 1][(nt & 1) * 2 + 1]);
#pragma unroll
            for (int mt = 0; mt < 4; mt++)
                LDSM4(af[mt], pAl + rowA[mt] + (uint32_t)((cA ^ sA[mt]) << 4));
#pragma unroll
            for (int mt = 0; mt < 4; mt++)
#pragma unroll
                for (int nt = 0; nt < 4; nt++)
                    MMAH(acc[mt][nt], af[mt],
                         bf[nt >> 1][(nt & 1) * 2], bf[nt >> 1][(nt & 1) * 2 + 1]);
        }
    }

#pragma unroll
    for (int mt = 0; mt < 4; mt++) {
        int r0 = m0 + mw + mt * 16 + (lane >> 2);
#pragma unroll
        for (int nt = 0; nt < 4; nt++) {
            int col = n0 + nw + nt * 8 + 2 * (lane & 3);
            if (col < N) {
                if (H16OUT == 0) {
                    float2 v0 = make_float2(acc[mt][nt][0], acc[mt][nt][1]);
                    float2 v1 = make_float2(acc[mt][nt][2], acc[mt][nt][3]);
                    *(float2*)(C + (size_t)r0 * ldc + col) = v0;
                    *(float2*)(C + (size_t)(r0 + 8) * ldc + col) = v1;
                } else {
                    float a0 = acc[mt][nt][0], a1 = acc[mt][nt][1];
                    float a2 = acc[mt][nt][2], a3 = acc[mt][nt][3];
                    float h0 = __half2float(__float2half_rn(a0));
                    float h1 = __half2float(__float2half_rn(a1));
                    float h2f = __half2float(__float2half_rn(a2));
                    float h3 = __half2float(__float2half_rn(a3));
                    *(uint32_t*)(Ch + (size_t)r0 * ldc + col) = packh(a0, a1);
                    *(uint32_t*)(Cl + (size_t)r0 * ldc + col) = packh(a0 - h0, a1 - h1);
                    *(uint32_t*)(Ch + (size_t)(r0 + 8) * ldc + col) = packh(a2, a3);
                    *(uint32_t*)(Cl + (size_t)(r0 + 8) * ldc + col) = packh(a2 - h2f, a3 - h3);
                }
            }
        }
    }
}

__global__ void __launch_bounds__(256, 2) gemm2_k(
    const h16* __restrict__ Ah, const h16* __restrict__ Al,
    const h16* __restrict__ B, float* __restrict__ C,
    int N, int K, int lda, int ldb, int ldc)
{
    extern __shared__ char smem[];
    gemm2_body<0>(Ah, Al, B, C, nullptr, nullptr, N, K, lda, ldb, ldc,
                  blockIdx.y * 128, blockIdx.x * 128, smem);
}

__global__ void __launch_bounds__(256, 2) gemm2h_dual_k(
    const h16* __restrict__ A0h, const h16* __restrict__ A0l,
    const h16* __restrict__ B0, h16* __restrict__ C0h, h16* __restrict__ C0l,
    int N0, int K0, int lda0, int ldb0, int ldc0,
    const h16* __restrict__ A1h, const h16* __restrict__ A1l,
    const h16* __restrict__ B1, h16* __restrict__ C1h, h16* __restrict__ C1l,
    int N1, int K1, int lda1, int ldb1, int ldc1, int nx0)
{
    extern __shared__ char smem[];
    if ((int)blockIdx.x < nx0)
        gemm2_body<1>(A0h, A0l, B0, nullptr, C0h, C0l, N0, K0, lda0, ldb0, ldc0,
                      blockIdx.y * 128, blockIdx.x * 128, smem);
    else
        gemm2_body<1>(A1h, A1l, B1, nullptr, C1h, C1l, N1, K1, lda1, ldb1, ldc1,
                      blockIdx.y * 128, (blockIdx.x - nx0) * 128, smem);
}

// ---------------------------------------------------------------------------
// Fused flash attention (fp16). K/V loaded strided from kvexp hi/lo planes;
// Q roped in smem after load. Emits hi/lo fp16 output planes.
// ---------------------------------------------------------------------------
#define FL_SMEM 229376
__global__ void __launch_bounds__(256, 1) flash_k(
    const h16* __restrict__ qh_, const h16* __restrict__ ql_,
    const h16* __restrict__ kvh_, const h16* __restrict__ kvl_,
    const h16* __restrict__ kpeh_, const h16* __restrict__ kpel_,
    const float* __restrict__ mb, const int* __restrict__ pos,
    h16* __restrict__ ath, h16* __restrict__ atl)
{
    extern __shared__ char smem[];
    int bh = blockIdx.x, b = bh >> 5, h = bh & 31;
    int qi = 7 - blockIdx.y;
    int t0 = qi * 128;
    int tid = threadIdx.x, lane = tid & 31, wid = tid >> 5;
    int wrow = wid * 16;

    uint32_t S0 = smem_u32(smem);
    uint32_t Qh = S0, Ql = S0 + 49152;
    uint32_t Kb = S0 + 98304;
    uint32_t Vb = S0 + 196608;

    const h16* Qgh = qh_ + ((size_t)(b * 1024 + t0)) * 6144 + h * 192;
    const h16* Qgl = ql_ + ((size_t)(b * 1024 + t0)) * 6144 + h * 192;
    const h16* KNh = kvh_ + (size_t)b * 1024 * 8192 + h * 256;
    const h16* KNl = kvl_ + (size_t)b * 1024 * 8192 + h * 256;
    const h16* KPh = kpeh_ + (size_t)b * 1024 * 64;
    const h16* KPl = kpel_ + (size_t)b * 1024 * 64;
    const h16* Vgh = KNh + 128;
    const h16* Vgl = KNl + 128;
    const float* mbb = mb + b * 1024;

#pragma unroll
    for (int sp = 0; sp < 6; sp++) {
        load_plane(Qh + sp * 8192, Qgh, 0, 6144, sp * 32, tid, 128);
        load_plane(Ql + sp * 8192, Qgl, 0, 6144, sp * 32, tid, 128);
    }
#pragma unroll
    for (int sp = 0; sp < 4; sp++) {
        load_plane64(Kb + sp * 4096,         KNh + sp * 32, 8192, tid);
        load_plane64(Kb + 24576 + sp * 4096, KNl + sp * 32, 8192, tid);
    }
#pragma unroll
    for (int sp = 4; sp < 6; sp++) {
        load_plane64(Kb + sp * 4096,         KPh + (sp - 4) * 32, 64, tid);
        load_plane64(Kb + 24576 + sp * 4096, KPl + (sp - 4) * 32, 64, tid);
    }
    CP_COMMIT();

    // ---- rope Q pe columns (subplanes 4,5) in smem ----
    CP_WAIT(0);
    __syncthreads();
    {
        int j = tid & 31;
        float invf = powf(10000.f, -(float)j / 32.f);
#pragma unroll
        for (int it = 0; it < 16; it++) {
            int r = (tid >> 5) + it * 8;
            uint32_t off = (uint32_t)(r * 64 +
                (((j >> 3) ^ ((r >> 1) & 3)) << 4) + (j & 7) * 2);
            h16* qh4 = (h16*)(smem + 4 * 8192 + off);
            h16* qh5 = (h16*)(smem + 5 * 8192 + off);
            h16* ql4 = (h16*)(smem + 49152 + 4 * 8192 + off);
            h16* ql5 = (h16*)(smem + 49152 + 5 * 8192 + off);
            float x1 = __half2float(*qh4) + __half2float(*ql4);
            float x2 = __half2float(*qh5) + __half2float(*ql5);
            float p = (float)pos[b * 1024 + t0 + r];
            float sn, cs; sincosf(p * invf, &sn, &cs);
            float y1 = x1 * cs - x2 * sn;
            float y2 = x1 * sn + x2 * cs;
            h16 h1 = __float2half_rn(y1);
            *qh4 = h1; *ql4 = __float2half_rn(y1 - __half2float(h1));
            h16 h2 = __float2half_rn(y2);
            *qh5 = h2; *ql5 = __float2half_rn(y2 - __half2float(h2));
        }
    }

    int nst = (t0 + 128) >> 6;
    float m0 = -1e30f, m1 = -1e30f, l0 = 0.f, l1 = 0.f;
    float O[16][4];
#pragma unroll
    for (int i = 0; i < 16; i++)
#pragma unroll
        for (int j = 0; j < 4; j++) O[i][j] = 0.f;

    int rA = wrow + (lane & 15);
    int swA = (rA >> 1) & 3;
    int rB[4], swB[4];
#pragma unroll
    for (int g = 0; g < 4; g++) {
        rB[g] = g * 16 + (lane & 7) + ((lane >> 4) << 3);
        swB[g] = (rB[g] >> 1) & 3;
    }
    int aSel = (lane >> 4) & 1, bSel = (lane >> 3) & 1;
    int trow = t0 + wrow + (lane >> 2);

    for (int i = 0; i < nst; i++) {
        __syncthreads();
        load_v(Vb,         Vgh + (size_t)i * 64 * 8192, 8192, tid);
        load_v(Vb + 16384, Vgl + (size_t)i * 64 * 8192, 8192, tid);
        CP_COMMIT();
        if (i + 1 < nst) {
            uint32_t Ks = Kb + ((i + 1) & 1) * 49152;
            size_t roff = (size_t)(i + 1) * 64;
#pragma unroll
            for (int sp = 0; sp < 4; sp++) {
                load_plane64(Ks + sp * 4096,         KNh + roff * 8192 + sp * 32, 8192, tid);
                load_plane64(Ks + 24576 + sp * 4096, KNl + roff * 8192 + sp * 32, 8192, tid);
            }
#pragma unroll
            for (int sp = 4; sp < 6; sp++) {
                load_plane64(Ks + sp * 4096,         KPh + roff * 64 + (sp - 4) * 32, 64, tid);
                load_plane64(Ks + 24576 + sp * 4096, KPl + roff * 64 + (sp - 4) * 32, 64, tid);
            }
        }
        CP_COMMIT();

        CP_WAIT(2);
        __syncthreads();

        // ---- S = QK^T (3 passes: QhKh, QhKl, QlKh) ----
        float S[8][4];
#pragma unroll
        for (int nt = 0; nt < 8; nt++)
#pragma unroll
            for (int j = 0; j < 4; j++) S[nt][j] = 0.f;

        uint32_t Ks = Kb + (i & 1) * 49152;
#pragma unroll
        for (int ks = 0; ks < 12; ks++) {
            int sp = ks >> 1;
            int cA = ((ks & 1) << 1) + aSel;
            int cB = ((ks & 1) << 1) + bSel;
            uint32_t ah[4], bhf[4][4], blf[4][4];
            LDSM4(ah, Qh + sp * 8192 + rA * 64 + (uint32_t)((cA ^ swA) << 4));
#pragma unroll
            for (int g = 0; g < 4; g++)
                LDSM4(bhf[g], Ks + sp * 4096 + rB[g] * 64 + (uint32_t)((cB ^ swB[g]) << 4));
#pragma unroll
            for (int g = 0; g < 4; g++) {
                MMAH(S[2 * g], ah, bhf[g][0], bhf[g][1]);
                MMAH(S[2 * g + 1], ah, bhf[g][2], bhf[g][3]);
            }
#pragma unroll
            for (int g = 0; g < 4; g++)
                LDSM4(blf[g], Ks + 24576 + sp * 4096 + rB[g] * 64 + (uint32_t)((cB ^ swB[g]) << 4));
#pragma unroll
            for (int g = 0; g < 4; g++) {
                MMAH(S[2 * g], ah, blf[g][0], blf[g][1]);
                MMAH(S[2 * g + 1], ah, blf[g][2], blf[g][3]);
            }
            LDSM4(ah, Ql + sp * 8192 + rA * 64 + (uint32_t)((cA ^ swA) << 4));
#pragma unroll
            for (int g = 0; g < 4; g++) {
                MMAH(S[2 * g], ah, bhf[g][0], bhf[g][1]);
                MMAH(S[2 * g + 1], ah, bhf[g][2], bhf[g][3]);
            }
        }

        // ---- online softmax ----
        int s0i = i * 64;
        float mx0 = -1e30f, mx1 = -1e30f;
#pragma unroll
        for (int nt = 0; nt < 8; nt++) {
            int sb0 = s0i + nt * 8 + ((lane & 3) << 1);
            float bias0 = mbb[sb0], bias1 = mbb[sb0 + 1];
            float v0 = S[nt][0] * SCALE_QK + bias0; if (sb0     > trow)     v0 = -1e30f;
            float v1 = S[nt][1] * SCALE_QK + bias1; if (sb0 + 1 > trow)     v1 = -1e30f;
            float v2 = S[nt][2] * SCALE_QK + bias0; if (sb0     > trow + 8) v2 = -1e30f;
            float v3 = S[nt][3] * SCALE_QK + bias1; if (sb0 + 1 > trow + 8) v3 = -1e30f;
            S[nt][0] = v0; S[nt][1] = v1; S[nt][2] = v2; S[nt][3] = v3;
            mx0 = fmaxf(mx0, fmaxf(v0, v1));
            mx1 = fmaxf(mx1, fmaxf(v2, v3));
        }
        mx0 = fmaxf(mx0, __shfl_xor_sync(0xffffffffu, mx0, 1));
        mx0 = fmaxf(mx0, __shfl_xor_sync(0xffffffffu, mx0, 2));
        mx1 = fmaxf(mx1, __shfl_xor_sync(0xffffffffu, mx1, 1));
        mx1 = fmaxf(mx1, __shfl_xor_sync(0xffffffffu, mx1, 2));
        float mn0 = fmaxf(m0, mx0), mn1 = fmaxf(m1, mx1);
        float cr0 = __expf(m0 - mn0), cr1 = __expf(m1 - mn1);
        float sum0 = 0.f, sum1 = 0.f;
#pragma unroll
        for (int nt = 0; nt < 8; nt++) {
            S[nt][0] = __expf(S[nt][0] - mn0);
            S[nt][1] = __expf(S[nt][1] - mn0);
            S[nt][2] = __expf(S[nt][2] - mn1);
            S[nt][3] = __expf(S[nt][3] - mn1);
            sum0 += S[nt][0] + S[nt][1];
            sum1 += S[nt][2] + S[nt][3];
        }
        sum0 += __shfl_xor_sync(0xffffffffu, sum0, 1);
        sum0 += __shfl_xor_sync(0xffffffffu, sum0, 2);
        sum1 += __shfl_xor_sync(0xffffffffu, sum1, 1);
        sum1 += __shfl_xor_sync(0xffffffffu, sum1, 2);
        l0 = l0 * cr0 + sum0;  l1 = l1 * cr1 + sum1;
        m0 = mn0;  m1 = mn1;
#pragma unroll
        for (int nd = 0; nd < 16; nd++) {
            O[nd][0] *= cr0; O[nd][1] *= cr0;
            O[nd][2] *= cr1; O[nd][3] *= cr1;
        }

        CP_WAIT(1);
        __syncthreads();

        // ---- O += P @ V (2 passes: P·Vh + P·Vl) ----
        int rV = (lane & 15);
#pragma unroll
        for (int kc = 0; kc < 4; kc++) {
            uint32_t phi[4];
#pragma unroll
            for (int j = 0; j < 2; j++) {
                int nt = 2 * kc + j;
                phi[2 * j]     = packh(S[nt][0], S[nt][1]);
                phi[2 * j + 1] = packh(S[nt][2], S[nt][3]);
            }
            int row = kc * 16 + rV;
            int sw = row & 7;
            uint32_t rbase = (uint32_t)row * 256;
            int cgrp = (lane >> 4) << 3;
#pragma unroll
            for (int g = 0; g < 8; g++) {
                int cch = (((g << 4) + cgrp) >> 3) ^ sw;
                uint32_t v4[4];
                LDSM4T(v4, Vb + rbase + (uint32_t)(cch << 4));
                MMAH_P(O[2 * g],     phi[0], phi[1], phi[2], phi[3], v4[0], v4[1]);
                MMAH_P(O[2 * g + 1], phi[0], phi[1], phi[2], phi[3], v4[2], v4[3]);
                LDSM4T(v4, Vb + 16384 + rbase + (uint32_t)(cch << 4));
                MMAH_P(O[2 * g],     phi[0], phi[1], phi[2], phi[3], v4[0], v4[1]);
                MMAH_P(O[2 * g + 1], phi[0], phi[1], phi[2], phi[3], v4[2], v4[3]);
            }
        }
    }

    // ---- epilogue: O / l -> hi/lo fp16 planes ----
    float inv0 = 1.f / l0, inv1 = 1.f / l1;
    size_t row0 = ((size_t)(b * 1024) + trow) * 4096 + h * 128;
    size_t row1 = row0 + (size_t)8 * 4096;
    int dcol = (lane & 3) * 2;
#pragma unroll
    for (int nd = 0; nd < 16; nd++) {
        float o0 = O[nd][0] * inv0, o1 = O[nd][1] * inv0;
        float o2 = O[nd][2] * inv1, o3 = O[nd][3] * inv1;
        float h0 = __half2float(__float2half_rn(o0));
        float h1 = __half2float(__float2half_rn(o1));
        float h2f = __half2float(__float2half_rn(o2));
        float h3 = __half2float(__float2half_rn(o3));
        int c = nd * 8 + dcol;
        *(uint32_t*)(ath + row0 + c) = packh(o0, o1);
        *(uint32_t*)(atl + row0 + c) = packh(o0 - h0, o1 - h1);
        *(uint32_t*)(ath + row1 + c) = packh(o2, o3);
        *(uint32_t*)(atl + row1 + c) = packh(o2 - h2f, o3 - h3);
    }
}

// ------------------------- conversion / elementwise -------------------------
__device__ __forceinline__ void split1h(float v, h16* h, h16* l, size_t i) {
    h16 hi = __float2half_rn(v);
    h[i] = hi;
    l[i] = __float2half_rn(v - __half2float(hi));
}

// Fused prologue: weight transpose+convert (5 weights) + x hi/lo split.
__global__ void prep_k(const float* __restrict__ wq_a,
                       const float* __restrict__ wkv_a,
                       const float* __restrict__ wq_b,
                       const float* __restrict__ wkv_b,
                       const float* __restrict__ wo,
                       const float* __restrict__ x,
                       h16* __restrict__ wab, h16* __restrict__ wqb,
                       h16* __restrict__ wkvb, h16* __restrict__ wot,
                       h16* __restrict__ xh, h16* __restrict__ xl)
{
    __shared__ float t[32][33];
    int bx = blockIdx.x;
    int tx = threadIdx.x, ty = threadIdx.y;
    if (bx >= 38144) {            // x split: 32768 blocks
        long i = (long)(bx - 38144) * 256 + ty * 32 + tx;
        split1h(x[i], xh, xl, i);
        return;
    }
    const float* W; h16* T; int K, N, nx, tIdx, rowOff;
    if (bx < 6144)       { W = wq_a;  T = wab;  K = 4096; N = 1536; nx = 48;  tIdx = bx;         rowOff = 0; }
    else if (bx < 8448)  { W = wkv_a; T = wab;  K = 4096; N = 576;  nx = 18;  tIdx = bx - 6144;  rowOff = 1536; }
    else if (bx < 17664) { W = wq_b;  T = wqb;  K = 1536; N = 6144; nx = 192; tIdx = bx - 8448;  rowOff = 0; }
    else if (bx < 21760) { W = wkv_b; T = wkvb; K = 512;  N = 8192; nx = 256; tIdx = bx - 17664; rowOff = 0; }
    else                 { W = wo;    T = wot;  K = 4096; N = 4096; nx = 128; tIdx = bx - 21760; rowOff = 0; }
    int n0 = (tIdx % nx) * 32, k0 = (tIdx / nx) * 32;
#pragma unroll
    for (int j = 0; j < 32; j += 8)
        t[ty + j][tx] = W[(size_t)(k0 + ty + j) * N + n0 + tx];
    __syncthreads();
#pragma unroll
    for (int j = 0; j < 32; j += 8)
        T[(size_t)(rowOff + n0 + ty + j) * K + k0 + tx] =
            __float2half_rn(t[tx][ty + j]);
}

// Fused post-down-proj: rmsnorms -> hi/lo, rope k_pe -> planes, mask bias.
__global__ void postdown_k(const float* __restrict__ qkv,
                           const float* __restrict__ qw,
                           const float* __restrict__ kvw,
                           const int* __restrict__ amask,
                           const int* __restrict__ pos,
                           h16* __restrict__ qlh, h16* __restrict__ qll,
                           h16* __restrict__ kvh, h16* __restrict__ kvl,
                           h16* __restrict__ kpeh, h16* __restrict__ kpel,
                           float* __restrict__ mb)
{
    int rb = blockIdx.x;
    int tid = threadIdx.x;
    if (rb >= 4352) {                       // mask bias: 8 blocks
        int i = (rb - 4352) * 256 + tid;
        if (i < 2048) mb[i] = amask[i] ? 0.f : -1e30f;
        return;
    }
    if (rb >= 4096) {                       // rope k_pe: 256 blocks x 8 warps
        int w = (rb - 4096) * 8 + (tid >> 5);
        int lane = tid & 31;
        const float* base = qkv + (size_t)w * 2112 + 2048;
        float p = (float)pos[w];
        float invf = powf(10000.f, -(float)lane / 32.f);
        float sn, cs; sincosf(p * invf, &sn, &cs);
        float x1 = base[lane], x2 = base[32 + lane];
        size_t ob = (size_t)w * 64;
        split1h(x1 * cs - x2 * sn, kpeh, kpel, ob + lane);
        split1h(x1 * sn + x2 * cs, kpeh, kpel, ob + 32 + lane);
        return;
    }
    __shared__ float red[256];
    int isq = rb < 2048;
    long row = isq ? rb : rb - 2048;
    int n = isq ? 1536 : 512;
    const float* p = qkv + row * 2112 + (isq ? 0 : 1536);
    const float* w = isq ? qw : kvw;
    h16* oh = (isq ? qlh : kvh) + row * n;
    h16* ol = (isq ? qll : kvl) + row * n;
    float ss = 0.f;
    for (int c = tid; c < n; c += 256) { float v = p[c]; ss += v * v; }
    red[tid] = ss; __syncthreads();
    for (int s = 128; s > 0; s >>= 1) {
        if (tid < s) red[tid] += red[tid + s];
        __syncthreads();
    }
    float r = rsqrtf(red[0] / (float)n + 1e-6f);
    for (int c = tid; c < n; c += 256) {
        float v = p[c] * r * w[c];
        h16 hi = __float2half_rn(v);
        oh[c] = hi;
        ol[c] = __float2half_rn(v - __half2float(hi));
    }
}

// ---------------------------------------------------------------------------
extern "C" void kernel_launch(void* const* d_in, const int* in_sizes, int n_in,
                              void* d_out, int out_size)
{
    const float* x        = (const float*)d_in[0];
    const float* wq_a     = (const float*)d_in[1];
    const float* q_norm_w = (const float*)d_in[2];
    const float* wq_b     = (const float*)d_in[3];
    const float* wkv_a    = (const float*)d_in[4];
    const float* kv_norm_w= (const float*)d_in[5];
    const float* wkv_b    = (const float*)d_in[6];
    const float* wo       = (const float*)d_in[7];
    const int*   amask    = (const int*)d_in[8];
    const int*   pos      = (const int*)d_in[9];
    float*       out      = (float*)d_out;

    cudaFuncSetAttribute(gemm2_k, cudaFuncAttributeMaxDynamicSharedMemorySize,
                         GEMM2_SMEM);
    cudaFuncSetAttribute(gemm2h_dual_k, cudaFuncAttributeMaxDynamicSharedMemorySize,
                         GEMM2_SMEM);
    cudaFuncSetAttribute(flash_k, cudaFuncAttributeMaxDynamicSharedMemorySize,
                         FL_SMEM);

    float *qkv, *mb;
    h16 *xh,*xl,*qlh,*qll,*qh,*ql,*kvh,*kvl,*kvexph,*kvexpl,*kpeh,*kpel,*ath,*atl;
    h16 *wab,*wqb,*wkvb,*wot;
    cudaGetSymbolAddress((void**)&qkv,  g_qkv);
    cudaGetSymbolAddress((void**)&mb,   g_mb);
    cudaGetSymbolAddress((void**)&xh, g_xh);   cudaGetSymbolAddress((void**)&xl, g_xl);
    cudaGetSymbolAddress((void**)&qlh,g_qlh);  cudaGetSymbolAddress((void**)&qll,g_qll);
    cudaGetSymbolAddress((void**)&qh, g_qh);   cudaGetSymbolAddress((void**)&ql, g_ql);
    cudaGetSymbolAddress((void**)&kvh,g_kvh);  cudaGetSymbolAddress((void**)&kvl,g_kvl);
    cudaGetSymbolAddress((void**)&kvexph,g_kvexph);
    cudaGetSymbolAddress((void**)&kvexpl,g_kvexpl);
    cudaGetSymbolAddress((void**)&kpeh,g_kpeh); cudaGetSymbolAddress((void**)&kpel,g_kpel);
    cudaGetSymbolAddress((void**)&ath,g_ath);  cudaGetSymbolAddress((void**)&atl,g_atl);
    cudaGetSymbolAddress((void**)&wab,g_wab);  cudaGetSymbolAddress((void**)&wqb,g_wqb);
    cudaGetSymbolAddress((void**)&wkvb,g_wkvb); cudaGetSymbolAddress((void**)&wot,g_wo);

    // 0. fused prologue: weight transpose+convert, x split
    prep_k<<<70912, dim3(32, 8)>>>(wq_a, wkv_a, wq_b, wkv_b, wo, x,
                                   wab, wqb, wkvb, wot, xh, xl);
    // 1. merged down-proj: qkv = x @ [wq_a | wkv_a]   [2048, 2112] fp32
    gemm2_k<<<dim3(17, 16), 256, GEMM2_SMEM>>>(xh, xl, wab, qkv,
        2112, 4096, 4096, 4096, 2112);
    // 2. fused rmsnorms + rope k_pe + mask bias
    postdown_k<<<4360, 256>>>(qkv, q_norm_w, kv_norm_w, amask, pos,
                              qlh, qll, kvh, kvl, kpeh, kpel, mb);
    // 3. dual up-proj writing hi/lo planes directly
    gemm2h_dual_k<<<dim3(112, 16), 256, GEMM2_SMEM>>>(
        qlh, qll, wqb, qh, ql,          6144, 1536, 1536, 1536, 6144,
        kvh, kvl, wkvb, kvexph, kvexpl, 8192, 512, 512, 512, 8192, 48);
    // 4. fused attention (rope-on-load, strided K/V) -> ath/atl
    flash_k<<<dim3(64, 8), 256, FL_SMEM>>>(qh, ql, kvexph, kvexpl,
                                           kpeh, kpel, mb, pos, ath, atl);
    // 5. out = attn @ wo
    gemm2_k<<<dim3(32, 16), 256, GEMM2_SMEM>>>(ath, atl, wot, out,
        4096, 4096, 4096, 4096, 4096);
}

// round 11
// speedup vs baseline: 2.2867x; 1.3349x over previous
#include <cuda_runtime.h>
#include <cuda_fp16.h>
#include <math.h>
#include <stdint.h>

typedef __half h16;
#define TT 1024
#define SCALE_QK 0.07216878364870323f

// ------------------------- device scratch (no cudaMalloc) -------------------
__device__ float g_qkv  [2048*2112];   // qlow | kv | k_pe(fp32, pre-rope)
__device__ float g_mb   [2048];

__device__ h16 g_xh[2048*4096];
__device__ h16 g_qlh[2048*1536], g_qll[2048*1536];
__device__ h16 g_qh[2048*6144],  g_ql[2048*6144];
__device__ h16 g_kvh[2048*512],  g_kvl[2048*512];
__device__ h16 g_kvexph[2048ll*8192], g_kvexpl[2048ll*8192];
__device__ h16 g_kpeh[2048*64],  g_kpel[2048*64];
__device__ h16 g_ath[2048*4096];
__device__ h16 g_wab[2112*4096];
__device__ h16 g_wqb[6144*1536];
__device__ h16 g_wkvb[8192*512];
__device__ h16 g_wo[4096*4096];

// ------------------------------ PTX helpers (sm_80-safe) --------------------
__device__ __forceinline__ uint32_t smem_u32(const void* p) {
    uint32_t a;
    asm("{ .reg .u64 t; cvta.to.shared.u64 t, %1; cvt.u32.u64 %0, t; }"
        : "=r"(a) : "l"(p));
    return a;
}

#define LDSM4(r, a) asm volatile( \
    "ldmatrix.sync.aligned.m8n8.x4.shared.b16 {%0,%1,%2,%3}, [%4];" \
    : "=r"((r)[0]), "=r"((r)[1]), "=r"((r)[2]), "=r"((r)[3]) : "r"(a))

#define LDSM4T(r, a) asm volatile( \
    "ldmatrix.sync.aligned.m8n8.x4.trans.shared.b16 {%0,%1,%2,%3}, [%4];" \
    : "=r"((r)[0]), "=r"((r)[1]), "=r"((r)[2]), "=r"((r)[3]) : "r"(a))

#define MMAH(d, a, b0, b1) asm volatile( \
    "mma.sync.aligned.m16n8k16.row.col.f32.f16.f16.f32 " \
    "{%0,%1,%2,%3},{%4,%5,%6,%7},{%8,%9},{%0,%1,%2,%3};" \
    : "+f"((d)[0]), "+f"((d)[1]), "+f"((d)[2]), "+f"((d)[3]) \
    : "r"((a)[0]), "r"((a)[1]), "r"((a)[2]), "r"((a)[3]), "r"(b0), "r"(b1))

#define MMAH_P(d, a0, a1, a2, a3, b0, b1) asm volatile( \
    "mma.sync.aligned.m16n8k16.row.col.f32.f16.f16.f32 " \
    "{%0,%1,%2,%3},{%4,%5,%6,%7},{%8,%9},{%0,%1,%2,%3};" \
    : "+f"((d)[0]), "+f"((d)[1]), "+f"((d)[2]), "+f"((d)[3]) \
    : "r"(a0), "r"(a1), "r"(a2), "r"(a3), "r"(b0), "r"(b1))

__device__ __forceinline__ void cpa16(uint32_t dst, const void* src, int valid) {
    int sz = valid ? 16 : 0;
    asm volatile("cp.async.cg.shared.global [%0], [%1], 16, %2;"
                 :: "r"(dst), "l"(src), "r"(sz));
}
#define CP_COMMIT() asm volatile("cp.async.commit_group;" ::: "memory")
#define CP_WAIT(n)  asm volatile("cp.async.wait_group %0;" :: "n"(n) : "memory")

__device__ __forceinline__ uint32_t packh(float a, float b) {
    __half2 t = __floats2half2_rn(a, b);
    return *reinterpret_cast<uint32_t*>(&t);
}

// Load one 128x32 h16 plane into swizzled smem (rows of 64B).
__device__ __forceinline__ void load_plane(uint32_t sb, const h16* __restrict__ G,
                                           int row0, int ld, int k0, int tid,
                                           int nvalid) {
#pragma unroll
    for (int i = 0; i < 2; i++) {
        int idx = tid * 2 + i;
        int r = idx >> 2, c = idx & 3;
        uint32_t dst = sb + r * 64 + ((c ^ ((r >> 1) & 3)) << 4);
        int ok = r < nvalid;
        const h16* src = G + (size_t)(row0 + (ok ? r : 0)) * ld + k0 + c * 8;
        cpa16(dst, src, ok);
    }
}

// Load one 64x32 h16 subplane (256 threads -> 1 line each). G pre-offset.
__device__ __forceinline__ void load_plane64(uint32_t sb, const h16* __restrict__ G,
                                             int ld, int tid) {
    int r = tid >> 2, c = tid & 3;
    uint32_t dst = sb + r * 64 + ((c ^ ((r >> 1) & 3)) << 4);
    cpa16(dst, G + (size_t)r * ld + c * 8, 1);
}

// Load one 64x128 h16 V plane (rows of 256B) with row-xor swizzle; row stride ld.
__device__ __forceinline__ void load_v(uint32_t sb, const h16* __restrict__ G,
                                       int ld, int tid) {
#pragma unroll
    for (int i = 0; i < 4; i++) {
        int idx = i * 256 + tid;
        int r = idx >> 4, c = idx & 15;
        uint32_t dst = sb + r * 256 + ((c ^ (r & 7)) << 4);
        cpa16(dst, G + (size_t)r * ld + c * 8, 1);
    }
}

// ---------------------------------------------------------------------------
// Split-fp16 HMMA GEMM body, 4-stage cp.async pipeline.
// NPASS=2: C = (Ah+Al) @ B^T ; NPASS=1: C = Ah @ B^T.
// H16OUT=0: fp32 C; H16OUT=1: hi/lo fp16 planes.
// ---------------------------------------------------------------------------
#define GEMM2_SMEM 98304
#define GEMM1_SMEM 65536
template<int H16OUT, int NPASS>
__device__ __forceinline__ void gemm_body(
    const h16* __restrict__ Ah, const h16* __restrict__ Al,
    const h16* __restrict__ B, float* __restrict__ C,
    h16* __restrict__ Ch, h16* __restrict__ Cl,
    int N, int K, int lda, int ldb, int ldc, int m0, int n0, char* smem)
{
    const int STAGE = (NPASS == 2) ? 24576 : 16384;
    const int BOFF  = (NPASS == 2) ? 16384 : 8192;
    int tid = threadIdx.x, lane = tid & 31, wid = tid >> 5;
    int mw = (wid & 1) * 64, nw = (wid >> 1) * 32;
    uint32_t s0 = smem_u32(smem);
    int nvB = min(128, N - n0);
    int nch = K >> 5;

    uint32_t rowA[4]; int sA[4];
#pragma unroll
    for (int mt = 0; mt < 4; mt++) {
        int r = mw + mt * 16 + (lane & 15);
        rowA[mt] = r * 64; sA[mt] = (r >> 1) & 3;
    }
    uint32_t rowB[2]; int sB[2];
#pragma unroll
    for (int h2 = 0; h2 < 2; h2++) {
        int r = nw + h2 * 16 + (lane & 7) + ((lane >> 4) << 3);
        rowB[h2] = r * 64; sB[h2] = (r >> 1) & 3;
    }
    int aCk = (lane >> 4) & 1, bCk = (lane >> 3) & 1;

    float acc[4][4][4];
#pragma unroll
    for (int i = 0; i < 4; i++)
#pragma unroll
        for (int j = 0; j < 4; j++)
#pragma unroll
            for (int r = 0; r < 4; r++) acc[i][j][r] = 0.f;

    // prologue: stages 0..2
#pragma unroll
    for (int pc = 0; pc < 3; pc++) {
        if (pc < nch) {
            uint32_t sb = s0 + pc * STAGE;
            load_plane(sb,        Ah, m0, lda, pc * 32, tid, 128);
            if (NPASS == 2)
                load_plane(sb + 8192, Al, m0, lda, pc * 32, tid, 128);
            load_plane(sb + BOFF, B,  n0, ldb, pc * 32, tid, nvB);
        }
        CP_COMMIT();
    }

    for (int c = 0; c < nch; c++) {
        CP_WAIT(2);
        __syncthreads();
        if (c + 3 < nch) {
            uint32_t sb = s0 + ((c + 3) & 3) * STAGE;
            int k0 = (c + 3) * 32;
            load_plane(sb,        Ah, m0, lda, k0, tid, 128);
            if (NPASS == 2)
                load_plane(sb + 8192, Al, m0, lda, k0, tid, 128);
            load_plane(sb + BOFF, B,  n0, ldb, k0, tid, nvB);
        }
        CP_COMMIT();

        uint32_t base = s0 + (c & 3) * STAGE;
        uint32_t pAh = base, pAl = base + 8192, pB = base + BOFF;
#pragma unroll
        for (int ks = 0; ks < 2; ks++) {
            uint32_t af[4][4], bf[2][4];
            int cA = ks * 2 + aCk, cB = ks * 2 + bCk;
#pragma unroll
            for (int mt = 0; mt < 4; mt++)
                LDSM4(af[mt], pAh + rowA[mt] + (uint32_t)((cA ^ sA[mt]) << 4));
#pragma unroll
            for (int h2 = 0; h2 < 2; h2++)
                LDSM4(bf[h2], pB + rowB[h2] + (uint32_t)((cB ^ sB[h2]) << 4));
#pragma unroll
            for (int mt = 0; mt < 4; mt++)
#pragma unroll
                for (int nt = 0; nt < 4; nt++)
                    MMAH(acc[mt][nt], af[mt],
                         bf[nt >> 1][(nt & 1) * 2], bf[nt >> 1][(nt & 1) * 2 + 1]);
            if (NPASS == 2) {
#pragma unroll
                for (int mt = 0; mt < 4; mt++)
                    LDSM4(af[mt], pAl + rowA[mt] + (uint32_t)((cA ^ sA[mt]) << 4));
#pragma unroll
                for (int mt = 0; mt < 4; mt++)
#pragma unroll
                    for (int nt = 0; nt < 4; nt++)
                        MMAH(acc[mt][nt], af[mt],
                             bf[nt >> 1][(nt & 1) * 2], bf[nt >> 1][(nt & 1) * 2 + 1]);
            }
        }
    }

#pragma unroll
    for (int mt = 0; mt < 4; mt++) {
        int r0 = m0 + mw + mt * 16 + (lane >> 2);
#pragma unroll
        for (int nt = 0; nt < 4; nt++) {
            int col = n0 + nw + nt * 8 + 2 * (lane & 3);
            if (col < N) {
                if (H16OUT == 0) {
                    float2 v0 = make_float2(acc[mt][nt][0], acc[mt][nt][1]);
                    float2 v1 = make_float2(acc[mt][nt][2], acc[mt][nt][3]);
                    *(float2*)(C + (size_t)r0 * ldc + col) = v0;
                    *(float2*)(C + (size_t)(r0 + 8) * ldc + col) = v1;
                } else {
                    float a0 = acc[mt][nt][0], a1 = acc[mt][nt][1];
                    float a2 = acc[mt][nt][2], a3 = acc[mt][nt][3];
                    float h0 = __half2float(__float2half_rn(a0));
                    float h1 = __half2float(__float2half_rn(a1));
                    float h2f = __half2float(__float2half_rn(a2));
                    float h3 = __half2float(__float2half_rn(a3));
                    *(uint32_t*)(Ch + (size_t)r0 * ldc + col) = packh(a0, a1);
                    *(uint32_t*)(Cl + (size_t)r0 * ldc + col) = packh(a0 - h0, a1 - h1);
                    *(uint32_t*)(Ch + (size_t)(r0 + 8) * ldc + col) = packh(a2, a3);
                    *(uint32_t*)(Cl + (size_t)(r0 + 8) * ldc + col) = packh(a2 - h2f, a3 - h3);
                }
            }
        }
    }
}

// 1-pass fp16 GEMM, fp32 out
__global__ void __launch_bounds__(256, 2) gemm1_k(
    const h16* __restrict__ A, const h16* __restrict__ B, float* __restrict__ C,
    int N, int K, int lda, int ldb, int ldc)
{
    extern __shared__ char smem[];
    gemm_body<0, 1>(A, nullptr, B, C, nullptr, nullptr, N, K, lda, ldb, ldc,
                    blockIdx.y * 128, blockIdx.x * 128, smem);
}

// dual 2-pass GEMM, hi/lo fp16 out
__global__ void __launch_bounds__(256, 2) gemm2h_dual_k(
    const h16* __restrict__ A0h, const h16* __restrict__ A0l,
    const h16* __restrict__ B0, h16* __restrict__ C0h, h16* __restrict__ C0l,
    int N0, int K0, int lda0, int ldb0, int ldc0,
    const h16* __restrict__ A1h, const h16* __restrict__ A1l,
    const h16* __restrict__ B1, h16* __restrict__ C1h, h16* __restrict__ C1l,
    int N1, int K1, int lda1, int ldb1, int ldc1, int nx0)
{
    extern __shared__ char smem[];
    if ((int)blockIdx.x < nx0)
        gemm_body<1, 2>(A0h, A0l, B0, nullptr, C0h, C0l, N0, K0, lda0, ldb0, ldc0,
                        blockIdx.y * 128, blockIdx.x * 128, smem);
    else
        gemm_body<1, 2>(A1h, A1l, B1, nullptr, C1h, C1l, N1, K1, lda1, ldb1, ldc1,
                        blockIdx.y * 128, (blockIdx.x - nx0) * 128, smem);
}

// ---------------------------------------------------------------------------
// Fused flash attention (fp16). K/V loaded strided from kvexp hi/lo planes;
// Q roped in smem after load. Emits single fp16 output plane (ath).
// ---------------------------------------------------------------------------
#define FL_SMEM 229376
__global__ void __launch_bounds__(256, 1) flash_k(
    const h16* __restrict__ qh_, const h16* __restrict__ ql_,
    const h16* __restrict__ kvh_, const h16* __restrict__ kvl_,
    const h16* __restrict__ kpeh_, const h16* __restrict__ kpel_,
    const float* __restrict__ mb, const int* __restrict__ pos,
    h16* __restrict__ ath)
{
    extern __shared__ char smem[];
    int bh = blockIdx.x, b = bh >> 5, h = bh & 31;
    int qi = 7 - blockIdx.y;
    int t0 = qi * 128;
    int tid = threadIdx.x, lane = tid & 31, wid = tid >> 5;
    int wrow = wid * 16;

    uint32_t S0 = smem_u32(smem);
    uint32_t Qh = S0, Ql = S0 + 49152;
    uint32_t Kb = S0 + 98304;
    uint32_t Vb = S0 + 196608;

    const h16* Qgh = qh_ + ((size_t)(b * 1024 + t0)) * 6144 + h * 192;
    const h16* Qgl = ql_ + ((size_t)(b * 1024 + t0)) * 6144 + h * 192;
    const h16* KNh = kvh_ + (size_t)b * 1024 * 8192 + h * 256;
    const h16* KNl = kvl_ + (size_t)b * 1024 * 8192 + h * 256;
    const h16* KPh = kpeh_ + (size_t)b * 1024 * 64;
    const h16* KPl = kpel_ + (size_t)b * 1024 * 64;
    const h16* Vgh = KNh + 128;
    const h16* Vgl = KNl + 128;
    const float* mbb = mb + b * 1024;

#pragma unroll
    for (int sp = 0; sp < 6; sp++) {
        load_plane(Qh + sp * 8192, Qgh, 0, 6144, sp * 32, tid, 128);
        load_plane(Ql + sp * 8192, Qgl, 0, 6144, sp * 32, tid, 128);
    }
#pragma unroll
    for (int sp = 0; sp < 4; sp++) {
        load_plane64(Kb + sp * 4096,         KNh + sp * 32, 8192, tid);
        load_plane64(Kb + 24576 + sp * 4096, KNl + sp * 32, 8192, tid);
    }
#pragma unroll
    for (int sp = 4; sp < 6; sp++) {
        load_plane64(Kb + sp * 4096,         KPh + (sp - 4) * 32, 64, tid);
        load_plane64(Kb + 24576 + sp * 4096, KPl + (sp - 4) * 32, 64, tid);
    }
    CP_COMMIT();

    // ---- rope Q pe columns (subplanes 4,5) in smem ----
    CP_WAIT(0);
    __syncthreads();
    {
        int j = tid & 31;
        float invf = powf(10000.f, -(float)j / 32.f);
#pragma unroll
        for (int it = 0; it < 16; it++) {
            int r = (tid >> 5) + it * 8;
            uint32_t off = (uint32_t)(r * 64 +
                (((j >> 3) ^ ((r >> 1) & 3)) << 4) + (j & 7) * 2);
            h16* qh4 = (h16*)(smem + 4 * 8192 + off);
            h16* qh5 = (h16*)(smem + 5 * 8192 + off);
            h16* ql4 = (h16*)(smem + 49152 + 4 * 8192 + off);
            h16* ql5 = (h16*)(smem + 49152 + 5 * 8192 + off);
            float x1 = __half2float(*qh4) + __half2float(*ql4);
            float x2 = __half2float(*qh5) + __half2float(*ql5);
            float p = (float)pos[b * 1024 + t0 + r];
            float sn, cs; sincosf(p * invf, &sn, &cs);
            float y1 = x1 * cs - x2 * sn;
            float y2 = x1 * sn + x2 * cs;
            h16 h1 = __float2half_rn(y1);
            *qh4 = h1; *ql4 = __float2half_rn(y1 - __half2float(h1));
            h16 h2 = __float2half_rn(y2);
            *qh5 = h2; *ql5 = __float2half_rn(y2 - __half2float(h2));
        }
    }

    int nst = (t0 + 128) >> 6;
    float m0 = -1e30f, m1 = -1e30f, l0 = 0.f, l1 = 0.f;
    float O[16][4];
#pragma unroll
    for (int i = 0; i < 16; i++)
#pragma unroll
        for (int j = 0; j < 4; j++) O[i][j] = 0.f;

    int rA = wrow + (lane & 15);
    int swA = (rA >> 1) & 3;
    int rB[4], swB[4];
#pragma unroll
    for (int g = 0; g < 4; g++) {
        rB[g] = g * 16 + (lane & 7) + ((lane >> 4) << 3);
        swB[g] = (rB[g] >> 1) & 3;
    }
    int aSel = (lane >> 4) & 1, bSel = (lane >> 3) & 1;
    int trow = t0 + wrow + (lane >> 2);

    for (int i = 0; i < nst; i++) {
        __syncthreads();
        load_v(Vb,         Vgh + (size_t)i * 64 * 8192, 8192, tid);
        load_v(Vb + 16384, Vgl + (size_t)i * 64 * 8192, 8192, tid);
        CP_COMMIT();
        if (i + 1 < nst) {
            uint32_t Ks = Kb + ((i + 1) & 1) * 49152;
            size_t roff = (size_t)(i + 1) * 64;
#pragma unroll
            for (int sp = 0; sp < 4; sp++) {
                load_plane64(Ks + sp * 4096,         KNh + roff * 8192 + sp * 32, 8192, tid);
                load_plane64(Ks + 24576 + sp * 4096, KNl + roff * 8192 + sp * 32, 8192, tid);
            }
#pragma unroll
            for (int sp = 4; sp < 6; sp++) {
                load_plane64(Ks + sp * 4096,         KPh + roff * 64 + (sp - 4) * 32, 64, tid);
                load_plane64(Ks + 24576 + sp * 4096, KPl + roff * 64 + (sp - 4) * 32, 64, tid);
            }
        }
        CP_COMMIT();

        CP_WAIT(2);
        __syncthreads();

        // ---- S = QK^T (3 passes: QhKh, QhKl, QlKh) ----
        float S[8][4];
#pragma unroll
        for (int nt = 0; nt < 8; nt++)
#pragma unroll
            for (int j = 0; j < 4; j++) S[nt][j] = 0.f;

        uint32_t Ks = Kb + (i & 1) * 49152;
#pragma unroll
        for (int ks = 0; ks < 12; ks++) {
            int sp = ks >> 1;
            int cA = ((ks & 1) << 1) + aSel;
            int cB = ((ks & 1) << 1) + bSel;
            uint32_t ah[4], bhf[4][4], blf[4][4];
            LDSM4(ah, Qh + sp * 8192 + rA * 64 + (uint32_t)((cA ^ swA) << 4));
#pragma unroll
            for (int g = 0; g < 4; g++)
                LDSM4(bhf[g], Ks + sp * 4096 + rB[g] * 64 + (uint32_t)((cB ^ swB[g]) << 4));
#pragma unroll
            for (int g = 0; g < 4; g++) {
                MMAH(S[2 * g], ah, bhf[g][0], bhf[g][1]);
                MMAH(S[2 * g + 1], ah, bhf[g][2], bhf[g][3]);
            }
#pragma unroll
            for (int g = 0; g < 4; g++)
                LDSM4(blf[g], Ks + 24576 + sp * 4096 + rB[g] * 64 + (uint32_t)((cB ^ swB[g]) << 4));
#pragma unroll
            for (int g = 0; g < 4; g++) {
                MMAH(S[2 * g], ah, blf[g][0], blf[g][1]);
                MMAH(S[2 * g + 1], ah, blf[g][2], blf[g][3]);
            }
            LDSM4(ah, Ql + sp * 8192 + rA * 64 + (uint32_t)((cA ^ swA) << 4));
#pragma unroll
            for (int g = 0; g < 4; g++) {
                MMAH(S[2 * g], ah, bhf[g][0], bhf[g][1]);
                MMAH(S[2 * g + 1], ah, bhf[g][2], bhf[g][3]);
            }
        }

        // ---- online softmax ----
        int s0i = i * 64;
        float mx0 = -1e30f, mx1 = -1e30f;
#pragma unroll
        for (int nt = 0; nt < 8; nt++) {
            int sb0 = s0i + nt * 8 + ((lane & 3) << 1);
            float bias0 = mbb[sb0], bias1 = mbb[sb0 + 1];
            float v0 = S[nt][0] * SCALE_QK + bias0; if (sb0     > trow)     v0 = -1e30f;
            float v1 = S[nt][1] * SCALE_QK + bias1; if (sb0 + 1 > trow)     v1 = -1e30f;
            float v2 = S[nt][2] * SCALE_QK + bias0; if (sb0     > trow + 8) v2 = -1e30f;
            float v3 = S[nt][3] * SCALE_QK + bias1; if (sb0 + 1 > trow + 8) v3 = -1e30f;
            S[nt][0] = v0; S[nt][1] = v1; S[nt][2] = v2; S[nt][3] = v3;
            mx0 = fmaxf(mx0, fmaxf(v0, v1));
            mx1 = fmaxf(mx1, fmaxf(v2, v3));
        }
        mx0 = fmaxf(mx0, __shfl_xor_sync(0xffffffffu, mx0, 1));
        mx0 = fmaxf(mx0, __shfl_xor_sync(0xffffffffu, mx0, 2));
        mx1 = fmaxf(mx1, __shfl_xor_sync(0xffffffffu, mx1, 1));
        mx1 = fmaxf(mx1, __shfl_xor_sync(0xffffffffu, mx1, 2));
        float mn0 = fmaxf(m0, mx0), mn1 = fmaxf(m1, mx1);
        float cr0 = __expf(m0 - mn0), cr1 = __expf(m1 - mn1);
        float sum0 = 0.f, sum1 = 0.f;
#pragma unroll
        for (int nt = 0; nt < 8; nt++) {
            S[nt][0] = __expf(S[nt][0] - mn0);
            S[nt][1] = __expf(S[nt][1] - mn0);
            S[nt][2] = __expf(S[nt][2] - mn1);
            S[nt][3] = __expf(S[nt][3] - mn1);
            sum0 += S[nt][0] + S[nt][1];
            sum1 += S[nt][2] + S[nt][3];
        }
        sum0 += __shfl_xor_sync(0xffffffffu, sum0, 1);
        sum0 += __shfl_xor_sync(0xffffffffu, sum0, 2);
        sum1 += __shfl_xor_sync(0xffffffffu, sum1, 1);
        sum1 += __shfl_xor_sync(0xffffffffu, sum1, 2);
        l0 = l0 * cr0 + sum0;  l1 = l1 * cr1 + sum1;
        m0 = mn0;  m1 = mn1;
#pragma unroll
        for (int nd = 0; nd < 16; nd++) {
            O[nd][0] *= cr0; O[nd][1] *= cr0;
            O[nd][2] *= cr1; O[nd][3] *= cr1;
        }

        CP_WAIT(1);
        __syncthreads();

        // ---- O += P @ V (2 passes: P·Vh + P·Vl) ----
        int rV = (lane & 15);
#pragma unroll
        for (int kc = 0; kc < 4; kc++) {
            uint32_t phi[4];
#pragma unroll
            for (int j = 0; j < 2; j++) {
                int nt = 2 * kc + j;
                phi[2 * j]     = packh(S[nt][0], S[nt][1]);
                phi[2 * j + 1] = packh(S[nt][2], S[nt][3]);
            }
            int row = kc * 16 + rV;
            int sw = row & 7;
            uint32_t rbase = (uint32_t)row * 256;
            int cgrp = (lane >> 4) << 3;
#pragma unroll
            for (int g = 0; g < 8; g++) {
                int cch = (((g << 4) + cgrp) >> 3) ^ sw;
                uint32_t v4[4];
                LDSM4T(v4, Vb + rbase + (uint32_t)(cch << 4));
                MMAH_P(O[2 * g],     phi[0], phi[1], phi[2], phi[3], v4[0], v4[1]);
                MMAH_P(O[2 * g + 1], phi[0], phi[1], phi[2], phi[3], v4[2], v4[3]);
                LDSM4T(v4, Vb + 16384 + rbase + (uint32_t)(cch << 4));
                MMAH_P(O[2 * g],     phi[0], phi[1], phi[2], phi[3], v4[0], v4[1]);
                MMAH_P(O[2 * g + 1], phi[0], phi[1], phi[2], phi[3], v4[2], v4[3]);
            }
        }
    }

    // ---- epilogue: O / l -> single fp16 plane ----
    float inv0 = 1.f / l0, inv1 = 1.f / l1;
    size_t row0 = ((size_t)(b * 1024) + trow) * 4096 + h * 128;
    size_t row1 = row0 + (size_t)8 * 4096;
    int dcol = (lane & 3) * 2;
#pragma unroll
    for (int nd = 0; nd < 16; nd++) {
        int c = nd * 8 + dcol;
        *(uint32_t*)(ath + row0 + c) = packh(O[nd][0] * inv0, O[nd][1] * inv0);
        *(uint32_t*)(ath + row1 + c) = packh(O[nd][2] * inv1, O[nd][3] * inv1);
    }
}

// ------------------------- conversion / elementwise -------------------------
__device__ __forceinline__ void split1h(float v, h16* h, h16* l, size_t i) {
    h16 hi = __float2half_rn(v);
    h[i] = hi;
    l[i] = __float2half_rn(v - __half2float(hi));
}

// Fused prologue: weight transpose+convert (5 weights) + x fp16 convert.
__global__ void prep_k(const float* __restrict__ wq_a,
                       const float* __restrict__ wkv_a,
                       const float* __restrict__ wq_b,
                       const float* __restrict__ wkv_b,
                       const float* __restrict__ wo,
                       const float* __restrict__ x,
                       h16* __restrict__ wab, h16* __restrict__ wqb,
                       h16* __restrict__ wkvb, h16* __restrict__ wot,
                       h16* __restrict__ xh)
{
    __shared__ float t[32][33];
    int bx = blockIdx.x;
    int tx = threadIdx.x, ty = threadIdx.y;
    if (bx >= 38144) {            // x convert: 32768 blocks
        long i = (long)(bx - 38144) * 256 + ty * 32 + tx;
        xh[i] = __float2half_rn(x[i]);
        return;
    }
    const float* W; h16* T; int K, N, nx, tIdx, rowOff;
    if (bx < 6144)       { W = wq_a;  T = wab;  K = 4096; N = 1536; nx = 48;  tIdx = bx;         rowOff = 0; }
    else if (bx < 8448)  { W = wkv_a; T = wab;  K = 4096; N = 576;  nx = 18;  tIdx = bx - 6144;  rowOff = 1536; }
    else if (bx < 17664) { W = wq_b;  T = wqb;  K = 1536; N = 6144; nx = 192; tIdx = bx - 8448;  rowOff = 0; }
    else if (bx < 21760) { W = wkv_b; T = wkvb; K = 512;  N = 8192; nx = 256; tIdx = bx - 17664; rowOff = 0; }
    else                 { W = wo;    T = wot;  K = 4096; N = 4096; nx = 128; tIdx = bx - 21760; rowOff = 0; }
    int n0 = (tIdx % nx) * 32, k0 = (tIdx / nx) * 32;
#pragma unroll
    for (int j = 0; j < 32; j += 8)
        t[ty + j][tx] = W[(size_t)(k0 + ty + j) * N + n0 + tx];
    __syncthreads();
#pragma unroll
    for (int j = 0; j < 32; j += 8)
        T[(size_t)(rowOff + n0 + ty + j) * K + k0 + tx] =
            __float2half_rn(t[tx][ty + j]);
}

// Fused post-down-proj: rmsnorms -> hi/lo, rope k_pe -> planes, mask bias.
__global__ void postdown_k(const float* __restrict__ qkv,
                           const float* __restrict__ qw,
                           const float* __restrict__ kvw,
                           const int* __restrict__ amask,
                           const int* __restrict__ pos,
                           h16* __restrict__ qlh, h16* __restrict__ qll,
                           h16* __restrict__ kvh, h16* __restrict__ kvl,
                           h16* __restrict__ kpeh, h16* __restrict__ kpel,
                           float* __restrict__ mb)
{
    int rb = blockIdx.x;
    int tid = threadIdx.x;
    if (rb >= 4352) {                       // mask bias: 8 blocks
        int i = (rb - 4352) * 256 + tid;
        if (i < 2048) mb[i] = amask[i] ? 0.f : -1e30f;
        return;
    }
    if (rb >= 4096) {                       // rope k_pe: 256 blocks x 8 warps
        int w = (rb - 4096) * 8 + (tid >> 5);
        int lane = tid & 31;
        const float* base = qkv + (size_t)w * 2112 + 2048;
        float p = (float)pos[w];
        float invf = powf(10000.f, -(float)lane / 32.f);
        float sn, cs; sincosf(p * invf, &sn, &cs);
        float x1 = base[lane], x2 = base[32 + lane];
        size_t ob = (size_t)w * 64;
        split1h(x1 * cs - x2 * sn, kpeh, kpel, ob + lane);
        split1h(x1 * sn + x2 * cs, kpeh, kpel, ob + 32 + lane);
        return;
    }
    __shared__ float red[256];
    int isq = rb < 2048;
    long row = isq ? rb : rb - 2048;
    int n = isq ? 1536 : 512;
    const float* p = qkv + row * 2112 + (isq ? 0 : 1536);
    const float* w = isq ? qw : kvw;
    h16* oh = (isq ? qlh : kvh) + row * n;
    h16* ol = (isq ? qll : kvl) + row * n;
    float ss = 0.f;
    for (int c = tid; c < n; c += 256) { float v = p[c]; ss += v * v; }
    red[tid] = ss; __syncthreads();
    for (int s = 128; s > 0; s >>= 1) {
        if (tid < s) red[tid] += red[tid + s];
        __syncthreads();
    }
    float r = rsqrtf(red[0] / (float)n + 1e-6f);
    for (int c = tid; c < n; c += 256) {
        float v = p[c] * r * w[c];
        h16 hi = __float2half_rn(v);
        oh[c] = hi;
        ol[c] = __float2half_rn(v - __half2float(hi));
    }
}

// ---------------------------------------------------------------------------
extern "C" void kernel_launch(void* const* d_in, const int* in_sizes, int n_in,
                              void* d_out, int out_size)
{
    const float* x        = (const float*)d_in[0];
    const float* wq_a     = (const float*)d_in[1];
    const float* q_norm_w = (const float*)d_in[2];
    const float* wq_b     = (const float*)d_in[3];
    const float* wkv_a    = (const float*)d_in[4];
    const float* kv_norm_w= (const float*)d_in[5];
    const float* wkv_b    = (const float*)d_in[6];
    const float* wo       = (const float*)d_in[7];
    const int*   amask    = (const int*)d_in[8];
    const int*   pos      = (const int*)d_in[9];
    float*       out      = (float*)d_out;

    cudaFuncSetAttribute(gemm1_k, cudaFuncAttributeMaxDynamicSharedMemorySize,
                         GEMM1_SMEM);
    cudaFuncSetAttribute(gemm2h_dual_k, cudaFuncAttributeMaxDynamicSharedMemorySize,
                         GEMM2_SMEM);
    cudaFuncSetAttribute(flash_k, cudaFuncAttributeMaxDynamicSharedMemorySize,
                         FL_SMEM);

    float *qkv, *mb;
    h16 *xh,*qlh,*qll,*qh,*ql,*kvh,*kvl,*kvexph,*kvexpl,*kpeh,*kpel,*ath;
    h16 *wab,*wqb,*wkvb,*wot;
    cudaGetSymbolAddress((void**)&qkv,  g_qkv);
    cudaGetSymbolAddress((void**)&mb,   g_mb);
    cudaGetSymbolAddress((void**)&xh, g_xh);
    cudaGetSymbolAddress((void**)&qlh,g_qlh);  cudaGetSymbolAddress((void**)&qll,g_qll);
    cudaGetSymbolAddress((void**)&qh, g_qh);   cudaGetSymbolAddress((void**)&ql, g_ql);
    cudaGetSymbolAddress((void**)&kvh,g_kvh);  cudaGetSymbolAddress((void**)&kvl,g_kvl);
    cudaGetSymbolAddress((void**)&kvexph,g_kvexph);
    cudaGetSymbolAddress((void**)&kvexpl,g_kvexpl);
    cudaGetSymbolAddress((void**)&kpeh,g_kpeh); cudaGetSymbolAddress((void**)&kpel,g_kpel);
    cudaGetSymbolAddress((void**)&ath,g_ath);
    cudaGetSymbolAddress((void**)&wab,g_wab);  cudaGetSymbolAddress((void**)&wqb,g_wqb);
    cudaGetSymbolAddress((void**)&wkvb,g_wkvb); cudaGetSymbolAddress((void**)&wot,g_wo);

    // 0. fused prologue: weight transpose+convert, x convert
    prep_k<<<70912, dim3(32, 8)>>>(wq_a, wkv_a, wq_b, wkv_b, wo, x,
                                   wab, wqb, wkvb, wot, xh);
    // 1. merged down-proj (1-pass): qkv = x @ [wq_a | wkv_a]   [2048, 2112]
    gemm1_k<<<dim3(17, 16), 256, GEMM1_SMEM>>>(xh, wab, qkv,
        2112, 4096, 4096, 4096, 2112);
    // 2. fused rmsnorms + rope k_pe + mask bias
    postdown_k<<<4360, 256>>>(qkv, q_norm_w, kv_norm_w, amask, pos,
                              qlh, qll, kvh, kvl, kpeh, kpel, mb);
    // 3. dual up-proj (2-pass) writing hi/lo planes directly
    gemm2h_dual_k<<<dim3(112, 16), 256, GEMM2_SMEM>>>(
        qlh, qll, wqb, qh, ql,          6144, 1536, 1536, 1536, 6144,
        kvh, kvl, wkvb, kvexph, kvexpl, 8192, 512, 512, 512, 8192, 48);
    // 4. fused attention (rope-on-load, strided K/V) -> ath
    flash_k<<<dim3(64, 8), 256, FL_SMEM>>>(qh, ql, kvexph, kvexpl,
                                           kpeh, kpel, mb, pos, ath);
    // 5. out = attn @ wo (1-pass)
    gemm1_k<<<dim3(32, 16), 256, GEMM1_SMEM>>>(ath, wot, out,
        4096, 4096, 4096, 4096, 4096);
}

// round 12
// speedup vs baseline: 3.0744x; 1.3444x over previous
#include <cuda_runtime.h>
#include <cuda_fp16.h>
#include <math.h>
#include <stdint.h>

typedef __half h16;
#define TT 1024
#define SCALE_QK 0.07216878364870323f

// ------------------------- device scratch (no cudaMalloc) -------------------
__device__ float g_qkv  [2048*2112];   // qlow | kv | k_pe(fp32, pre-rope)
__device__ float g_mb   [2048];

__device__ h16 g_xh[2048*4096];
__device__ h16 g_qlow[2048*1536];
__device__ h16 g_q[2048*6144];
__device__ h16 g_kv[2048*512];
__device__ h16 g_kvexp[2048ll*8192];
__device__ h16 g_kpe[2048*64];
__device__ h16 g_at[2048*4096];
__device__ h16 g_wab[2112*4096];
__device__ h16 g_wqb[6144*1536];
__device__ h16 g_wkvb[8192*512];
__device__ h16 g_wo[4096*4096];

// ------------------------------ PTX helpers (sm_80-safe) --------------------
__device__ __forceinline__ uint32_t smem_u32(const void* p) {
    uint32_t a;
    asm("{ .reg .u64 t; cvta.to.shared.u64 t, %1; cvt.u32.u64 %0, t; }"
        : "=r"(a) : "l"(p));
    return a;
}

#define LDSM4(r, a) asm volatile( \
    "ldmatrix.sync.aligned.m8n8.x4.shared.b16 {%0,%1,%2,%3}, [%4];" \
    : "=r"((r)[0]), "=r"((r)[1]), "=r"((r)[2]), "=r"((r)[3]) : "r"(a))

#define LDSM4T(r, a) asm volatile( \
    "ldmatrix.sync.aligned.m8n8.x4.trans.shared.b16 {%0,%1,%2,%3}, [%4];" \
    : "=r"((r)[0]), "=r"((r)[1]), "=r"((r)[2]), "=r"((r)[3]) : "r"(a))

#define MMAH(d, a, b0, b1) asm volatile( \
    "mma.sync.aligned.m16n8k16.row.col.f32.f16.f16.f32 " \
    "{%0,%1,%2,%3},{%4,%5,%6,%7},{%8,%9},{%0,%1,%2,%3};" \
    : "+f"((d)[0]), "+f"((d)[1]), "+f"((d)[2]), "+f"((d)[3]) \
    : "r"((a)[0]), "r"((a)[1]), "r"((a)[2]), "r"((a)[3]), "r"(b0), "r"(b1))

#define MMAH_P(d, a0, a1, a2, a3, b0, b1) asm volatile( \
    "mma.sync.aligned.m16n8k16.row.col.f32.f16.f16.f32 " \
    "{%0,%1,%2,%3},{%4,%5,%6,%7},{%8,%9},{%0,%1,%2,%3};" \
    : "+f"((d)[0]), "+f"((d)[1]), "+f"((d)[2]), "+f"((d)[3]) \
    : "r"(a0), "r"(a1), "r"(a2), "r"(a3), "r"(b0), "r"(b1))

__device__ __forceinline__ void cpa16(uint32_t dst, const void* src, int valid) {
    int sz = valid ? 16 : 0;
    asm volatile("cp.async.cg.shared.global [%0], [%1], 16, %2;"
                 :: "r"(dst), "l"(src), "r"(sz));
}
#define CP_COMMIT() asm volatile("cp.async.commit_group;" ::: "memory")
#define CP_WAIT(n)  asm volatile("cp.async.wait_group %0;" :: "n"(n) : "memory")

__device__ __forceinline__ uint32_t packh(float a, float b) {
    __half2 t = __floats2half2_rn(a, b);
    return *reinterpret_cast<uint32_t*>(&t);
}

// Load one 128x32 h16 plane into swizzled smem (rows of 64B).
__device__ __forceinline__ void load_plane(uint32_t sb, const h16* __restrict__ G,
                                           int row0, int ld, int k0, int tid,
                                           int nvalid) {
#pragma unroll
    for (int i = 0; i < 2; i++) {
        int idx = tid * 2 + i;
        int r = idx >> 2, c = idx & 3;
        uint32_t dst = sb + r * 64 + ((c ^ ((r >> 1) & 3)) << 4);
        int ok = r < nvalid;
        const h16* src = G + (size_t)(row0 + (ok ? r : 0)) * ld + k0 + c * 8;
        cpa16(dst, src, ok);
    }
}

// Load one 64x32 h16 subplane (256 threads -> 1 line each). G pre-offset.
__device__ __forceinline__ void load_plane64(uint32_t sb, const h16* __restrict__ G,
                                             int ld, int tid) {
    int r = tid >> 2, c = tid & 3;
    uint32_t dst = sb + r * 64 + ((c ^ ((r >> 1) & 3)) << 4);
    cpa16(dst, G + (size_t)r * ld + c * 8, 1);
}

// Load one 64x128 h16 V plane (rows of 256B) with row-xor swizzle; row stride ld.
__device__ __forceinline__ void load_v(uint32_t sb, const h16* __restrict__ G,
                                       int ld, int tid) {
#pragma unroll
    for (int i = 0; i < 4; i++) {
        int idx = i * 256 + tid;
        int r = idx >> 4, c = idx & 15;
        uint32_t dst = sb + r * 256 + ((c ^ (r & 7)) << 4);
        cpa16(dst, G + (size_t)r * ld + c * 8, 1);
    }
}

// ---------------------------------------------------------------------------
// Single-pass fp16 HMMA GEMM body, 4-stage cp.async pipeline.
// H16OUT=0: fp32 C; H16OUT=1: fp16 C.
// ---------------------------------------------------------------------------
#define GEMM_SMEM 65536
template<int H16OUT>
__device__ __forceinline__ void gemm_body(
    const h16* __restrict__ A, const h16* __restrict__ B,
    float* __restrict__ C, h16* __restrict__ Ch,
    int N, int K, int lda, int ldb, int ldc, int m0, int n0, char* smem)
{
    int tid = threadIdx.x, lane = tid & 31, wid = tid >> 5;
    int mw = (wid & 1) * 64, nw = (wid >> 1) * 32;
    uint32_t s0 = smem_u32(smem);
    int nvB = min(128, N - n0);
    int nch = K >> 5;

    uint32_t rowA[4]; int sA[4];
#pragma unroll
    for (int mt = 0; mt < 4; mt++) {
        int r = mw + mt * 16 + (lane & 15);
        rowA[mt] = r * 64; sA[mt] = (r >> 1) & 3;
    }
    uint32_t rowB[2]; int sB[2];
#pragma unroll
    for (int h2 = 0; h2 < 2; h2++) {
        int r = nw + h2 * 16 + (lane & 7) + ((lane >> 4) << 3);
        rowB[h2] = r * 64; sB[h2] = (r >> 1) & 3;
    }
    int aCk = (lane >> 4) & 1, bCk = (lane >> 3) & 1;

    float acc[4][4][4];
#pragma unroll
    for (int i = 0; i < 4; i++)
#pragma unroll
        for (int j = 0; j < 4; j++)
#pragma unroll
            for (int r = 0; r < 4; r++) acc[i][j][r] = 0.f;

    // prologue: stages 0..2
#pragma unroll
    for (int pc = 0; pc < 3; pc++) {
        if (pc < nch) {
            uint32_t sb = s0 + pc * 16384;
            load_plane(sb,        A, m0, lda, pc * 32, tid, 128);
            load_plane(sb + 8192, B, n0, ldb, pc * 32, tid, nvB);
        }
        CP_COMMIT();
    }

    for (int c = 0; c < nch; c++) {
        CP_WAIT(2);
        __syncthreads();
        if (c + 3 < nch) {
            uint32_t sb = s0 + ((c + 3) & 3) * 16384;
            int k0 = (c + 3) * 32;
            load_plane(sb,        A, m0, lda, k0, tid, 128);
            load_plane(sb + 8192, B, n0, ldb, k0, tid, nvB);
        }
        CP_COMMIT();

        uint32_t base = s0 + (c & 3) * 16384;
        uint32_t pA = base, pB = base + 8192;
#pragma unroll
        for (int ks = 0; ks < 2; ks++) {
            uint32_t af[4][4], bf[2][4];
            int cA = ks * 2 + aCk, cB = ks * 2 + bCk;
#pragma unroll
            for (int mt = 0; mt < 4; mt++)
                LDSM4(af[mt], pA + rowA[mt] + (uint32_t)((cA ^ sA[mt]) << 4));
#pragma unroll
            for (int h2 = 0; h2 < 2; h2++)
                LDSM4(bf[h2], pB + rowB[h2] + (uint32_t)((cB ^ sB[h2]) << 4));
#pragma unroll
            for (int mt = 0; mt < 4; mt++)
#pragma unroll
                for (int nt = 0; nt < 4; nt++)
                    MMAH(acc[mt][nt], af[mt],
                         bf[nt >> 1][(nt & 1) * 2], bf[nt >> 1][(nt & 1) * 2 + 1]);
        }
    }

#pragma unroll
    for (int mt = 0; mt < 4; mt++) {
        int r0 = m0 + mw + mt * 16 + (lane >> 2);
#pragma unroll
        for (int nt = 0; nt < 4; nt++) {
            int col = n0 + nw + nt * 8 + 2 * (lane & 3);
            if (col < N) {
                if (H16OUT == 0) {
                    float2 v0 = make_float2(acc[mt][nt][0], acc[mt][nt][1]);
                    float2 v1 = make_float2(acc[mt][nt][2], acc[mt][nt][3]);
                    *(float2*)(C + (size_t)r0 * ldc + col) = v0;
                    *(float2*)(C + (size_t)(r0 + 8) * ldc + col) = v1;
                } else {
                    *(uint32_t*)(Ch + (size_t)r0 * ldc + col) =
                        packh(acc[mt][nt][0], acc[mt][nt][1]);
                    *(uint32_t*)(Ch + (size_t)(r0 + 8) * ldc + col) =
                        packh(acc[mt][nt][2], acc[mt][nt][3]);
                }
            }
        }
    }
}

// fp32-out GEMM
__global__ void __launch_bounds__(256, 2) gemm1_k(
    const h16* __restrict__ A, const h16* __restrict__ B, float* __restrict__ C,
    int N, int K, int lda, int ldb, int ldc)
{
    extern __shared__ char smem[];
    gemm_body<0>(A, B, C, nullptr, N, K, lda, ldb, ldc,
                 blockIdx.y * 128, blockIdx.x * 128, smem);
}

// dual fp16-out GEMM (q up-proj + kv up-proj)
__global__ void __launch_bounds__(256, 2) gemm1h_dual_k(
    const h16* __restrict__ A0, const h16* __restrict__ B0, h16* __restrict__ C0,
    int N0, int K0, int lda0, int ldb0, int ldc0,
    const h16* __restrict__ A1, const h16* __restrict__ B1, h16* __restrict__ C1,
    int N1, int K1, int lda1, int ldb1, int ldc1, int nx0)
{
    extern __shared__ char smem[];
    if ((int)blockIdx.x < nx0)
        gemm_body<1>(A0, B0, nullptr, C0, N0, K0, lda0, ldb0, ldc0,
                     blockIdx.y * 128, blockIdx.x * 128, smem);
    else
        gemm_body<1>(A1, B1, nullptr, C1, N1, K1, lda1, ldb1, ldc1,
                     blockIdx.y * 128, (blockIdx.x - nx0) * 128, smem);
}

// ---------------------------------------------------------------------------
// Fused flash attention, single fp16 planes. 112KB smem -> 2 CTAs/SM.
// Q roped in smem after load; K gathered strided (nope from kvexp + pe plane);
// V strided from kvexp.
// ---------------------------------------------------------------------------
#define FL_SMEM 114688
__global__ void __launch_bounds__(256, 2) flash_k(
    const h16* __restrict__ q_, const h16* __restrict__ kv_,
    const h16* __restrict__ kpe_,
    const float* __restrict__ mb, const int* __restrict__ pos,
    h16* __restrict__ at_)
{
    extern __shared__ char smem[];
    int bh = blockIdx.x, b = bh >> 5, h = bh & 31;
    int qi = 7 - blockIdx.y;
    int t0 = qi * 128;
    int tid = threadIdx.x, lane = tid & 31, wid = tid >> 5;
    int wrow = wid * 16;

    uint32_t S0 = smem_u32(smem);
    uint32_t Qs = S0;                  // 49152
    uint32_t Kb = S0 + 49152;          // 2 stages x 24576
    uint32_t Vb = S0 + 98304;          // 16384

    const h16* Qg = q_ + ((size_t)(b * 1024 + t0)) * 6144 + h * 192;
    const h16* KN = kv_ + (size_t)b * 1024 * 8192 + h * 256;
    const h16* KP = kpe_ + (size_t)b * 1024 * 64;
    const h16* Vg = KN + 128;
    const float* mbb = mb + b * 1024;

#pragma unroll
    for (int sp = 0; sp < 6; sp++)
        load_plane(Qs + sp * 8192, Qg, 0, 6144, sp * 32, tid, 128);
#pragma unroll
    for (int sp = 0; sp < 4; sp++)
        load_plane64(Kb + sp * 4096, KN + sp * 32, 8192, tid);
#pragma unroll
    for (int sp = 4; sp < 6; sp++)
        load_plane64(Kb + sp * 4096, KP + (sp - 4) * 32, 64, tid);
    CP_COMMIT();

    // ---- rope Q pe columns (subplanes 4,5) in smem ----
    CP_WAIT(0);
    __syncthreads();
    {
        int j = tid & 31;
        float invf = powf(10000.f, -(float)j / 32.f);
#pragma unroll
        for (int it = 0; it < 16; it++) {
            int r = (tid >> 5) + it * 8;
            uint32_t off = (uint32_t)(r * 64 +
                (((j >> 3) ^ ((r >> 1) & 3)) << 4) + (j & 7) * 2);
            h16* q4 = (h16*)(smem + 4 * 8192 + off);
            h16* q5 = (h16*)(smem + 5 * 8192 + off);
            float x1 = __half2float(*q4), x2 = __half2float(*q5);
            float p = (float)pos[b * 1024 + t0 + r];
            float sn, cs; sincosf(p * invf, &sn, &cs);
            *q4 = __float2half_rn(x1 * cs - x2 * sn);
            *q5 = __float2half_rn(x1 * sn + x2 * cs);
        }
    }

    int nst = (t0 + 128) >> 6;
    float m0 = -1e30f, m1 = -1e30f, l0 = 0.f, l1 = 0.f;
    float O[16][4];
#pragma unroll
    for (int i = 0; i < 16; i++)
#pragma unroll
        for (int j = 0; j < 4; j++) O[i][j] = 0.f;

    int rA = wrow + (lane & 15);
    int swA = (rA >> 1) & 3;
    int rB[4], swB[4];
#pragma unroll
    for (int g = 0; g < 4; g++) {
        rB[g] = g * 16 + (lane & 7) + ((lane >> 4) << 3);
        swB[g] = (rB[g] >> 1) & 3;
    }
    int aSel = (lane >> 4) & 1, bSel = (lane >> 3) & 1;
    int trow = t0 + wrow + (lane >> 2);

    for (int i = 0; i < nst; i++) {
        __syncthreads();
        load_v(Vb, Vg + (size_t)i * 64 * 8192, 8192, tid);
        CP_COMMIT();
        if (i + 1 < nst) {
            uint32_t Ks = Kb + ((i + 1) & 1) * 24576;
            size_t roff = (size_t)(i + 1) * 64;
#pragma unroll
            for (int sp = 0; sp < 4; sp++)
                load_plane64(Ks + sp * 4096, KN + roff * 8192 + sp * 32, 8192, tid);
#pragma unroll
            for (int sp = 4; sp < 6; sp++)
                load_plane64(Ks + sp * 4096, KP + roff * 64 + (sp - 4) * 32, 64, tid);
        }
        CP_COMMIT();

        CP_WAIT(2);
        __syncthreads();

        // ---- S = QK^T (single pass) ----
        float S[8][4];
#pragma unroll
        for (int nt = 0; nt < 8; nt++)
#pragma unroll
            for (int j = 0; j < 4; j++) S[nt][j] = 0.f;

        uint32_t Ks = Kb + (i & 1) * 24576;
#pragma unroll
        for (int ks = 0; ks < 12; ks++) {
            int sp = ks >> 1;
            int cA = ((ks & 1) << 1) + aSel;
            int cB = ((ks & 1) << 1) + bSel;
            uint32_t ah[4], bf[4][4];
            LDSM4(ah, Qs + sp * 8192 + rA * 64 + (uint32_t)((cA ^ swA) << 4));
#pragma unroll
            for (int g = 0; g < 4; g++)
                LDSM4(bf[g], Ks + sp * 4096 + rB[g] * 64 + (uint32_t)((cB ^ swB[g]) << 4));
#pragma unroll
            for (int g = 0; g < 4; g++) {
                MMAH(S[2 * g], ah, bf[g][0], bf[g][1]);
                MMAH(S[2 * g + 1], ah, bf[g][2], bf[g][3]);
            }
        }

        // ---- online softmax ----
        int s0i = i * 64;
        float mx0 = -1e30f, mx1 = -1e30f;
#pragma unroll
        for (int nt = 0; nt < 8; nt++) {
            int sb0 = s0i + nt * 8 + ((lane & 3) << 1);
            float bias0 = mbb[sb0], bias1 = mbb[sb0 + 1];
            float v0 = S[nt][0] * SCALE_QK + bias0; if (sb0     > trow)     v0 = -1e30f;
            float v1 = S[nt][1] * SCALE_QK + bias1; if (sb0 + 1 > trow)     v1 = -1e30f;
            float v2 = S[nt][2] * SCALE_QK + bias0; if (sb0     > trow + 8) v2 = -1e30f;
            float v3 = S[nt][3] * SCALE_QK + bias1; if (sb0 + 1 > trow + 8) v3 = -1e30f;
            S[nt][0] = v0; S[nt][1] = v1; S[nt][2] = v2; S[nt][3] = v3;
            mx0 = fmaxf(mx0, fmaxf(v0, v1));
            mx1 = fmaxf(mx1, fmaxf(v2, v3));
        }
        mx0 = fmaxf(mx0, __shfl_xor_sync(0xffffffffu, mx0, 1));
        mx0 = fmaxf(mx0, __shfl_xor_sync(0xffffffffu, mx0, 2));
        mx1 = fmaxf(mx1, __shfl_xor_sync(0xffffffffu, mx1, 1));
        mx1 = fmaxf(mx1, __shfl_xor_sync(0xffffffffu, mx1, 2));
        float mn0 = fmaxf(m0, mx0), mn1 = fmaxf(m1, mx1);
        float cr0 = __expf(m0 - mn0), cr1 = __expf(m1 - mn1);
        float sum0 = 0.f, sum1 = 0.f;
#pragma unroll
        for (int nt = 0; nt < 8; nt++) {
            S[nt][0] = __expf(S[nt][0] - mn0);
            S[nt][1] = __expf(S[nt][1] - mn0);
            S[nt][2] = __expf(S[nt][2] - mn1);
            S[nt][3] = __expf(S[nt][3] - mn1);
            sum0 += S[nt][0] + S[nt][1];
            sum1 += S[nt][2] + S[nt][3];
        }
        sum0 += __shfl_xor_sync(0xffffffffu, sum0, 1);
        sum0 += __shfl_xor_sync(0xffffffffu, sum0, 2);
        sum1 += __shfl_xor_sync(0xffffffffu, sum1, 1);
        sum1 += __shfl_xor_sync(0xffffffffu, sum1, 2);
        l0 = l0 * cr0 + sum0;  l1 = l1 * cr1 + sum1;
        m0 = mn0;  m1 = mn1;
#pragma unroll
        for (int nd = 0; nd < 16; nd++) {
            O[nd][0] *= cr0; O[nd][1] *= cr0;
            O[nd][2] *= cr1; O[nd][3] *= cr1;
        }

        CP_WAIT(1);
        __syncthreads();

        // ---- O += P @ V (single pass) ----
        int rV = (lane & 15);
#pragma unroll
        for (int kc = 0; kc < 4; kc++) {
            uint32_t phi[4];
#pragma unroll
            for (int j = 0; j < 2; j++) {
                int nt = 2 * kc + j;
                phi[2 * j]     = packh(S[nt][0], S[nt][1]);
                phi[2 * j + 1] = packh(S[nt][2], S[nt][3]);
            }
            int row = kc * 16 + rV;
            int sw = row & 7;
            uint32_t rbase = (uint32_t)row * 256;
            int cgrp = (lane >> 4) << 3;
#pragma unroll
            for (int g = 0; g < 8; g++) {
                int cch = (((g << 4) + cgrp) >> 3) ^ sw;
                uint32_t v4[4];
                LDSM4T(v4, Vb + rbase + (uint32_t)(cch << 4));
                MMAH_P(O[2 * g],     phi[0], phi[1], phi[2], phi[3], v4[0], v4[1]);
                MMAH_P(O[2 * g + 1], phi[0], phi[1], phi[2], phi[3], v4[2], v4[3]);
            }
        }
    }

    // ---- epilogue: O / l -> fp16 plane ----
    float inv0 = 1.f / l0, inv1 = 1.f / l1;
    size_t row0 = ((size_t)(b * 1024) + trow) * 4096 + h * 128;
    size_t row1 = row0 + (size_t)8 * 4096;
    int dcol = (lane & 3) * 2;
#pragma unroll
    for (int nd = 0; nd < 16; nd++) {
        int c = nd * 8 + dcol;
        *(uint32_t*)(at_ + row0 + c) = packh(O[nd][0] * inv0, O[nd][1] * inv0);
        *(uint32_t*)(at_ + row1 + c) = packh(O[nd][2] * inv1, O[nd][3] * inv1);
    }
}

// ------------------------- conversion / elementwise -------------------------
// Fused prologue: weight transpose+convert (5 weights) + x fp16 convert.
__global__ void prep_k(const float* __restrict__ wq_a,
                       const float* __restrict__ wkv_a,
                       const float* __restrict__ wq_b,
                       const float* __restrict__ wkv_b,
                       const float* __restrict__ wo,
                       const float* __restrict__ x,
                       h16* __restrict__ wab, h16* __restrict__ wqb,
                       h16* __restrict__ wkvb, h16* __restrict__ wot,
                       h16* __restrict__ xh)
{
    __shared__ float t[32][33];
    int bx = blockIdx.x;
    int tx = threadIdx.x, ty = threadIdx.y;
    if (bx >= 38144) {            // x convert: 32768 blocks
        long i = (long)(bx - 38144) * 256 + ty * 32 + tx;
        xh[i] = __float2half_rn(x[i]);
        return;
    }
    const float* W; h16* T; int K, N, nx, tIdx, rowOff;
    if (bx < 6144)       { W = wq_a;  T = wab;  K = 4096; N = 1536; nx = 48;  tIdx = bx;         rowOff = 0; }
    else if (bx < 8448)  { W = wkv_a; T = wab;  K = 4096; N = 576;  nx = 18;  tIdx = bx - 6144;  rowOff = 1536; }
    else if (bx < 17664) { W = wq_b;  T = wqb;  K = 1536; N = 6144; nx = 192; tIdx = bx - 8448;  rowOff = 0; }
    else if (bx < 21760) { W = wkv_b; T = wkvb; K = 512;  N = 8192; nx = 256; tIdx = bx - 17664; rowOff = 0; }
    else                 { W = wo;    T = wot;  K = 4096; N = 4096; nx = 128; tIdx = bx - 21760; rowOff = 0; }
    int n0 = (tIdx % nx) * 32, k0 = (tIdx / nx) * 32;
#pragma unroll
    for (int j = 0; j < 32; j += 8)
        t[ty + j][tx] = W[(size_t)(k0 + ty + j) * N + n0 + tx];
    __syncthreads();
#pragma unroll
    for (int j = 0; j < 32; j += 8)
        T[(size_t)(rowOff + n0 + ty + j) * K + k0 + tx] =
            __float2half_rn(t[tx][ty + j]);
}

// Fused post-down-proj: rmsnorms -> fp16, rope k_pe -> plane, mask bias.
__global__ void postdown_k(const float* __restrict__ qkv,
                           const float* __restrict__ qw,
                           const float* __restrict__ kvw,
                           const int* __restrict__ amask,
                           const int* __restrict__ pos,
                           h16* __restrict__ qlow, h16* __restrict__ kv,
                           h16* __restrict__ kpe, float* __restrict__ mb)
{
    int rb = blockIdx.x;
    int tid = threadIdx.x;
    if (rb >= 4352) {                       // mask bias: 8 blocks
        int i = (rb - 4352) * 256 + tid;
        if (i < 2048) mb[i] = amask[i] ? 0.f : -1e30f;
        return;
    }
    if (rb >= 4096) {                       // rope k_pe: 256 blocks x 8 warps
        int w = (rb - 4096) * 8 + (tid >> 5);
        int lane = tid & 31;
        const float* base = qkv + (size_t)w * 2112 + 2048;
        float p = (float)pos[w];
        float invf = powf(10000.f, -(float)lane / 32.f);
        float sn, cs; sincosf(p * invf, &sn, &cs);
        float x1 = base[lane], x2 = base[32 + lane];
        size_t ob = (size_t)w * 64;
        kpe[ob + lane]      = __float2half_rn(x1 * cs - x2 * sn);
        kpe[ob + 32 + lane] = __float2half_rn(x1 * sn + x2 * cs);
        return;
    }
    __shared__ float red[256];
    int isq = rb < 2048;
    long row = isq ? rb : rb - 2048;
    int n = isq ? 1536 : 512;
    const float* p = qkv + row * 2112 + (isq ? 0 : 1536);
    const float* w = isq ? qw : kvw;
    h16* oh = (isq ? qlow : kv) + row * n;
    float ss = 0.f;
    for (int c = tid; c < n; c += 256) { float v = p[c]; ss += v * v; }
    red[tid] = ss; __syncthreads();
    for (int s = 128; s > 0; s >>= 1) {
        if (tid < s) red[tid] += red[tid + s];
        __syncthreads();
    }
    float r = rsqrtf(red[0] / (float)n + 1e-6f);
    for (int c = tid; c < n; c += 256)
        oh[c] = __float2half_rn(p[c] * r * w[c]);
}

// ---------------------------------------------------------------------------
extern "C" void kernel_launch(void* const* d_in, const int* in_sizes, int n_in,
                              void* d_out, int out_size)
{
    const float* x        = (const float*)d_in[0];
    const float* wq_a     = (const float*)d_in[1];
    const float* q_norm_w = (const float*)d_in[2];
    const float* wq_b     = (const float*)d_in[3];
    const float* wkv_a    = (const float*)d_in[4];
    const float* kv_norm_w= (const float*)d_in[5];
    const float* wkv_b    = (const float*)d_in[6];
    const float* wo       = (const float*)d_in[7];
    const int*   amask    = (const int*)d_in[8];
    const int*   pos      = (const int*)d_in[9];
    float*       out      = (float*)d_out;

    cudaFuncSetAttribute(gemm1_k, cudaFuncAttributeMaxDynamicSharedMemorySize,
                         GEMM_SMEM);
    cudaFuncSetAttribute(gemm1h_dual_k, cudaFuncAttributeMaxDynamicSharedMemorySize,
                         GEMM_SMEM);
    cudaFuncSetAttribute(flash_k, cudaFuncAttributeMaxDynamicSharedMemorySize,
                         FL_SMEM);

    float *qkv, *mb;
    h16 *xh,*qlow,*q,*kv,*kvexp,*kpe,*at;
    h16 *wab,*wqb,*wkvb,*wot;
    cudaGetSymbolAddress((void**)&qkv,  g_qkv);
    cudaGetSymbolAddress((void**)&mb,   g_mb);
    cudaGetSymbolAddress((void**)&xh,   g_xh);
    cudaGetSymbolAddress((void**)&qlow, g_qlow);
    cudaGetSymbolAddress((void**)&q,    g_q);
    cudaGetSymbolAddress((void**)&kv,   g_kv);
    cudaGetSymbolAddress((void**)&kvexp,g_kvexp);
    cudaGetSymbolAddress((void**)&kpe,  g_kpe);
    cudaGetSymbolAddress((void**)&at,   g_at);
    cudaGetSymbolAddress((void**)&wab,  g_wab);
    cudaGetSymbolAddress((void**)&wqb,  g_wqb);
    cudaGetSymbolAddress((void**)&wkvb, g_wkvb);
    cudaGetSymbolAddress((void**)&wot,  g_wo);

    // 0. fused prologue: weight transpose+convert, x convert
    prep_k<<<70912, dim3(32, 8)>>>(wq_a, wkv_a, wq_b, wkv_b, wo, x,
                                   wab, wqb, wkvb, wot, xh);
    // 1. merged down-proj: qkv = x @ [wq_a | wkv_a]   [2048, 2112] fp32
    gemm1_k<<<dim3(17, 16), 256, GEMM_SMEM>>>(xh, wab, qkv,
        2112, 4096, 4096, 4096, 2112);
    // 2. fused rmsnorms + rope k_pe + mask bias
    postdown_k<<<4360, 256>>>(qkv, q_norm_w, kv_norm_w, amask, pos,
                              qlow, kv, kpe, mb);
    // 3. dual up-proj -> fp16 planes
    gemm1h_dual_k<<<dim3(112, 16), 256, GEMM_SMEM>>>(
        qlow, wqb, q,     6144, 1536, 1536, 1536, 6144,
        kv,   wkvb, kvexp, 8192, 512, 512, 512, 8192, 48);
    // 4. fused attention (rope-on-load, strided K/V) -> at
    flash_k<<<dim3(64, 8), 256, FL_SMEM>>>(q, kvexp, kpe, mb, pos, at);
    // 5. out = attn @ wo
    gemm1_k<<<dim3(32, 16), 256, GEMM_SMEM>>>(at, wot, out,
        4096, 4096, 4096, 4096, 4096);
}